// round 7
// baseline (speedup 1.0000x reference)
#include <cuda_runtime.h>
#include <cuda_bf16.h>
#include <math.h>
#include <stdint.h>

#define B_ 8
#define T_ 128
#define E_ 30522
#define H_ 1000
#define S_ 64
#define NZ_ 10000
#define EPNZ_ 40522
#define G4H_ (4*H_)
#define KP_ 30528   // E padded to mult of 32
#define NZP_ 10016  // NZ padded to mult of 32
#define HP_ 1024    // H padded to mult of 32

// ---------------- fp32 scratch ----------------
__device__ float g_outWT[(size_t)H_*E_];
__device__ float g_encGX[(size_t)T_*B_*G4H_];
__device__ float g_M[(size_t)H_*H_];
__device__ float g_n1[(size_t)S_*B_*H_];
__device__ float g_n2[(size_t)S_*B_*T_];
__device__ float g_emb0[B_*H_];
__device__ float g_v2[H_];
__device__ float g_encT[(size_t)B_*H_*T_];   // transposed encoder outputs [b][j][t]
__device__ float g_h[2][B_*H_];
__device__ float g_c[B_*H_];
__device__ float g_emb[B_*H_];
__device__ float g_lg[B_*T_];
__device__ float g_app[B_*H_];
__device__ float g_outv[B_*H_];
__device__ float g_Hs[(size_t)S_*B_*H_];

// ---------------- bf16 split operands ----------------
__device__ __nv_bfloat16 g_inpH[(size_t)T_*B_*KP_],  g_inpL[(size_t)T_*B_*KP_];
__device__ __nv_bfloat16 g_wihH[(size_t)G4H_*KP_],   g_wihL[(size_t)G4H_*KP_];
__device__ __nv_bfloat16 g_embEH[(size_t)H_*KP_],    g_embEL[(size_t)H_*KP_];
__device__ __nv_bfloat16 g_embNH[(size_t)H_*NZP_],   g_embNL[(size_t)H_*NZP_];
__device__ __nv_bfloat16 g_oWTH[(size_t)H_*KP_],     g_oWTL[(size_t)H_*KP_];
__device__ __nv_bfloat16 g_oWH[(size_t)E_*HP_],      g_oWL[(size_t)E_*HP_];
__device__ __nv_bfloat16 g_nzH[(size_t)S_*B_*NZP_],  g_nzL[(size_t)S_*B_*NZP_];
__device__ __nv_bfloat16 g_HsH[(size_t)S_*B_*HP_],   g_HsL[(size_t)S_*B_*HP_];

__device__ __forceinline__ float wsum(float v){
#pragma unroll
    for (int o = 16; o; o >>= 1) v += __shfl_xor_sync(0xffffffffu, v, o);
    return v;
}
__device__ __forceinline__ float sigf(float x){ return 1.f/(1.f+expf(-x)); }

__device__ __forceinline__ uint32_t smem_u32(const void* p){
    uint32_t a;
    asm("{ .reg .u64 t; cvta.to.shared.u64 t, %1; cvt.u32.u64 %0, t; }" : "=r"(a) : "l"(p));
    return a;
}
__device__ __forceinline__ void ldsm4(uint32_t* r, uint32_t a){
    asm volatile("ldmatrix.sync.aligned.m8n8.x4.shared.b16 {%0,%1,%2,%3}, [%4];"
        : "=r"(r[0]),"=r"(r[1]),"=r"(r[2]),"=r"(r[3]) : "r"(a));
}
__device__ __forceinline__ void mma16816(float* c, const uint32_t* a,
                                         uint32_t b0, uint32_t b1){
    asm volatile("mma.sync.aligned.m16n8k16.row.col.f32.bf16.bf16.f32 "
        "{%0,%1,%2,%3}, {%4,%5,%6,%7}, {%8,%9}, {%0,%1,%2,%3};"
        : "+f"(c[0]),"+f"(c[1]),"+f"(c[2]),"+f"(c[3])
        : "r"(a[0]),"r"(a[1]),"r"(a[2]),"r"(a[3]), "r"(b0),"r"(b1));
}
__device__ __forceinline__ void cpasync16(uint32_t dst, const void* src, int sz){
    asm volatile("cp.async.cg.shared.global [%0], [%1], 16, %2;"
        :: "r"(dst), "l"(src), "r"(sz));
}

#define BKE 32
#define RPAD 80                 // row stride bytes (40 bf16)
#define ARR_B (128*RPAD)        // 10240
#define STAGE_B (4*ARR_B)       // 40960
#define NSTG 3
#define SMEM_B (NSTG*STAGE_B)   // 122880

// ---------------- split-bf16 HMMA NT GEMM: C = A@B^T (+bias) ----------------
// grid: (Mblocks, Nblocks) -- x indexes M so a wave shares the B operand.
__global__ __launch_bounds__(256,1)
void mma_gemm(const __nv_bfloat16* __restrict__ Ah, const __nv_bfloat16* __restrict__ Al,
              const __nv_bfloat16* __restrict__ Bh, const __nv_bfloat16* __restrict__ Bl,
              float* __restrict__ C, const float* __restrict__ bias0,
              const float* __restrict__ bias1,
              int M, int N, int K, int ldc)
{
    extern __shared__ char smem[];
    uint32_t sb = smem_u32(smem);
    const int tid = threadIdx.x, lane = tid & 31, wid = tid >> 5;
    const int row0 = blockIdx.x*128, col0 = blockIdx.y*128;
    const int wm = wid >> 2, wn = wid & 3;

    float c[4][4][4];
#pragma unroll
    for (int i = 0; i < 4; i++)
#pragma unroll
        for (int j = 0; j < 4; j++)
#pragma unroll
            for (int q = 0; q < 4; q++) c[i][j][q] = 0.f;

    const int NT = K/BKE;

    auto load = [&](int kt, int stg){
        int k0 = kt*BKE;
#pragma unroll
        for (int i = 0; i < 8; i++){
            int v = tid + i*256;
            int arr = v >> 9;              // 0:Ah 1:Al 2:Bh 3:Bl
            int r = (v >> 2) & 127;
            int ch = v & 3;
            int gk = k0 + ch*8;
            const __nv_bfloat16* src; int gr, lim;
            if (arr < 2){ gr = row0 + r; lim = M; src = arr ? Al : Ah; }
            else        { gr = col0 + r; lim = N; src = (arr == 3) ? Bl : Bh; }
            int ok = (gr < lim);
            const __nv_bfloat16* g = src + (size_t)(ok ? gr : 0)*K + gk;
            uint32_t d = sb + stg*STAGE_B + arr*ARR_B + r*RPAD + ch*16;
            cpasync16(d, g, ok ? 16 : 0);
        }
        asm volatile("cp.async.commit_group;" ::: "memory");
    };

    load(0, 0);
    load(1, 1);
    for (int kt = 0; kt < NT; kt++){
        if (kt + 2 < NT) load(kt+2, (kt+2)%NSTG);
        else asm volatile("cp.async.commit_group;" ::: "memory");
        asm volatile("cp.async.wait_group 2;" ::: "memory");
        __syncthreads();

        uint32_t sbase = sb + (kt % NSTG)*STAGE_B;
#pragma unroll
        for (int ks = 0; ks < 2; ks++){
            uint32_t fb = (uint32_t)(lane & 15)*RPAD + (uint32_t)(lane >> 4)*16u + ks*32u;
            uint32_t bh[2][4], bl[2][4];
#pragma unroll
            for (int nj = 0; nj < 2; nj++){
                uint32_t ab = sbase + 2*ARR_B + (uint32_t)(wn*32 + nj*16)*RPAD + fb;
                ldsm4(bh[nj], ab);
                ldsm4(bl[nj], ab + ARR_B);
            }
#pragma unroll
            for (int mi = 0; mi < 4; mi++){
                uint32_t aa = sbase + (uint32_t)(wm*64 + mi*16)*RPAD + fb;
                uint32_t a4h[4], a4l[4];
                ldsm4(a4h, aa);
                ldsm4(a4l, aa + ARR_B);
#pragma unroll
                for (int nf = 0; nf < 4; nf++){
                    int nj = nf >> 1, s = nf & 1;
                    uint32_t b0h = bh[nj][s], b1h = bh[nj][2+s];
                    uint32_t b0l = bl[nj][s], b1l = bl[nj][2+s];
                    mma16816(c[mi][nf], a4h, b0h, b1h);
                    mma16816(c[mi][nf], a4h, b0l, b1l);
                    mma16816(c[mi][nf], a4l, b0h, b1h);
                }
            }
        }
        __syncthreads();
    }

#pragma unroll
    for (int mi = 0; mi < 4; mi++){
#pragma unroll
        for (int nf = 0; nf < 4; nf++){
            int gr = row0 + wm*64 + mi*16 + (lane >> 2);
            int gc = col0 + wn*32 + nf*8 + (lane & 3)*2;
#pragma unroll
            for (int q = 0; q < 4; q++){
                int rr = gr + (q >> 1)*8;
                int cc = gc + (q & 1);
                if (rr < M && cc < N){
                    float v = c[mi][nf][q];
                    if (bias0) v += bias0[cc];
                    if (bias1) v += bias1[cc];
                    C[(size_t)rr*ldc + cc] = v;
                }
            }
        }
    }
}

// ---------------- split kernels ----------------
__global__ void split_rows_k(const float* __restrict__ src, long srcLd, int colOff,
                             int Kr, int Kp,
                             __nv_bfloat16* __restrict__ hi, __nv_bfloat16* __restrict__ lo)
{
    long r = blockIdx.x;
    const float* s = src + r*srcLd + colOff;
    __nv_bfloat16* Hh = hi + r*Kp;
    __nv_bfloat16* Ll = lo + r*Kp;
    for (int k = threadIdx.x; k < Kp; k += 256){
        float x = (k < Kr) ? s[k] : 0.f;
        __nv_bfloat16 h = __float2bfloat16(x);
        Hh[k] = h;
        Ll[k] = __float2bfloat16(x - __bfloat162float(h));
    }
}

__global__ void split_inp_k(const float* __restrict__ inp,
                            __nv_bfloat16* __restrict__ hi, __nv_bfloat16* __restrict__ lo)
{
    int m = blockIdx.x;             // m = t*B + b
    int t = m / B_, b = m % B_;
    const float* s = inp + ((long)b*T_ + t)*E_;
    __nv_bfloat16* Hh = hi + (long)m*KP_;
    __nv_bfloat16* Ll = lo + (long)m*KP_;
    for (int k = threadIdx.x; k < KP_; k += 256){
        float x = (k < E_) ? s[k] : 0.f;
        __nv_bfloat16 h = __float2bfloat16(x);
        Hh[k] = h;
        Ll[k] = __float2bfloat16(x - __bfloat162float(h));
    }
}

// ---------------- small SIMT GEMM for n2attn ----------------
__global__ __launch_bounds__(256,2)
void sgemm_nt(const float* __restrict__ A, const float* __restrict__ Bm,
              float* __restrict__ C,
              const float* __restrict__ bias0,
              int M, int N, int K, int lda, int ldb, int bColOff, int ldc)
{
    __shared__ float As[16][132];
    __shared__ float Bs[16][132];
    const int row0 = blockIdx.y*128, col0 = blockIdx.x*128;
    const int tid = threadIdx.x;
    const int tx = tid & 15, ty = tid >> 4;
    const int lk = tid & 15, lr0 = tid >> 4;
    long aOff[8]; int aOk[8]; long bOff[8]; int bOk[8];
#pragma unroll
    for (int i = 0; i < 8; i++){
        int gr = row0 + lr0 + i*16;
        aOk[i] = (gr < M); aOff[i] = (long)(aOk[i] ? gr : 0)*lda;
        int gc = col0 + lr0 + i*16;
        bOk[i] = (gc < N); bOff[i] = (long)(bOk[i] ? gc : 0)*ldb + bColOff;
    }
    float acc[8][8];
#pragma unroll
    for (int i = 0; i < 8; i++)
#pragma unroll
        for (int j = 0; j < 8; j++) acc[i][j] = 0.f;
    for (int k0 = 0; k0 < K; k0 += 16){
        int gk = k0 + lk; bool kOk = (gk < K);
#pragma unroll
        for (int i = 0; i < 8; i++){
            As[lk][lr0+i*16] = (kOk && aOk[i]) ? A[aOff[i]+gk] : 0.f;
            Bs[lk][lr0+i*16] = (kOk && bOk[i]) ? Bm[bOff[i]+gk] : 0.f;
        }
        __syncthreads();
#pragma unroll
        for (int kk = 0; kk < 16; kk++){
            float4 a0 = *(const float4*)&As[kk][ty*8];
            float4 a1 = *(const float4*)&As[kk][ty*8+4];
            float4 b0 = *(const float4*)&Bs[kk][tx*8];
            float4 b1 = *(const float4*)&Bs[kk][tx*8+4];
            float a[8] = {a0.x,a0.y,a0.z,a0.w,a1.x,a1.y,a1.z,a1.w};
            float b[8] = {b0.x,b0.y,b0.z,b0.w,b1.x,b1.y,b1.z,b1.w};
#pragma unroll
            for (int i = 0; i < 8; i++)
#pragma unroll
                for (int j = 0; j < 8; j++) acc[i][j] += a[i]*b[j];
        }
        __syncthreads();
    }
#pragma unroll
    for (int i = 0; i < 8; i++){
        int gr = row0 + ty*8 + i;
        if (gr >= M) continue;
#pragma unroll
        for (int j = 0; j < 8; j++){
            int gc = col0 + tx*8 + j;
            if (gc >= N) continue;
            float v = acc[i][j];
            if (bias0) v += bias0[gc];
            C[(long)gr*ldc + gc] = v;
        }
    }
}

__global__ void transpose_k(const float* __restrict__ src, float* __restrict__ dst,
                            int R, int Cc)
{
    __shared__ float t[32][33];
    int r0 = blockIdx.x*32, c0 = blockIdx.y*32;
    for (int i = threadIdx.y; i < 32; i += 8){
        int r = r0+i, c = c0+threadIdx.x;
        t[i][threadIdx.x] = (r < R && c < Cc) ? src[(long)r*Cc + c] : 0.f;
    }
    __syncthreads();
    for (int i = threadIdx.y; i < 32; i += 8){
        int dr = c0+i, dc = r0+threadIdx.x;
        if (dr < Cc && dc < R) dst[(long)dr*R + dc] = t[threadIdx.x][i];
    }
}

__global__ void skinny_k(const float* __restrict__ A, const float* __restrict__ Bm)
{
    __shared__ float Ash[8*1024];
    int w = threadIdx.x >> 5, lane = threadIdx.x & 31;
    int j = blockIdx.x*8 + w;
    float acc[8] = {0,0,0,0,0,0,0,0};
    for (int k0 = 0; k0 < E_; k0 += 1024){
        int kc = min(1024, E_ - k0);
        __syncthreads();
        for (int idx = threadIdx.x; idx < 8192; idx += 256){
            int r = idx >> 10, k = idx & 1023;
            Ash[idx] = (k < kc) ? A[(long)r*E_ + k0 + k] : 0.f;
        }
        __syncthreads();
        if (j < H_){
            const float* br = Bm + (long)j*EPNZ_ + k0;
            for (int k = lane; k < kc; k += 32){
                float wv = br[k];
#pragma unroll
                for (int b = 0; b < 8; b++) acc[b] += wv*Ash[b*1024 + k];
            }
        }
    }
    if (j < H_){
#pragma unroll
        for (int b = 0; b < 8; b++) acc[b] = wsum(acc[b]);
        if (lane == 0)
            for (int b = 0; b < 8; b++) g_emb0[b*H_ + j] = acc[b];
    }
}

__global__ void vvec_k(const float* __restrict__ embW, const float* __restrict__ out_b,
                       const float* __restrict__ emb_b)
{
    __shared__ float red[256];
    int j = blockIdx.x;
    float s = 0.f;
    for (int k = threadIdx.x; k < E_; k += 256) s += embW[(long)j*EPNZ_ + k]*out_b[k];
    red[threadIdx.x] = s; __syncthreads();
    for (int o = 128; o; o >>= 1){
        if (threadIdx.x < o) red[threadIdx.x] += red[threadIdx.x+o];
        __syncthreads();
    }
    if (threadIdx.x == 0) g_v2[j] = red[0] + emb_b[j];
}

__global__ void zero_k(){
    int i = blockIdx.x*256 + threadIdx.x;
    if (i < B_*H_){ g_h[0][i] = 0.f; g_c[i] = 0.f; }
}

__global__ void enc_step_k(const float* __restrict__ Whh, int t)
{
    __shared__ float hs[B_*H_];
    const float* hIn = g_h[t & 1];
    float* hOut = g_h[(t & 1) ^ 1];
    const float* gx = g_encGX + (long)t*B_*G4H_;
    int tid = threadIdx.x;
    for (int i = tid; i < B_*H_; i += 256) hs[i] = hIn[i];
    __syncthreads();
    int w = tid >> 5, lane = tid & 31;
    int j = blockIdx.x*8 + w;
    const float *w0 = Whh+(long)j*H_, *w1 = Whh+(long)(H_+j)*H_;
    const float *w2 = Whh+(long)(2*H_+j)*H_, *w3 = Whh+(long)(3*H_+j)*H_;
    float a0[8]={0},a1[8]={0},a2[8]={0},a3[8]={0};
    for (int k = lane; k < H_; k += 32){
        float x0=w0[k],x1=w1[k],x2=w2[k],x3=w3[k];
#pragma unroll
        for (int b = 0; b < 8; b++){
            float hv = hs[b*H_+k];
            a0[b]+=x0*hv; a1[b]+=x1*hv; a2[b]+=x2*hv; a3[b]+=x3*hv;
        }
    }
#pragma unroll
    for (int b = 0; b < 8; b++){
        a0[b]=wsum(a0[b]); a1[b]=wsum(a1[b]); a2[b]=wsum(a2[b]); a3[b]=wsum(a3[b]);
    }
    if (lane == 0){
#pragma unroll
        for (int b = 0; b < 8; b++){
            const float* gr = gx + (long)b*G4H_;
            float ig = sigf (gr[j]       + a0[b]);
            float fg = sigf (gr[H_+j]    + a1[b]);
            float gg = tanhf(gr[2*H_+j]  + a2[b]);
            float og = sigf (gr[3*H_+j]  + a3[b]);
            float c = fg*g_c[b*H_+j] + ig*gg;
            g_c[b*H_+j] = c;
            float h = og*tanhf(c);
            hOut[b*H_+j] = h;
            g_encT[((long)b*H_ + j)*T_ + t] = h;   // transposed layout
        }
    }
}

__global__ void emb0_k(const float* __restrict__ emb_b)
{
    int i = blockIdx.x*256 + threadIdx.x;
    if (i < B_*H_) g_emb[i] = g_emb0[i] + g_n1[i] + emb_b[i % H_];
}

__global__ void dk1_k(int s)
{
    __shared__ float hs[B_*H_];
    const float* hIn = g_h[s & 1];
    const float* n1 = g_n1 + (long)s*B_*H_;
    int tid = threadIdx.x;
    for (int i = tid; i < B_*H_; i += 256) hs[i] = hIn[i];
    __syncthreads();
    int w = tid >> 5, lane = tid & 31;
    int j = blockIdx.x*8 + w;
    const float* mr = g_M + (long)j*H_;
    float acc[8]={0,0,0,0,0,0,0,0};
    for (int k = lane; k < H_; k += 32){
        float mv = mr[k];
#pragma unroll
        for (int b = 0; b < 8; b++) acc[b] += mv*hs[b*H_+k];
    }
#pragma unroll
    for (int b = 0; b < 8; b++) acc[b] = wsum(acc[b]);
    if (lane == 0){
        float vb = g_v2[j];
        for (int b = 0; b < 8; b++) g_emb[b*H_+j] = acc[b] + n1[b*H_+j] + vb;
    }
}

// attention logits: grid 16 blocks, warp w handles t = bx*8+w, loop over b
__global__ void attlog_k(const float* __restrict__ attW, int s)
{
    __shared__ float xs[2*H_];
    int tid = threadIdx.x, w = tid >> 5, lane = tid & 31;
    int t = blockIdx.x*8 + w;
    const float* hIn = g_h[s & 1];
    const float* n2 = g_n2 + (long)s*B_*T_;
    const float* wr = attW + (long)t*3*H_;
    for (int b = 0; b < B_; b++){
        __syncthreads();
        for (int i = tid; i < H_; i += 256){ xs[i] = g_emb[b*H_+i]; xs[H_+i] = hIn[b*H_+i]; }
        __syncthreads();
        float sv = 0.f;
        for (int k = lane; k < 2*H_; k += 32) sv += wr[k]*xs[k];
        sv = wsum(sv);
        if (lane == 0) g_lg[b*T_+t] = sv + n2[b*T_+t];
    }
}

// softmax + applied (coalesced encT): grid 8 blocks
__global__ void attapp_k()
{
    __shared__ float ps[T_];
    int b = blockIdx.x, tid = threadIdx.x, w = tid >> 5, lane = tid & 31;
    if (w == 0){
        float m = -1e30f;
        for (int i = lane; i < T_; i += 32) m = fmaxf(m, g_lg[b*T_+i]);
#pragma unroll
        for (int o = 16; o; o >>= 1) m = fmaxf(m, __shfl_xor_sync(0xffffffffu, m, o));
        float ss = 0.f;
        for (int i = lane; i < T_; i += 32){ float e = expf(g_lg[b*T_+i]-m); ps[i] = e; ss += e; }
        ss = wsum(ss);
        float inv = 1.f/ss;
        for (int i = lane; i < T_; i += 32) ps[i] *= inv;
    }
    __syncthreads();
    for (int j = tid; j < H_; j += 256){
        const float* et = g_encT + ((long)b*H_ + j)*T_;
        float sv = 0.f;
#pragma unroll 8
        for (int t = 0; t < T_; t++) sv += ps[t]*et[t];
        g_app[b*H_+j] = sv;
    }
}

__global__ void dk3_k(const float* __restrict__ combW, const float* __restrict__ comb_b)
{
    __shared__ float sh[B_*H_];
    int tid = threadIdx.x;
    int w = tid >> 5, lane = tid & 31;
    int j = blockIdx.x*8 + w;
    const float* wr = combW + (long)j*2*H_;
    float acc[8]={0,0,0,0,0,0,0,0};
    for (int i = tid; i < B_*H_; i += 256) sh[i] = g_emb[i];
    __syncthreads();
    for (int k = lane; k < H_; k += 32){
        float wv = wr[k];
#pragma unroll
        for (int b = 0; b < 8; b++) acc[b] += wv*sh[b*H_+k];
    }
    __syncthreads();
    for (int i = tid; i < B_*H_; i += 256) sh[i] = g_app[i];
    __syncthreads();
    for (int k = lane; k < H_; k += 32){
        float wv = wr[H_+k];
#pragma unroll
        for (int b = 0; b < 8; b++) acc[b] += wv*sh[b*H_+k];
    }
#pragma unroll
    for (int b = 0; b < 8; b++) acc[b] = wsum(acc[b]);
    if (lane == 0){
        float cb = comb_b[j];
        for (int b = 0; b < 8; b++) g_outv[b*H_+j] = fmaxf(0.f, acc[b] + cb);
    }
}

__global__ void dk4_k(const float* __restrict__ Wih, const float* __restrict__ Whh,
                      const float* __restrict__ bih, const float* __restrict__ bhh, int s)
{
    __shared__ float sh[B_*H_];
    int pp = s & 1;
    const float* hIn = g_h[pp];
    float* hOut = g_h[pp ^ 1];
    int tid = threadIdx.x;
    int w = tid >> 5, lane = tid & 31;
    int j = blockIdx.x*8 + w;
    float a0[8]={0},a1[8]={0},a2[8]={0},a3[8]={0};
    for (int i = tid; i < B_*H_; i += 256) sh[i] = g_outv[i];
    __syncthreads();
    {
        const float *w0=Wih+(long)j*H_, *w1=Wih+(long)(H_+j)*H_;
        const float *w2=Wih+(long)(2*H_+j)*H_, *w3=Wih+(long)(3*H_+j)*H_;
        for (int k = lane; k < H_; k += 32){
            float x0=w0[k],x1=w1[k],x2=w2[k],x3=w3[k];
#pragma unroll
            for (int b = 0; b < 8; b++){
                float hv = sh[b*H_+k];
                a0[b]+=x0*hv; a1[b]+=x1*hv; a2[b]+=x2*hv; a3[b]+=x3*hv;
            }
        }
    }
    __syncthreads();
    for (int i = tid; i < B_*H_; i += 256) sh[i] = hIn[i];
    __syncthreads();
    {
        const float *w0=Whh+(long)j*H_, *w1=Whh+(long)(H_+j)*H_;
        const float *w2=Whh+(long)(2*H_+j)*H_, *w3=Whh+(long)(3*H_+j)*H_;
        for (int k = lane; k < H_; k += 32){
            float x0=w0[k],x1=w1[k],x2=w2[k],x3=w3[k];
#pragma unroll
            for (int b = 0; b < 8; b++){
                float hv = sh[b*H_+k];
                a0[b]+=x0*hv; a1[b]+=x1*hv; a2[b]+=x2*hv; a3[b]+=x3*hv;
            }
        }
    }
#pragma unroll
    for (int b = 0; b < 8; b++){
        a0[b]=wsum(a0[b]); a1[b]=wsum(a1[b]); a2[b]=wsum(a2[b]); a3[b]=wsum(a3[b]);
    }
    if (lane == 0){
        float bi0=bih[j]+bhh[j], bi1=bih[H_+j]+bhh[H_+j];
        float bi2=bih[2*H_+j]+bhh[2*H_+j], bi3=bih[3*H_+j]+bhh[3*H_+j];
#pragma unroll
        for (int b = 0; b < 8; b++){
            float ig = sigf (a0[b]+bi0);
            float fg = sigf (a1[b]+bi1);
            float gg = tanhf(a2[b]+bi2);
            float og = sigf (a3[b]+bi3);
            float c = fg*g_c[b*H_+j] + ig*gg;
            g_c[b*H_+j] = c;
            float h = og*tanhf(c);
            hOut[b*H_+j] = h;
            g_Hs[((long)s*B_ + b)*H_ + j] = h;
        }
    }
}

extern "C" void kernel_launch(void* const* d_in, const int* in_sizes, int n_in,
                              void* d_out, int out_size)
{
    int off = (in_sizes[1] == 1) ? 1 : 0;
    const float* input    = (const float*)d_in[0];
    const float* noise1   = (const float*)d_in[1+off];
    const float* noise2   = (const float*)d_in[2+off];
    const float* init_dec = (const float*)d_in[3+off];
    const float* enc_Wih  = (const float*)d_in[4+off];
    const float* enc_Whh  = (const float*)d_in[5+off];
    const float* enc_bih  = (const float*)d_in[6+off];
    const float* enc_bhh  = (const float*)d_in[7+off];
    const float* dec_Wih  = (const float*)d_in[8+off];
    const float* dec_Whh  = (const float*)d_in[9+off];
    const float* dec_bih  = (const float*)d_in[10+off];
    const float* dec_bhh  = (const float*)d_in[11+off];
    const float* emb_W    = (const float*)d_in[12+off];
    const float* emb_b    = (const float*)d_in[13+off];
    const float* attn_W   = (const float*)d_in[14+off];
    const float* attn_b   = (const float*)d_in[15+off];
    const float* comb_W   = (const float*)d_in[16+off];
    const float* comb_b   = (const float*)d_in[17+off];
    const float* out_W    = (const float*)d_in[18+off];
    const float* out_b    = (const float*)d_in[19+off];
    float* out = (float*)d_out;

    float *p_outWT, *p_gx, *p_M, *p_n1, *p_n2, *p_Hs;
    cudaGetSymbolAddress((void**)&p_outWT, g_outWT);
    cudaGetSymbolAddress((void**)&p_gx,    g_encGX);
    cudaGetSymbolAddress((void**)&p_M,     g_M);
    cudaGetSymbolAddress((void**)&p_n1,    g_n1);
    cudaGetSymbolAddress((void**)&p_n2,    g_n2);
    cudaGetSymbolAddress((void**)&p_Hs,    g_Hs);
    __nv_bfloat16 *inpH,*inpL,*wihH,*wihL,*embEH,*embEL,*embNH,*embNL;
    __nv_bfloat16 *oWTH,*oWTL,*oWH,*oWL,*nzH,*nzL,*HsH,*HsL;
    cudaGetSymbolAddress((void**)&inpH, g_inpH);   cudaGetSymbolAddress((void**)&inpL, g_inpL);
    cudaGetSymbolAddress((void**)&wihH, g_wihH);   cudaGetSymbolAddress((void**)&wihL, g_wihL);
    cudaGetSymbolAddress((void**)&embEH, g_embEH); cudaGetSymbolAddress((void**)&embEL, g_embEL);
    cudaGetSymbolAddress((void**)&embNH, g_embNH); cudaGetSymbolAddress((void**)&embNL, g_embNL);
    cudaGetSymbolAddress((void**)&oWTH, g_oWTH);   cudaGetSymbolAddress((void**)&oWTL, g_oWTL);
    cudaGetSymbolAddress((void**)&oWH, g_oWH);     cudaGetSymbolAddress((void**)&oWL, g_oWL);
    cudaGetSymbolAddress((void**)&nzH, g_nzH);     cudaGetSymbolAddress((void**)&nzL, g_nzL);
    cudaGetSymbolAddress((void**)&HsH, g_HsH);     cudaGetSymbolAddress((void**)&HsL, g_HsL);

    cudaFuncSetAttribute(mma_gemm, cudaFuncAttributeMaxDynamicSharedMemorySize, SMEM_B);

    zero_k<<<32,256>>>();

    // ---- operand prep (bf16 hi/lo splits, padded K) ----
    transpose_k<<<dim3((E_+31)/32,(H_+31)/32), dim3(32,8)>>>(out_W, p_outWT, E_, H_);
    split_inp_k<<<T_*B_,256>>>(input, inpH, inpL);
    split_rows_k<<<G4H_,256>>>(enc_Wih, E_, 0, E_, KP_, wihH, wihL);
    split_rows_k<<<H_,256>>>(emb_W, EPNZ_, 0, E_, KP_, embEH, embEL);
    split_rows_k<<<H_,256>>>(emb_W, EPNZ_, E_, NZ_, NZP_, embNH, embNL);
    split_rows_k<<<H_,256>>>(p_outWT, E_, 0, E_, KP_, oWTH, oWTL);
    split_rows_k<<<E_,256>>>(out_W, H_, 0, H_, HP_, oWH, oWL);
    split_rows_k<<<S_*B_,256>>>(noise1, NZ_, 0, NZ_, NZP_, nzH, nzL);

    // ---- batched GEMMs on HMMA (grid.x = M-blocks so each wave shares B) ----
    // G1: enc_gx [T*B, 4H] = input_g @ Wih^T + biases
    mma_gemm<<<dim3(8, 32), 256, SMEM_B>>>(inpH, inpL, wihH, wihL,
        p_gx, enc_bih, enc_bhh, T_*B_, G4H_, KP_, G4H_);
    // G2: M [H,H] = emb_W[:, :E] @ out_W
    mma_gemm<<<dim3(8, 8), 256, SMEM_B>>>(embEH, embEL, oWTH, oWTL,
        p_M, 0, 0, H_, H_, KP_, H_);
    // G3: n1emb [S*B, H] = noise1 @ emb_W[:, E:]^T
    mma_gemm<<<dim3(4, 8), 256, SMEM_B>>>(nzH, nzL, embNH, embNL,
        p_n1, 0, 0, S_*B_, H_, NZP_, H_);

    vvec_k<<<H_,256>>>(emb_W, out_b, emb_b);

    // n2attn [S*B, T] = noise2 @ attn_W[:, 2H:]^T + attn_b (tiny, SIMT)
    sgemm_nt<<<dim3(1,4),256>>>(noise2, attn_W, p_n2, attn_b,
        S_*B_, T_, H_, H_, 3*H_, 2*H_, T_);

    skinny_k<<<H_/8,256>>>(init_dec, emb_W);

    for (int t = 0; t < T_; t++)
        enc_step_k<<<H_/8,256>>>(enc_Whh, t);

    for (int s = 0; s < S_; s++){
        if (s == 0) emb0_k<<<32,256>>>(emb_b);
        else        dk1_k<<<H_/8,256>>>(s);
        attlog_k<<<T_/8,256>>>(attn_W, s);
        attapp_k<<<B_,256>>>();
        dk3_k<<<H_/8,256>>>(comb_W, comb_b);
        dk4_k<<<H_/8,256>>>(dec_Wih, dec_Whh, dec_bih, dec_bhh, s);
    }

    // G4: summary [S*B, E] = Hs @ out_W^T + out_b
    split_rows_k<<<S_*B_,256>>>(p_Hs, H_, 0, H_, HP_, HsH, HsL);
    mma_gemm<<<dim3(4, 239), 256, SMEM_B>>>(HsH, HsL, oWH, oWL,
        out, out_b, 0, S_*B_, E_, HP_, E_);
}

// round 8
// speedup vs baseline: 1.1359x; 1.1359x over previous
#include <cuda_runtime.h>
#include <cuda_bf16.h>
#include <math.h>
#include <stdint.h>

#define B_ 8
#define T_ 128
#define E_ 30522
#define H_ 1000
#define S_ 64
#define NZ_ 10000
#define EPNZ_ 40522
#define G4H_ (4*H_)
#define KP_ 30528   // E padded to mult of 32
#define NZP_ 10016  // NZ padded to mult of 32
#define HP_ 1024    // H padded to mult of 32

// ---------------- fp32 scratch ----------------
__device__ float g_encGX[(size_t)T_*B_*G4H_];
__device__ float g_M[(size_t)H_*H_];
__device__ float g_n1[(size_t)S_*B_*H_];
__device__ float g_n2[(size_t)S_*B_*T_];
__device__ float g_emb0[B_*H_];
__device__ float g_v2[H_];
__device__ float g_encBTH[(size_t)B_*T_*H_];
__device__ float g_h[2][B_*H_];
__device__ float g_c[B_*H_];
__device__ float g_emb[B_*H_];
__device__ float g_app[B_*H_];
__device__ float g_outv[B_*H_];
__device__ float g_Hs[(size_t)S_*B_*H_];

// ---------------- bf16 split operands ----------------
__device__ __nv_bfloat16 g_inpH[(size_t)T_*B_*KP_],  g_inpL[(size_t)T_*B_*KP_];
__device__ __nv_bfloat16 g_wihH[(size_t)G4H_*KP_],   g_wihL[(size_t)G4H_*KP_];
__device__ __nv_bfloat16 g_embEH[(size_t)H_*KP_],    g_embEL[(size_t)H_*KP_];
__device__ __nv_bfloat16 g_embNH[(size_t)H_*NZP_],   g_embNL[(size_t)H_*NZP_];
__device__ __nv_bfloat16 g_oWTH[(size_t)H_*KP_],     g_oWTL[(size_t)H_*KP_];
__device__ __nv_bfloat16 g_oWH[(size_t)E_*HP_],      g_oWL[(size_t)E_*HP_];
__device__ __nv_bfloat16 g_nzH[(size_t)S_*B_*NZP_],  g_nzL[(size_t)S_*B_*NZP_];
__device__ __nv_bfloat16 g_HsH[(size_t)S_*B_*HP_],   g_HsL[(size_t)S_*B_*HP_];

__device__ __forceinline__ float wsum(float v){
#pragma unroll
    for (int o = 16; o; o >>= 1) v += __shfl_xor_sync(0xffffffffu, v, o);
    return v;
}
__device__ __forceinline__ float sigf(float x){ return 1.f/(1.f+expf(-x)); }

__device__ __forceinline__ uint32_t smem_u32(const void* p){
    uint32_t a;
    asm("{ .reg .u64 t; cvta.to.shared.u64 t, %1; cvt.u32.u64 %0, t; }" : "=r"(a) : "l"(p));
    return a;
}
__device__ __forceinline__ void ldsm4(uint32_t* r, uint32_t a){
    asm volatile("ldmatrix.sync.aligned.m8n8.x4.shared.b16 {%0,%1,%2,%3}, [%4];"
        : "=r"(r[0]),"=r"(r[1]),"=r"(r[2]),"=r"(r[3]) : "r"(a));
}
__device__ __forceinline__ void mma16816(float* c, const uint32_t* a,
                                         uint32_t b0, uint32_t b1){
    asm volatile("mma.sync.aligned.m16n8k16.row.col.f32.bf16.bf16.f32 "
        "{%0,%1,%2,%3}, {%4,%5,%6,%7}, {%8,%9}, {%0,%1,%2,%3};"
        : "+f"(c[0]),"+f"(c[1]),"+f"(c[2]),"+f"(c[3])
        : "r"(a[0]),"r"(a[1]),"r"(a[2]),"r"(a[3]), "r"(b0),"r"(b1));
}
__device__ __forceinline__ void cpasync16(uint32_t dst, const void* src, int sz){
    asm volatile("cp.async.cg.shared.global [%0], [%1], 16, %2;"
        :: "r"(dst), "l"(src), "r"(sz));
}

#define BKE 32
#define RPAD 80                 // row stride bytes (40 bf16)
#define ARR_B (128*RPAD)        // 10240
#define STAGE_B (4*ARR_B)       // 40960
#define SMEM_B (2*STAGE_B)      // 81920

// ---------------- split-bf16 HMMA NT GEMM: C = A@B^T (+bias) ----------------
// A[M,K] bf16 hi/lo, B[N,K] bf16 hi/lo (K mult of 32), C[M,ldc] fp32
__global__ __launch_bounds__(256,2)
void mma_gemm(const __nv_bfloat16* __restrict__ Ah, const __nv_bfloat16* __restrict__ Al,
              const __nv_bfloat16* __restrict__ Bh, const __nv_bfloat16* __restrict__ Bl,
              float* __restrict__ C, const float* __restrict__ bias0,
              const float* __restrict__ bias1,
              int M, int N, int K, int ldc)
{
    extern __shared__ char smem[];
    uint32_t sb = smem_u32(smem);
    const int tid = threadIdx.x, lane = tid & 31, wid = tid >> 5;
    const int row0 = blockIdx.y*128, col0 = blockIdx.x*128;
    const int wm = wid >> 2, wn = wid & 3;

    float c[4][4][4];
#pragma unroll
    for (int i = 0; i < 4; i++)
#pragma unroll
        for (int j = 0; j < 4; j++)
#pragma unroll
            for (int q = 0; q < 4; q++) c[i][j][q] = 0.f;

    const int NT = K/BKE;

    auto load = [&](int kt, int stg){
        int k0 = kt*BKE;
#pragma unroll
        for (int i = 0; i < 8; i++){
            int v = tid + i*256;
            int arr = v >> 9;              // 0:Ah 1:Al 2:Bh 3:Bl
            int r = (v >> 2) & 127;
            int ch = v & 3;
            int gk = k0 + ch*8;
            const __nv_bfloat16* src; int gr, lim;
            if (arr < 2){ gr = row0 + r; lim = M; src = arr ? Al : Ah; }
            else        { gr = col0 + r; lim = N; src = (arr == 3) ? Bl : Bh; }
            int ok = (gr < lim);
            const __nv_bfloat16* g = src + (size_t)(ok ? gr : 0)*K + gk;
            uint32_t d = sb + stg*STAGE_B + arr*ARR_B + r*RPAD + ch*16;
            cpasync16(d, g, ok ? 16 : 0);
        }
        asm volatile("cp.async.commit_group;" ::: "memory");
    };

    load(0, 0);
    for (int kt = 0; kt < NT; kt++){
        if (kt + 1 < NT){
            load(kt+1, (kt+1) & 1);
            asm volatile("cp.async.wait_group 1;" ::: "memory");
        } else {
            asm volatile("cp.async.wait_group 0;" ::: "memory");
        }
        __syncthreads();

        uint32_t sbase = sb + (kt & 1)*STAGE_B;
#pragma unroll
        for (int ks = 0; ks < 2; ks++){
            uint32_t fb = (uint32_t)(lane & 15)*RPAD + (uint32_t)(lane >> 4)*16u + ks*32u;
            uint32_t bh[2][4], bl[2][4];
#pragma unroll
            for (int nj = 0; nj < 2; nj++){
                uint32_t ab = sbase + 2*ARR_B + (uint32_t)(wn*32 + nj*16)*RPAD + fb;
                ldsm4(bh[nj], ab);
                ldsm4(bl[nj], ab + ARR_B);
            }
#pragma unroll
            for (int mi = 0; mi < 4; mi++){
                uint32_t aa = sbase + (uint32_t)(wm*64 + mi*16)*RPAD + fb;
                uint32_t a4h[4], a4l[4];
                ldsm4(a4h, aa);
                ldsm4(a4l, aa + ARR_B);
#pragma unroll
                for (int nf = 0; nf < 4; nf++){
                    int nj = nf >> 1, s = nf & 1;
                    uint32_t b0h = bh[nj][s], b1h = bh[nj][2+s];
                    uint32_t b0l = bl[nj][s], b1l = bl[nj][2+s];
                    mma16816(c[mi][nf], a4h, b0h, b1h);
                    mma16816(c[mi][nf], a4h, b0l, b1l);
                    mma16816(c[mi][nf], a4l, b0h, b1h);
                }
            }
        }
        __syncthreads();
    }

    // epilogue
#pragma unroll
    for (int mi = 0; mi < 4; mi++){
#pragma unroll
        for (int nf = 0; nf < 4; nf++){
            int gr = row0 + wm*64 + mi*16 + (lane >> 2);
            int gc = col0 + wn*32 + nf*8 + (lane & 3)*2;
#pragma unroll
            for (int q = 0; q < 4; q++){
                int rr = gr + (q >> 1)*8;
                int cc = gc + (q & 1);
                if (rr < M && cc < N){
                    float v = c[mi][nf][q];
                    if (bias0) v += bias0[cc];
                    if (bias1) v += bias1[cc];
                    C[(size_t)rr*ldc + cc] = v;
                }
            }
        }
    }
}

// ---------------- split kernels ----------------
__global__ void split_rows_k(const float* __restrict__ src, long srcLd, int colOff,
                             int Kr, int Kp,
                             __nv_bfloat16* __restrict__ hi, __nv_bfloat16* __restrict__ lo)
{
    long r = blockIdx.x;
    const float* s = src + r*srcLd + colOff;
    __nv_bfloat16* Hh = hi + r*Kp;
    __nv_bfloat16* Ll = lo + r*Kp;
    for (int k = threadIdx.x; k < Kp; k += 256){
        float x = (k < Kr) ? s[k] : 0.f;
        __nv_bfloat16 h = __float2bfloat16(x);
        Hh[k] = h;
        Ll[k] = __float2bfloat16(x - __bfloat162float(h));
    }
}

__global__ void split_inp_k(const float* __restrict__ inp,
                            __nv_bfloat16* __restrict__ hi, __nv_bfloat16* __restrict__ lo)
{
    int m = blockIdx.x;             // m = t*B + b
    int t = m / B_, b = m % B_;
    const float* s = inp + ((long)b*T_ + t)*E_;
    __nv_bfloat16* Hh = hi + (long)m*KP_;
    __nv_bfloat16* Ll = lo + (long)m*KP_;
    for (int k = threadIdx.x; k < KP_; k += 256){
        float x = (k < E_) ? s[k] : 0.f;
        __nv_bfloat16 h = __float2bfloat16(x);
        Hh[k] = h;
        Ll[k] = __float2bfloat16(x - __bfloat162float(h));
    }
}

// fused transpose+split: out_W [E,H] -> oWT hi/lo [H,KP_]
__global__ void split_tr_k(const float* __restrict__ src,
                           __nv_bfloat16* __restrict__ hi, __nv_bfloat16* __restrict__ lo)
{
    __shared__ float t[32][33];
    int e0 = blockIdx.x*32, j0 = blockIdx.y*32;
    for (int i = threadIdx.y; i < 32; i += 8){
        int e = e0+i, j = j0+threadIdx.x;
        t[i][threadIdx.x] = (e < E_ && j < H_) ? src[(long)e*H_ + j] : 0.f;
    }
    __syncthreads();
    for (int i = threadIdx.y; i < 32; i += 8){
        int j = j0+i, e = e0+threadIdx.x;
        if (j < H_ && e < KP_){
            float x = t[threadIdx.x][i];
            __nv_bfloat16 h = __float2bfloat16(x);
            hi[(long)j*KP_ + e] = h;
            lo[(long)j*KP_ + e] = __float2bfloat16(x - __bfloat162float(h));
        }
    }
}

// ---------------- small SIMT GEMM for n2attn ----------------
__global__ __launch_bounds__(256,2)
void sgemm_nt(const float* __restrict__ A, const float* __restrict__ Bm,
              float* __restrict__ C,
              const float* __restrict__ bias0,
              int M, int N, int K, int lda, int ldb, int bColOff, int ldc)
{
    __shared__ float As[16][132];
    __shared__ float Bs[16][132];
    const int row0 = blockIdx.y*128, col0 = blockIdx.x*128;
    const int tid = threadIdx.x;
    const int tx = tid & 15, ty = tid >> 4;
    const int lk = tid & 15, lr0 = tid >> 4;
    long aOff[8]; int aOk[8]; long bOff[8]; int bOk[8];
#pragma unroll
    for (int i = 0; i < 8; i++){
        int gr = row0 + lr0 + i*16;
        aOk[i] = (gr < M); aOff[i] = (long)(aOk[i] ? gr : 0)*lda;
        int gc = col0 + lr0 + i*16;
        bOk[i] = (gc < N); bOff[i] = (long)(bOk[i] ? gc : 0)*ldb + bColOff;
    }
    float acc[8][8];
#pragma unroll
    for (int i = 0; i < 8; i++)
#pragma unroll
        for (int j = 0; j < 8; j++) acc[i][j] = 0.f;
    for (int k0 = 0; k0 < K; k0 += 16){
        int gk = k0 + lk; bool kOk = (gk < K);
#pragma unroll
        for (int i = 0; i < 8; i++){
            As[lk][lr0+i*16] = (kOk && aOk[i]) ? A[aOff[i]+gk] : 0.f;
            Bs[lk][lr0+i*16] = (kOk && bOk[i]) ? Bm[bOff[i]+gk] : 0.f;
        }
        __syncthreads();
#pragma unroll
        for (int kk = 0; kk < 16; kk++){
            float4 a0 = *(const float4*)&As[kk][ty*8];
            float4 a1 = *(const float4*)&As[kk][ty*8+4];
            float4 b0 = *(const float4*)&Bs[kk][tx*8];
            float4 b1 = *(const float4*)&Bs[kk][tx*8+4];
            float a[8] = {a0.x,a0.y,a0.z,a0.w,a1.x,a1.y,a1.z,a1.w};
            float b[8] = {b0.x,b0.y,b0.z,b0.w,b1.x,b1.y,b1.z,b1.w};
#pragma unroll
            for (int i = 0; i < 8; i++)
#pragma unroll
                for (int j = 0; j < 8; j++) acc[i][j] += a[i]*b[j];
        }
        __syncthreads();
    }
#pragma unroll
    for (int i = 0; i < 8; i++){
        int gr = row0 + ty*8 + i;
        if (gr >= M) continue;
#pragma unroll
        for (int j = 0; j < 8; j++){
            int gc = col0 + tx*8 + j;
            if (gc >= N) continue;
            float v = acc[i][j];
            if (bias0) v += bias0[gc];
            C[(long)gr*ldc + gc] = v;
        }
    }
}

__global__ void skinny_k(const float* __restrict__ A, const float* __restrict__ Bm)
{
    __shared__ float Ash[8*1024];
    int w = threadIdx.x >> 5, lane = threadIdx.x & 31;
    int j = blockIdx.x*8 + w;
    float acc[8] = {0,0,0,0,0,0,0,0};
    for (int k0 = 0; k0 < E_; k0 += 1024){
        int kc = min(1024, E_ - k0);
        __syncthreads();
        for (int idx = threadIdx.x; idx < 8192; idx += 256){
            int r = idx >> 10, k = idx & 1023;
            Ash[idx] = (k < kc) ? A[(long)r*E_ + k0 + k] : 0.f;
        }
        __syncthreads();
        if (j < H_){
            const float* br = Bm + (long)j*EPNZ_ + k0;
            for (int k = lane; k < kc; k += 32){
                float wv = br[k];
#pragma unroll
                for (int b = 0; b < 8; b++) acc[b] += wv*Ash[b*1024 + k];
            }
        }
    }
    if (j < H_){
#pragma unroll
        for (int b = 0; b < 8; b++) acc[b] = wsum(acc[b]);
        if (lane == 0)
            for (int b = 0; b < 8; b++) g_emb0[b*H_ + j] = acc[b];
    }
}

__global__ void vvec_k(const float* __restrict__ embW, const float* __restrict__ out_b,
                       const float* __restrict__ emb_b)
{
    __shared__ float red[256];
    int j = blockIdx.x;
    float s = 0.f;
    for (int k = threadIdx.x; k < E_; k += 256) s += embW[(long)j*EPNZ_ + k]*out_b[k];
    red[threadIdx.x] = s; __syncthreads();
    for (int o = 128; o; o >>= 1){
        if (threadIdx.x < o) red[threadIdx.x] += red[threadIdx.x+o];
        __syncthreads();
    }
    if (threadIdx.x == 0) g_v2[j] = red[0] + emb_b[j];
}

__global__ void zero_k(){
    int i = blockIdx.x*256 + threadIdx.x;
    if (i < B_*H_){ g_h[0][i] = 0.f; g_c[i] = 0.f; }
}

__global__ void enc_step_k(const float* __restrict__ Whh, int t)
{
    __shared__ float hs[B_*H_];
    const float* hIn = g_h[t & 1];
    float* hOut = g_h[(t & 1) ^ 1];
    const float* gx = g_encGX + (long)t*B_*G4H_;
    int tid = threadIdx.x;
    for (int i = tid; i < B_*H_; i += 256) hs[i] = hIn[i];
    __syncthreads();
    int w = tid >> 5, lane = tid & 31;
    int j = blockIdx.x*8 + w;
    const float *w0 = Whh+(long)j*H_, *w1 = Whh+(long)(H_+j)*H_;
    const float *w2 = Whh+(long)(2*H_+j)*H_, *w3 = Whh+(long)(3*H_+j)*H_;
    float a0[8]={0},a1[8]={0},a2[8]={0},a3[8]={0};
    for (int k = lane; k < H_; k += 32){
        float x0=w0[k],x1=w1[k],x2=w2[k],x3=w3[k];
#pragma unroll
        for (int b = 0; b < 8; b++){
            float hv = hs[b*H_+k];
            a0[b]+=x0*hv; a1[b]+=x1*hv; a2[b]+=x2*hv; a3[b]+=x3*hv;
        }
    }
#pragma unroll
    for (int b = 0; b < 8; b++){
        a0[b]=wsum(a0[b]); a1[b]=wsum(a1[b]); a2[b]=wsum(a2[b]); a3[b]=wsum(a3[b]);
    }
    if (lane == 0){
#pragma unroll
        for (int b = 0; b < 8; b++){
            const float* gr = gx + (long)b*G4H_;
            float ig = sigf (gr[j]       + a0[b]);
            float fg = sigf (gr[H_+j]    + a1[b]);
            float gg = tanhf(gr[2*H_+j]  + a2[b]);
            float og = sigf (gr[3*H_+j]  + a3[b]);
            float c = fg*g_c[b*H_+j] + ig*gg;
            g_c[b*H_+j] = c;
            float h = og*tanhf(c);
            hOut[b*H_+j] = h;
            g_encBTH[((long)b*T_ + t)*H_ + j] = h;
        }
    }
}

__global__ void emb0_k(const float* __restrict__ emb_b)
{
    int i = blockIdx.x*256 + threadIdx.x;
    if (i < B_*H_) g_emb[i] = g_emb0[i] + g_n1[i] + emb_b[i % H_];
}

__global__ void dk1_k(int s)
{
    __shared__ float hs[B_*H_];
    const float* hIn = g_h[s & 1];
    const float* n1 = g_n1 + (long)s*B_*H_;
    int tid = threadIdx.x;
    for (int i = tid; i < B_*H_; i += 256) hs[i] = hIn[i];
    __syncthreads();
    int w = tid >> 5, lane = tid & 31;
    int j = blockIdx.x*8 + w;
    const float* mr = g_M + (long)j*H_;
    float acc[8]={0,0,0,0,0,0,0,0};
    for (int k = lane; k < H_; k += 32){
        float mv = mr[k];
#pragma unroll
        for (int b = 0; b < 8; b++) acc[b] += mv*hs[b*H_+k];
    }
#pragma unroll
    for (int b = 0; b < 8; b++) acc[b] = wsum(acc[b]);
    if (lane == 0){
        float vb = g_v2[j];
        for (int b = 0; b < 8; b++) g_emb[b*H_+j] = acc[b] + n1[b*H_+j] + vb;
    }
}

__global__ void dk2_k(const float* __restrict__ attW, int s)
{
    __shared__ float xs[2*H_];
    __shared__ float lg[T_];
    __shared__ float ps[T_];
    int b = blockIdx.x, tid = threadIdx.x;
    const float* hIn = g_h[s & 1];
    const float* n2 = g_n2 + (long)s*B_*T_;
    for (int i = tid; i < H_; i += 256){ xs[i] = g_emb[b*H_+i]; xs[H_+i] = hIn[b*H_+i]; }
    __syncthreads();
    int w = tid >> 5, lane = tid & 31;
    for (int ti = 0; ti < 16; ti++){
        int t = w*16 + ti;
        const float* wr = attW + (long)t*3*H_;
        float sv = 0.f;
        for (int k = lane; k < 2*H_; k += 32) sv += wr[k]*xs[k];
        sv = wsum(sv);
        if (lane == 0) lg[t] = sv + n2[b*T_+t];
    }
    __syncthreads();
    if (w == 0){
        float m = -1e30f;
        for (int i = lane; i < T_; i += 32) m = fmaxf(m, lg[i]);
#pragma unroll
        for (int o = 16; o; o >>= 1) m = fmaxf(m, __shfl_xor_sync(0xffffffffu, m, o));
        float ss = 0.f;
        for (int i = lane; i < T_; i += 32){ float e = expf(lg[i]-m); ps[i] = e; ss += e; }
        ss = wsum(ss);
        float inv = 1.f/ss;
        for (int i = lane; i < T_; i += 32) ps[i] *= inv;
    }
    __syncthreads();
    for (int j = tid; j < H_; j += 256){
        float sv = 0.f;
        const float* eb = g_encBTH + (long)b*T_*H_ + j;
#pragma unroll 4
        for (int t = 0; t < T_; t++) sv += ps[t]*eb[(long)t*H_];
        g_app[b*H_+j] = sv;
    }
}

__global__ void dk3_k(const float* __restrict__ combW, const float* __restrict__ comb_b)
{
    __shared__ float sh[B_*H_];
    int tid = threadIdx.x;
    int w = tid >> 5, lane = tid & 31;
    int j = blockIdx.x*8 + w;
    const float* wr = combW + (long)j*2*H_;
    float acc[8]={0,0,0,0,0,0,0,0};
    for (int i = tid; i < B_*H_; i += 256) sh[i] = g_emb[i];
    __syncthreads();
    for (int k = lane; k < H_; k += 32){
        float wv = wr[k];
#pragma unroll
        for (int b = 0; b < 8; b++) acc[b] += wv*sh[b*H_+k];
    }
    __syncthreads();
    for (int i = tid; i < B_*H_; i += 256) sh[i] = g_app[i];
    __syncthreads();
    for (int k = lane; k < H_; k += 32){
        float wv = wr[H_+k];
#pragma unroll
        for (int b = 0; b < 8; b++) acc[b] += wv*sh[b*H_+k];
    }
#pragma unroll
    for (int b = 0; b < 8; b++) acc[b] = wsum(acc[b]);
    if (lane == 0){
        float cb = comb_b[j];
        for (int b = 0; b < 8; b++) g_outv[b*H_+j] = fmaxf(0.f, acc[b] + cb);
    }
}

__global__ void dk4_k(const float* __restrict__ Wih, const float* __restrict__ Whh,
                      const float* __restrict__ bih, const float* __restrict__ bhh, int s)
{
    __shared__ float sh[B_*H_];
    int pp = s & 1;
    const float* hIn = g_h[pp];
    float* hOut = g_h[pp ^ 1];
    int tid = threadIdx.x;
    int w = tid >> 5, lane = tid & 31;
    int j = blockIdx.x*8 + w;
    float a0[8]={0},a1[8]={0},a2[8]={0},a3[8]={0};
    for (int i = tid; i < B_*H_; i += 256) sh[i] = g_outv[i];
    __syncthreads();
    {
        const float *w0=Wih+(long)j*H_, *w1=Wih+(long)(H_+j)*H_;
        const float *w2=Wih+(long)(2*H_+j)*H_, *w3=Wih+(long)(3*H_+j)*H_;
        for (int k = lane; k < H_; k += 32){
            float x0=w0[k],x1=w1[k],x2=w2[k],x3=w3[k];
#pragma unroll
            for (int b = 0; b < 8; b++){
                float hv = sh[b*H_+k];
                a0[b]+=x0*hv; a1[b]+=x1*hv; a2[b]+=x2*hv; a3[b]+=x3*hv;
            }
        }
    }
    __syncthreads();
    for (int i = tid; i < B_*H_; i += 256) sh[i] = hIn[i];
    __syncthreads();
    {
        const float *w0=Whh+(long)j*H_, *w1=Whh+(long)(H_+j)*H_;
        const float *w2=Whh+(long)(2*H_+j)*H_, *w3=Whh+(long)(3*H_+j)*H_;
        for (int k = lane; k < H_; k += 32){
            float x0=w0[k],x1=w1[k],x2=w2[k],x3=w3[k];
#pragma unroll
            for (int b = 0; b < 8; b++){
                float hv = sh[b*H_+k];
                a0[b]+=x0*hv; a1[b]+=x1*hv; a2[b]+=x2*hv; a3[b]+=x3*hv;
            }
        }
    }
#pragma unroll
    for (int b = 0; b < 8; b++){
        a0[b]=wsum(a0[b]); a1[b]=wsum(a1[b]); a2[b]=wsum(a2[b]); a3[b]=wsum(a3[b]);
    }
    if (lane == 0){
        float bi0=bih[j]+bhh[j], bi1=bih[H_+j]+bhh[H_+j];
        float bi2=bih[2*H_+j]+bhh[2*H_+j], bi3=bih[3*H_+j]+bhh[3*H_+j];
#pragma unroll
        for (int b = 0; b < 8; b++){
            float ig = sigf (a0[b]+bi0);
            float fg = sigf (a1[b]+bi1);
            float gg = tanhf(a2[b]+bi2);
            float og = sigf (a3[b]+bi3);
            float c = fg*g_c[b*H_+j] + ig*gg;
            g_c[b*H_+j] = c;
            float h = og*tanhf(c);
            hOut[b*H_+j] = h;
            g_Hs[((long)s*B_ + b)*H_ + j] = h;
        }
    }
}

extern "C" void kernel_launch(void* const* d_in, const int* in_sizes, int n_in,
                              void* d_out, int out_size)
{
    int off = (in_sizes[1] == 1) ? 1 : 0;
    const float* input    = (const float*)d_in[0];
    const float* noise1   = (const float*)d_in[1+off];
    const float* noise2   = (const float*)d_in[2+off];
    const float* init_dec = (const float*)d_in[3+off];
    const float* enc_Wih  = (const float*)d_in[4+off];
    const float* enc_Whh  = (const float*)d_in[5+off];
    const float* enc_bih  = (const float*)d_in[6+off];
    const float* enc_bhh  = (const float*)d_in[7+off];
    const float* dec_Wih  = (const float*)d_in[8+off];
    const float* dec_Whh  = (const float*)d_in[9+off];
    const float* dec_bih  = (const float*)d_in[10+off];
    const float* dec_bhh  = (const float*)d_in[11+off];
    const float* emb_W    = (const float*)d_in[12+off];
    const float* emb_b    = (const float*)d_in[13+off];
    const float* attn_W   = (const float*)d_in[14+off];
    const float* attn_b   = (const float*)d_in[15+off];
    const float* comb_W   = (const float*)d_in[16+off];
    const float* comb_b   = (const float*)d_in[17+off];
    const float* out_W    = (const float*)d_in[18+off];
    const float* out_b    = (const float*)d_in[19+off];
    float* out = (float*)d_out;

    float *p_gx, *p_M, *p_n1, *p_n2, *p_Hs;
    cudaGetSymbolAddress((void**)&p_gx,    g_encGX);
    cudaGetSymbolAddress((void**)&p_M,     g_M);
    cudaGetSymbolAddress((void**)&p_n1,    g_n1);
    cudaGetSymbolAddress((void**)&p_n2,    g_n2);
    cudaGetSymbolAddress((void**)&p_Hs,    g_Hs);
    __nv_bfloat16 *inpH,*inpL,*wihH,*wihL,*embEH,*embEL,*embNH,*embNL;
    __nv_bfloat16 *oWTH,*oWTL,*oWH,*oWL,*nzH,*nzL,*HsH,*HsL;
    cudaGetSymbolAddress((void**)&inpH, g_inpH);   cudaGetSymbolAddress((void**)&inpL, g_inpL);
    cudaGetSymbolAddress((void**)&wihH, g_wihH);   cudaGetSymbolAddress((void**)&wihL, g_wihL);
    cudaGetSymbolAddress((void**)&embEH, g_embEH); cudaGetSymbolAddress((void**)&embEL, g_embEL);
    cudaGetSymbolAddress((void**)&embNH, g_embNH); cudaGetSymbolAddress((void**)&embNL, g_embNL);
    cudaGetSymbolAddress((void**)&oWTH, g_oWTH);   cudaGetSymbolAddress((void**)&oWTL, g_oWTL);
    cudaGetSymbolAddress((void**)&oWH, g_oWH);     cudaGetSymbolAddress((void**)&oWL, g_oWL);
    cudaGetSymbolAddress((void**)&nzH, g_nzH);     cudaGetSymbolAddress((void**)&nzL, g_nzL);
    cudaGetSymbolAddress((void**)&HsH, g_HsH);     cudaGetSymbolAddress((void**)&HsL, g_HsL);

    cudaFuncSetAttribute(mma_gemm, cudaFuncAttributeMaxDynamicSharedMemorySize, SMEM_B);

    // launches 1-5: G1's inputs (so launch 6 = mma_gemm G1 gets profiled by ncu -s 5)
    zero_k<<<32,256>>>();
    split_inp_k<<<T_*B_,256>>>(input, inpH, inpL);
    split_rows_k<<<G4H_,256>>>(enc_Wih, E_, 0, E_, KP_, wihH, wihL);
    split_rows_k<<<H_,256>>>(emb_W, EPNZ_, 0, E_, KP_, embEH, embEL);
    split_rows_k<<<H_,256>>>(emb_W, EPNZ_, E_, NZ_, NZP_, embNH, embNL);

    // launch 6: G1: enc_gx [T*B, 4H] = input_g @ Wih^T + biases
    mma_gemm<<<dim3(32, 8), 256, SMEM_B>>>(inpH, inpL, wihH, wihL,
        p_gx, enc_bih, enc_bhh, T_*B_, G4H_, KP_, G4H_);

    // remaining prep
    split_tr_k<<<dim3((KP_+31)/32,(H_+31)/32), dim3(32,8)>>>(out_W, oWTH, oWTL);
    split_rows_k<<<E_,256>>>(out_W, H_, 0, H_, HP_, oWH, oWL);
    split_rows_k<<<S_*B_,256>>>(noise1, NZ_, 0, NZ_, NZP_, nzH, nzL);

    // G2: M [H,H] = emb_W[:, :E] @ out_W
    mma_gemm<<<dim3(8, 8), 256, SMEM_B>>>(embEH, embEL, oWTH, oWTL,
        p_M, 0, 0, H_, H_, KP_, H_);
    // G3: n1emb [S*B, H] = noise1 @ emb_W[:, E:]^T
    mma_gemm<<<dim3(8, 4), 256, SMEM_B>>>(nzH, nzL, embNH, embNL,
        p_n1, 0, 0, S_*B_, H_, NZP_, H_);

    vvec_k<<<H_,256>>>(emb_W, out_b, emb_b);

    // n2attn [S*B, T] = noise2 @ attn_W[:, 2H:]^T + attn_b (tiny, SIMT)
    sgemm_nt<<<dim3(1,4),256>>>(noise2, attn_W, p_n2, attn_b,
        S_*B_, T_, H_, H_, 3*H_, 2*H_, T_);

    skinny_k<<<H_/8,256>>>(init_dec, emb_W);

    for (int t = 0; t < T_; t++)
        enc_step_k<<<H_/8,256>>>(enc_Whh, t);

    for (int s = 0; s < S_; s++){
        if (s == 0) emb0_k<<<32,256>>>(emb_b);
        else        dk1_k<<<H_/8,256>>>(s);
        dk2_k<<<B_,256>>>(attn_W, s);
        dk3_k<<<H_/8,256>>>(comb_W, comb_b);
        dk4_k<<<H_/8,256>>>(dec_Wih, dec_Whh, dec_bih, dec_bhh, s);
    }

    // G4: summary [S*B, E] = Hs @ out_W^T + out_b
    split_rows_k<<<S_*B_,256>>>(p_Hs, H_, 0, H_, HP_, HsH, HsL);
    mma_gemm<<<dim3((E_+127)/128, 4), 256, SMEM_B>>>(HsH, HsL, oWH, oWL,
        out, out_b, 0, S_*B_, E_, HP_, E_);
}

// round 9
// speedup vs baseline: 1.2104x; 1.0655x over previous
#include <cuda_runtime.h>
#include <cuda_bf16.h>
#include <math.h>
#include <stdint.h>

#define B_ 8
#define T_ 128
#define E_ 30522
#define H_ 1000
#define S_ 64
#define NZ_ 10000
#define EPNZ_ 40522
#define G4H_ (4*H_)
#define KP_ 30528   // E padded (mult 32)
#define NZP_ 10016
#define HP_ 1024
#define NT_E (KP_/32)    // 954
#define NT_NZ (NZP_/32)  // 313
#define NT_H (HP_/32)    // 32

// ---------------- fp32 scratch ----------------
__device__ float g_encGX[(size_t)T_*B_*G4H_];
__device__ float g_M[(size_t)H_*H_];
__device__ float g_n1[(size_t)S_*B_*H_];
__device__ float g_n2[(size_t)S_*B_*T_];
__device__ float g_emb0[B_*H_];
__device__ float g_v2[H_];
__device__ float g_encBTH[(size_t)B_*T_*H_];
__device__ float g_h[2][B_*H_];
__device__ float g_c[B_*H_];
__device__ float g_emb[B_*H_];
__device__ float g_app[B_*H_];
__device__ float g_outv[B_*H_];
__device__ float g_Hs[(size_t)S_*B_*H_];

// ---------------- packed bf16 operands (panel = 128 rows; tile = 128x32 = 4096 bf16, swizzled) ----
__device__ __nv_bfloat16 g_inpH[(size_t)8*NT_E*4096],   g_inpL[(size_t)8*NT_E*4096];
__device__ __nv_bfloat16 g_wihH[(size_t)32*NT_E*4096],  g_wihL[(size_t)32*NT_E*4096];
__device__ __nv_bfloat16 g_embEH[(size_t)8*NT_E*4096],  g_embEL[(size_t)8*NT_E*4096];
__device__ __nv_bfloat16 g_embNH[(size_t)8*NT_NZ*4096], g_embNL[(size_t)8*NT_NZ*4096];
__device__ __nv_bfloat16 g_oWTH[(size_t)8*NT_E*4096],   g_oWTL[(size_t)8*NT_E*4096];
__device__ __nv_bfloat16 g_oWH[(size_t)239*NT_H*4096],  g_oWL[(size_t)239*NT_H*4096];
__device__ __nv_bfloat16 g_nzH[(size_t)4*NT_NZ*4096],   g_nzL[(size_t)4*NT_NZ*4096];
__device__ __nv_bfloat16 g_HsH[(size_t)4*NT_H*4096],    g_HsL[(size_t)4*NT_H*4096];

__device__ __forceinline__ float wsum(float v){
#pragma unroll
    for (int o = 16; o; o >>= 1) v += __shfl_xor_sync(0xffffffffu, v, o);
    return v;
}
__device__ __forceinline__ float sigf(float x){ return 1.f/(1.f+expf(-x)); }

__device__ __forceinline__ uint32_t smem_u32(const void* p){
    uint32_t a;
    asm("{ .reg .u64 t; cvta.to.shared.u64 t, %1; cvt.u32.u64 %0, t; }" : "=r"(a) : "l"(p));
    return a;
}
__device__ __forceinline__ void ldsm4(uint32_t* r, uint32_t a){
    asm volatile("ldmatrix.sync.aligned.m8n8.x4.shared.b16 {%0,%1,%2,%3}, [%4];"
        : "=r"(r[0]),"=r"(r[1]),"=r"(r[2]),"=r"(r[3]) : "r"(a));
}
__device__ __forceinline__ void mma16816(float* c, const uint32_t* a,
                                         uint32_t b0, uint32_t b1){
    asm volatile("mma.sync.aligned.m16n8k16.row.col.f32.bf16.bf16.f32 "
        "{%0,%1,%2,%3}, {%4,%5,%6,%7}, {%8,%9}, {%0,%1,%2,%3};"
        : "+f"(c[0]),"+f"(c[1]),"+f"(c[2]),"+f"(c[3])
        : "r"(a[0]),"r"(a[1]),"r"(a[2]),"r"(a[3]), "r"(b0),"r"(b1));
}
#define MB_INIT(mb, c)  asm volatile("mbarrier.init.shared.b64 [%0], %1;" :: "r"((uint32_t)(mb)), "r"((uint32_t)(c)) : "memory")
#define MB_EXPECT(mb, n) asm volatile("mbarrier.arrive.expect_tx.shared.b64 _, [%0], %1;" :: "r"((uint32_t)(mb)), "r"((uint32_t)(n)) : "memory")
#define MB_WAIT(mb, ph) do { \
    uint32_t _m=(uint32_t)(mb), _p=(uint32_t)(ph), _d; \
    asm volatile("{\n\t.reg .pred p;\n\tmbarrier.try_wait.parity.shared.b64 p, [%1], %2;\n\tselp.b32 %0, 1, 0, p;\n\t}" \
        : "=r"(_d) : "r"(_m), "r"(_p) : "memory"); \
    if (!_d){ \
        asm volatile("{\n\t.reg .pred P1;\n\tWL_%=:\n\tmbarrier.try_wait.parity.shared.b64 P1, [%0], %1;\n\t@P1 bra.uni WD_%=;\n\tbra.uni WL_%=;\n\tWD_%=:\n\t}" \
            :: "r"(_m), "r"(_p) : "memory"); \
    } } while(0)
__device__ __forceinline__ void bulk_cp(uint32_t dst, const void* src, uint32_t sz, uint32_t mb){
    asm volatile("cp.async.bulk.shared::cta.global.mbarrier::complete_tx::bytes [%0], [%1], %2, [%3];"
        :: "r"(dst), "l"(src), "r"(sz), "r"(mb) : "memory");
}

#define STG_B 32768    // 4 arrays x 8192B
#define SMEM_B (2*STG_B)

// ---------------- packed split-bf16 HMMA NT GEMM: C = A@B^T (+bias) ----------------
__global__ __launch_bounds__(256,2)
void mma_gemm(const __nv_bfloat16* __restrict__ Ah, const __nv_bfloat16* __restrict__ Al,
              const __nv_bfloat16* __restrict__ Bh, const __nv_bfloat16* __restrict__ Bl,
              float* __restrict__ C, const float* __restrict__ bias0,
              const float* __restrict__ bias1,
              int M, int N, int NT, int ldc)
{
    extern __shared__ char smem[];
    __shared__ __align__(8) uint64_t mbar[2];
    uint32_t sb = smem_u32(smem);
    uint32_t mba = smem_u32(mbar);
    const int tid = threadIdx.x, lane = tid & 31, wid = tid >> 5;
    const int pa = blockIdx.y, pb = blockIdx.x;
    const int row0 = pa*128, col0 = pb*128;
    const int wm = wid >> 2, wn = wid & 3;

    if (tid == 0){ MB_INIT(mba, 1); MB_INIT(mba+8, 1); }
    __syncthreads();

    float c[4][4][4];
#pragma unroll
    for (int i = 0; i < 4; i++)
#pragma unroll
        for (int j = 0; j < 4; j++)
#pragma unroll
            for (int q = 0; q < 4; q++) c[i][j][q] = 0.f;

    auto load = [&](int kt, int stg){
        if (tid == 0){
            uint32_t mb = mba + stg*8;
            MB_EXPECT(mb, STG_B);
            uint32_t d = sb + stg*STG_B;
            bulk_cp(d,          Ah + ((size_t)pa*NT + kt)*4096, 8192, mb);
            bulk_cp(d + 8192,   Al + ((size_t)pa*NT + kt)*4096, 8192, mb);
            bulk_cp(d + 16384,  Bh + ((size_t)pb*NT + kt)*4096, 8192, mb);
            bulk_cp(d + 24576,  Bl + ((size_t)pb*NT + kt)*4096, 8192, mb);
        }
    };

    int ph[2] = {0, 0};
    load(0, 0);
    for (int kt = 0; kt < NT; kt++){
        int cur = kt & 1;
        if (kt + 1 < NT) load(kt+1, cur ^ 1);
        MB_WAIT(mba + cur*8, ph[cur]); ph[cur] ^= 1;
        __syncthreads();

        uint32_t sbase = sb + cur*STG_B;
#pragma unroll
        for (int ks = 0; ks < 2; ks++){
            uint32_t bh[2][4], bl[2][4];
#pragma unroll
            for (int nj = 0; nj < 2; nj++){
                uint32_t rb = (uint32_t)(wn*32 + nj*16 + (lane & 15));
                uint32_t c4 = (uint32_t)(ks*2 + (lane >> 4)) ^ ((rb >> 1) & 3);
                uint32_t ab = sbase + 16384 + rb*64 + c4*16;
                ldsm4(bh[nj], ab);
                ldsm4(bl[nj], ab + 8192);
            }
#pragma unroll
            for (int mi = 0; mi < 4; mi++){
                uint32_t ra = (uint32_t)(wm*64 + mi*16 + (lane & 15));
                uint32_t c4 = (uint32_t)(ks*2 + (lane >> 4)) ^ ((ra >> 1) & 3);
                uint32_t aa = sbase + ra*64 + c4*16;
                uint32_t a4h[4], a4l[4];
                ldsm4(a4h, aa);
                ldsm4(a4l, aa + 8192);
#pragma unroll
                for (int nf = 0; nf < 4; nf++){
                    int nj = nf >> 1, s = nf & 1;
                    uint32_t b0h = bh[nj][s], b1h = bh[nj][2+s];
                    uint32_t b0l = bl[nj][s], b1l = bl[nj][2+s];
                    mma16816(c[mi][nf], a4h, b0h, b1h);
                    mma16816(c[mi][nf], a4h, b0l, b1l);
                    mma16816(c[mi][nf], a4l, b0h, b1h);
                }
            }
        }
        __syncthreads();
    }

    // epilogue
#pragma unroll
    for (int mi = 0; mi < 4; mi++){
#pragma unroll
        for (int nf = 0; nf < 4; nf++){
            int gr = row0 + wm*64 + mi*16 + (lane >> 2);
            int gc = col0 + wn*32 + nf*8 + (lane & 3)*2;
#pragma unroll
            for (int q = 0; q < 4; q++){
                int rr = gr + (q >> 1)*8;
                int cc = gc + (q & 1);
                if (rr < M && cc < N){
                    float v = c[mi][nf][q];
                    if (bias0) v += bias0[cc];
                    if (bias1) v += bias1[cc];
                    C[(size_t)rr*ldc + cc] = v;
                }
            }
        }
    }
}

// ---------------- pack kernels (fp32 -> swizzled packed bf16 hi/lo) ----------------
// packed offset for panel-local row pr, tile kt, k-in-tile kc:
//   (p*NT + kt)*4096 + pr*32 + (((kc>>3) ^ ((pr>>1)&3))*8) + (kc&7)
__global__ void pack_rows_k(const float* __restrict__ src, long srcLd, int colOff,
                            int Rr, int Kr, int NT,
                            __nv_bfloat16* __restrict__ hi, __nv_bfloat16* __restrict__ lo)
{
    int r = blockIdx.x;
    int p = r >> 7, pr = r & 127;
    size_t pbase = ((size_t)p*NT)*4096 + (size_t)pr*32;
    const float* s = src + (size_t)r*srcLd + colOff;
    int Kp = NT*32;
    bool rok = (r < Rr);
    int sw = (pr >> 1) & 3;
    for (int k = threadIdx.x; k < Kp; k += 256){
        int kt = k >> 5, kc = k & 31;
        size_t off = pbase + (size_t)kt*4096 + (size_t)(((kc>>3) ^ sw)*8 + (kc&7));
        float x = (rok && k < Kr) ? s[k] : 0.f;
        __nv_bfloat16 h = __float2bfloat16(x);
        hi[off] = h;
        lo[off] = __float2bfloat16(x - __bfloat162float(h));
    }
}

__global__ void pack_inp_k(const float* __restrict__ inp,
                           __nv_bfloat16* __restrict__ hi, __nv_bfloat16* __restrict__ lo)
{
    int r = blockIdx.x;              // r = t*B + b
    int t = r / B_, b = r % B_;
    int p = r >> 7, pr = r & 127;
    size_t pbase = ((size_t)p*NT_E)*4096 + (size_t)pr*32;
    const float* s = inp + ((size_t)b*T_ + t)*E_;
    int sw = (pr >> 1) & 3;
    for (int k = threadIdx.x; k < KP_; k += 256){
        int kt = k >> 5, kc = k & 31;
        size_t off = pbase + (size_t)kt*4096 + (size_t)(((kc>>3) ^ sw)*8 + (kc&7));
        float x = (k < E_) ? s[k] : 0.f;
        __nv_bfloat16 h = __float2bfloat16(x);
        hi[off] = h;
        lo[off] = __float2bfloat16(x - __bfloat162float(h));
    }
}

// out_W [E,H] -> packed transpose rows j in [0,1024), k = e in [0,KP_)
__global__ void pack_tr_k(const float* __restrict__ src,
                          __nv_bfloat16* __restrict__ hi, __nv_bfloat16* __restrict__ lo)
{
    __shared__ float t[32][33];
    int e0 = blockIdx.x*32, j0 = blockIdx.y*32;
    for (int i = threadIdx.y; i < 32; i += 8){
        int e = e0+i, j = j0+threadIdx.x;
        t[i][threadIdx.x] = (e < E_ && j < H_) ? src[(size_t)e*H_ + j] : 0.f;
    }
    __syncthreads();
    for (int i = threadIdx.y; i < 32; i += 8){
        int j = j0+i;
        int e = e0+threadIdx.x;
        int p = j >> 7, pr = j & 127;
        int kt = e >> 5, kc = e & 31;
        size_t off = ((size_t)p*NT_E + kt)*4096 + (size_t)pr*32
                   + (size_t)((((kc>>3) ^ ((pr>>1)&3))*8) + (kc&7));
        float x = t[threadIdx.x][i];
        __nv_bfloat16 h = __float2bfloat16(x);
        hi[off] = h;
        lo[off] = __float2bfloat16(x - __bfloat162float(h));
    }
}

// ---------------- small SIMT GEMM for n2attn ----------------
__global__ __launch_bounds__(256,2)
void sgemm_nt(const float* __restrict__ A, const float* __restrict__ Bm,
              float* __restrict__ C,
              const float* __restrict__ bias0,
              int M, int N, int K, int lda, int ldb, int bColOff, int ldc)
{
    __shared__ float As[16][132];
    __shared__ float Bs[16][132];
    const int row0 = blockIdx.y*128, col0 = blockIdx.x*128;
    const int tid = threadIdx.x;
    const int tx = tid & 15, ty = tid >> 4;
    const int lk = tid & 15, lr0 = tid >> 4;
    long aOff[8]; int aOk[8]; long bOff[8]; int bOk[8];
#pragma unroll
    for (int i = 0; i < 8; i++){
        int gr = row0 + lr0 + i*16;
        aOk[i] = (gr < M); aOff[i] = (long)(aOk[i] ? gr : 0)*lda;
        int gc = col0 + lr0 + i*16;
        bOk[i] = (gc < N); bOff[i] = (long)(bOk[i] ? gc : 0)*ldb + bColOff;
    }
    float acc[8][8];
#pragma unroll
    for (int i = 0; i < 8; i++)
#pragma unroll
        for (int j = 0; j < 8; j++) acc[i][j] = 0.f;
    for (int k0 = 0; k0 < K; k0 += 16){
        int gk = k0 + lk; bool kOk = (gk < K);
#pragma unroll
        for (int i = 0; i < 8; i++){
            As[lk][lr0+i*16] = (kOk && aOk[i]) ? A[aOff[i]+gk] : 0.f;
            Bs[lk][lr0+i*16] = (kOk && bOk[i]) ? Bm[bOff[i]+gk] : 0.f;
        }
        __syncthreads();
#pragma unroll
        for (int kk = 0; kk < 16; kk++){
            float4 a0 = *(const float4*)&As[kk][ty*8];
            float4 a1 = *(const float4*)&As[kk][ty*8+4];
            float4 b0 = *(const float4*)&Bs[kk][tx*8];
            float4 b1 = *(const float4*)&Bs[kk][tx*8+4];
            float a[8] = {a0.x,a0.y,a0.z,a0.w,a1.x,a1.y,a1.z,a1.w};
            float b[8] = {b0.x,b0.y,b0.z,b0.w,b1.x,b1.y,b1.z,b1.w};
#pragma unroll
            for (int i = 0; i < 8; i++)
#pragma unroll
                for (int j = 0; j < 8; j++) acc[i][j] += a[i]*b[j];
        }
        __syncthreads();
    }
#pragma unroll
    for (int i = 0; i < 8; i++){
        int gr = row0 + ty*8 + i;
        if (gr >= M) continue;
#pragma unroll
        for (int j = 0; j < 8; j++){
            int gc = col0 + tx*8 + j;
            if (gc >= N) continue;
            float v = acc[i][j];
            if (bias0) v += bias0[gc];
            C[(long)gr*ldc + gc] = v;
        }
    }
}

__global__ void skinny_k(const float* __restrict__ A, const float* __restrict__ Bm)
{
    __shared__ float Ash[8*1024];
    int w = threadIdx.x >> 5, lane = threadIdx.x & 31;
    int j = blockIdx.x*8 + w;
    float acc[8] = {0,0,0,0,0,0,0,0};
    for (int k0 = 0; k0 < E_; k0 += 1024){
        int kc = min(1024, E_ - k0);
        __syncthreads();
        for (int idx = threadIdx.x; idx < 8192; idx += 256){
            int r = idx >> 10, k = idx & 1023;
            Ash[idx] = (k < kc) ? A[(long)r*E_ + k0 + k] : 0.f;
        }
        __syncthreads();
        if (j < H_){
            const float* br = Bm + (long)j*EPNZ_ + k0;
            for (int k = lane; k < kc; k += 32){
                float wv = br[k];
#pragma unroll
                for (int b = 0; b < 8; b++) acc[b] += wv*Ash[b*1024 + k];
            }
        }
    }
    if (j < H_){
#pragma unroll
        for (int b = 0; b < 8; b++) acc[b] = wsum(acc[b]);
        if (lane == 0)
            for (int b = 0; b < 8; b++) g_emb0[b*H_ + j] = acc[b];
    }
}

__global__ void vvec_k(const float* __restrict__ embW, const float* __restrict__ out_b,
                       const float* __restrict__ emb_b)
{
    __shared__ float red[256];
    int j = blockIdx.x;
    float s = 0.f;
    for (int k = threadIdx.x; k < E_; k += 256) s += embW[(long)j*EPNZ_ + k]*out_b[k];
    red[threadIdx.x] = s; __syncthreads();
    for (int o = 128; o; o >>= 1){
        if (threadIdx.x < o) red[threadIdx.x] += red[threadIdx.x+o];
        __syncthreads();
    }
    if (threadIdx.x == 0) g_v2[j] = red[0] + emb_b[j];
}

__global__ void zero_k(){
    int i = blockIdx.x*256 + threadIdx.x;
    if (i < B_*H_){ g_h[0][i] = 0.f; g_c[i] = 0.f; }
}

__global__ void enc_step_k(const float* __restrict__ Whh, int t)
{
    __shared__ float hs[B_*H_];
    const float* hIn = g_h[t & 1];
    float* hOut = g_h[(t & 1) ^ 1];
    const float* gx = g_encGX + (long)t*B_*G4H_;
    int tid = threadIdx.x;
    for (int i = tid; i < B_*H_; i += 256) hs[i] = hIn[i];
    __syncthreads();
    int w = tid >> 5, lane = tid & 31;
    int j = blockIdx.x*8 + w;
    const float *w0 = Whh+(long)j*H_, *w1 = Whh+(long)(H_+j)*H_;
    const float *w2 = Whh+(long)(2*H_+j)*H_, *w3 = Whh+(long)(3*H_+j)*H_;
    float a0[8]={0},a1[8]={0},a2[8]={0},a3[8]={0};
    for (int k = lane; k < H_; k += 32){
        float x0=w0[k],x1=w1[k],x2=w2[k],x3=w3[k];
#pragma unroll
        for (int b = 0; b < 8; b++){
            float hv = hs[b*H_+k];
            a0[b]+=x0*hv; a1[b]+=x1*hv; a2[b]+=x2*hv; a3[b]+=x3*hv;
        }
    }
#pragma unroll
    for (int b = 0; b < 8; b++){
        a0[b]=wsum(a0[b]); a1[b]=wsum(a1[b]); a2[b]=wsum(a2[b]); a3[b]=wsum(a3[b]);
    }
    if (lane == 0){
#pragma unroll
        for (int b = 0; b < 8; b++){
            const float* gr = gx + (long)b*G4H_;
            float ig = sigf (gr[j]       + a0[b]);
            float fg = sigf (gr[H_+j]    + a1[b]);
            float gg = tanhf(gr[2*H_+j]  + a2[b]);
            float og = sigf (gr[3*H_+j]  + a3[b]);
            float c = fg*g_c[b*H_+j] + ig*gg;
            g_c[b*H_+j] = c;
            float h = og*tanhf(c);
            hOut[b*H_+j] = h;
            g_encBTH[((long)b*T_ + t)*H_ + j] = h;
        }
    }
}

__global__ void emb0_k(const float* __restrict__ emb_b)
{
    int i = blockIdx.x*256 + threadIdx.x;
    if (i < B_*H_) g_emb[i] = g_emb0[i] + g_n1[i] + emb_b[i % H_];
}

__global__ void dk1_k(int s)
{
    __shared__ float hs[B_*H_];
    const float* hIn = g_h[s & 1];
    const float* n1 = g_n1 + (long)s*B_*H_;
    int tid = threadIdx.x;
    for (int i = tid; i < B_*H_; i += 256) hs[i] = hIn[i];
    __syncthreads();
    int w = tid >> 5, lane = tid & 31;
    int j = blockIdx.x*8 + w;
    const float* mr = g_M + (long)j*H_;
    float acc[8]={0,0,0,0,0,0,0,0};
    for (int k = lane; k < H_; k += 32){
        float mv = mr[k];
#pragma unroll
        for (int b = 0; b < 8; b++) acc[b] += mv*hs[b*H_+k];
    }
#pragma unroll
    for (int b = 0; b < 8; b++) acc[b] = wsum(acc[b]);
    if (lane == 0){
        float vb = g_v2[j];
        for (int b = 0; b < 8; b++) g_emb[b*H_+j] = acc[b] + n1[b*H_+j] + vb;
    }
}

__global__ void dk2_k(const float* __restrict__ attW, int s)
{
    __shared__ float xs[2*H_];
    __shared__ float lg[T_];
    __shared__ float ps[T_];
    int b = blockIdx.x, tid = threadIdx.x;
    const float* hIn = g_h[s & 1];
    const float* n2 = g_n2 + (long)s*B_*T_;
    for (int i = tid; i < H_; i += 256){ xs[i] = g_emb[b*H_+i]; xs[H_+i] = hIn[b*H_+i]; }
    __syncthreads();
    int w = tid >> 5, lane = tid & 31;
    for (int ti = 0; ti < 16; ti++){
        int t = w*16 + ti;
        const float* wr = attW + (long)t*3*H_;
        float sv = 0.f;
        for (int k = lane; k < 2*H_; k += 32) sv += wr[k]*xs[k];
        sv = wsum(sv);
        if (lane == 0) lg[t] = sv + n2[b*T_+t];
    }
    __syncthreads();
    if (w == 0){
        float m = -1e30f;
        for (int i = lane; i < T_; i += 32) m = fmaxf(m, lg[i]);
#pragma unroll
        for (int o = 16; o; o >>= 1) m = fmaxf(m, __shfl_xor_sync(0xffffffffu, m, o));
        float ss = 0.f;
        for (int i = lane; i < T_; i += 32){ float e = expf(lg[i]-m); ps[i] = e; ss += e; }
        ss = wsum(ss);
        float inv = 1.f/ss;
        for (int i = lane; i < T_; i += 32) ps[i] *= inv;
    }
    __syncthreads();
    for (int j = tid; j < H_; j += 256){
        float sv = 0.f;
        const float* eb = g_encBTH + (long)b*T_*H_ + j;
#pragma unroll 4
        for (int t = 0; t < T_; t++) sv += ps[t]*eb[(long)t*H_];
        g_app[b*H_+j] = sv;
    }
}

__global__ void dk3_k(const float* __restrict__ combW, const float* __restrict__ comb_b)
{
    __shared__ float sh[B_*H_];
    int tid = threadIdx.x;
    int w = tid >> 5, lane = tid & 31;
    int j = blockIdx.x*8 + w;
    const float* wr = combW + (long)j*2*H_;
    float acc[8]={0,0,0,0,0,0,0,0};
    for (int i = tid; i < B_*H_; i += 256) sh[i] = g_emb[i];
    __syncthreads();
    for (int k = lane; k < H_; k += 32){
        float wv = wr[k];
#pragma unroll
        for (int b = 0; b < 8; b++) acc[b] += wv*sh[b*H_+k];
    }
    __syncthreads();
    for (int i = tid; i < B_*H_; i += 256) sh[i] = g_app[i];
    __syncthreads();
    for (int k = lane; k < H_; k += 32){
        float wv = wr[H_+k];
#pragma unroll
        for (int b = 0; b < 8; b++) acc[b] += wv*sh[b*H_+k];
    }
#pragma unroll
    for (int b = 0; b < 8; b++) acc[b] = wsum(acc[b]);
    if (lane == 0){
        float cb = comb_b[j];
        for (int b = 0; b < 8; b++) g_outv[b*H_+j] = fmaxf(0.f, acc[b] + cb);
    }
}

__global__ void dk4_k(const float* __restrict__ Wih, const float* __restrict__ Whh,
                      const float* __restrict__ bih, const float* __restrict__ bhh, int s)
{
    __shared__ float sh[B_*H_];
    int pp = s & 1;
    const float* hIn = g_h[pp];
    float* hOut = g_h[pp ^ 1];
    int tid = threadIdx.x;
    int w = tid >> 5, lane = tid & 31;
    int j = blockIdx.x*8 + w;
    float a0[8]={0},a1[8]={0},a2[8]={0},a3[8]={0};
    for (int i = tid; i < B_*H_; i += 256) sh[i] = g_outv[i];
    __syncthreads();
    {
        const float *w0=Wih+(long)j*H_, *w1=Wih+(long)(H_+j)*H_;
        const float *w2=Wih+(long)(2*H_+j)*H_, *w3=Wih+(long)(3*H_+j)*H_;
        for (int k = lane; k < H_; k += 32){
            float x0=w0[k],x1=w1[k],x2=w2[k],x3=w3[k];
#pragma unroll
            for (int b = 0; b < 8; b++){
                float hv = sh[b*H_+k];
                a0[b]+=x0*hv; a1[b]+=x1*hv; a2[b]+=x2*hv; a3[b]+=x3*hv;
            }
        }
    }
    __syncthreads();
    for (int i = tid; i < B_*H_; i += 256) sh[i] = hIn[i];
    __syncthreads();
    {
        const float *w0=Whh+(long)j*H_, *w1=Whh+(long)(H_+j)*H_;
        const float *w2=Whh+(long)(2*H_+j)*H_, *w3=Whh+(long)(3*H_+j)*H_;
        for (int k = lane; k < H_; k += 32){
            float x0=w0[k],x1=w1[k],x2=w2[k],x3=w3[k];
#pragma unroll
            for (int b = 0; b < 8; b++){
                float hv = sh[b*H_+k];
                a0[b]+=x0*hv; a1[b]+=x1*hv; a2[b]+=x2*hv; a3[b]+=x3*hv;
            }
        }
    }
#pragma unroll
    for (int b = 0; b < 8; b++){
        a0[b]=wsum(a0[b]); a1[b]=wsum(a1[b]); a2[b]=wsum(a2[b]); a3[b]=wsum(a3[b]);
    }
    if (lane == 0){
        float bi0=bih[j]+bhh[j], bi1=bih[H_+j]+bhh[H_+j];
        float bi2=bih[2*H_+j]+bhh[2*H_+j], bi3=bih[3*H_+j]+bhh[3*H_+j];
#pragma unroll
        for (int b = 0; b < 8; b++){
            float ig = sigf (a0[b]+bi0);
            float fg = sigf (a1[b]+bi1);
            float gg = tanhf(a2[b]+bi2);
            float og = sigf (a3[b]+bi3);
            float c = fg*g_c[b*H_+j] + ig*gg;
            g_c[b*H_+j] = c;
            float h = og*tanhf(c);
            hOut[b*H_+j] = h;
            g_Hs[((long)s*B_ + b)*H_ + j] = h;
        }
    }
}

extern "C" void kernel_launch(void* const* d_in, const int* in_sizes, int n_in,
                              void* d_out, int out_size)
{
    int off = (in_sizes[1] == 1) ? 1 : 0;
    const float* input    = (const float*)d_in[0];
    const float* noise1   = (const float*)d_in[1+off];
    const float* noise2   = (const float*)d_in[2+off];
    const float* init_dec = (const float*)d_in[3+off];
    const float* enc_Wih  = (const float*)d_in[4+off];
    const float* enc_Whh  = (const float*)d_in[5+off];
    const float* enc_bih  = (const float*)d_in[6+off];
    const float* enc_bhh  = (const float*)d_in[7+off];
    const float* dec_Wih  = (const float*)d_in[8+off];
    const float* dec_Whh  = (const float*)d_in[9+off];
    const float* dec_bih  = (const float*)d_in[10+off];
    const float* dec_bhh  = (const float*)d_in[11+off];
    const float* emb_W    = (const float*)d_in[12+off];
    const float* emb_b    = (const float*)d_in[13+off];
    const float* attn_W   = (const float*)d_in[14+off];
    const float* attn_b   = (const float*)d_in[15+off];
    const float* comb_W   = (const float*)d_in[16+off];
    const float* comb_b   = (const float*)d_in[17+off];
    const float* out_W    = (const float*)d_in[18+off];
    const float* out_b    = (const float*)d_in[19+off];
    float* out = (float*)d_out;

    float *p_gx, *p_M, *p_n1, *p_n2, *p_Hs;
    cudaGetSymbolAddress((void**)&p_gx, g_encGX);
    cudaGetSymbolAddress((void**)&p_M,  g_M);
    cudaGetSymbolAddress((void**)&p_n1, g_n1);
    cudaGetSymbolAddress((void**)&p_n2, g_n2);
    cudaGetSymbolAddress((void**)&p_Hs, g_Hs);
    __nv_bfloat16 *inpH,*inpL,*wihH,*wihL,*embEH,*embEL,*embNH,*embNL;
    __nv_bfloat16 *oWTH,*oWTL,*oWH,*oWL,*nzH,*nzL,*HsH,*HsL;
    cudaGetSymbolAddress((void**)&inpH, g_inpH);   cudaGetSymbolAddress((void**)&inpL, g_inpL);
    cudaGetSymbolAddress((void**)&wihH, g_wihH);   cudaGetSymbolAddress((void**)&wihL, g_wihL);
    cudaGetSymbolAddress((void**)&embEH, g_embEH); cudaGetSymbolAddress((void**)&embEL, g_embEL);
    cudaGetSymbolAddress((void**)&embNH, g_embNH); cudaGetSymbolAddress((void**)&embNL, g_embNL);
    cudaGetSymbolAddress((void**)&oWTH, g_oWTH);   cudaGetSymbolAddress((void**)&oWTL, g_oWTL);
    cudaGetSymbolAddress((void**)&oWH, g_oWH);     cudaGetSymbolAddress((void**)&oWL, g_oWL);
    cudaGetSymbolAddress((void**)&nzH, g_nzH);     cudaGetSymbolAddress((void**)&nzL, g_nzL);
    cudaGetSymbolAddress((void**)&HsH, g_HsH);     cudaGetSymbolAddress((void**)&HsL, g_HsL);

    cudaFuncSetAttribute(mma_gemm, cudaFuncAttributeMaxDynamicSharedMemorySize, SMEM_B);

    // 1-3: G1 prerequisites (so G1 sits in the ncu-profiled slot)
    pack_inp_k<<<1024,256>>>(input, inpH, inpL);
    pack_rows_k<<<4096,256>>>(enc_Wih, E_, 0, G4H_, E_, NT_E, wihH, wihL);
    pack_rows_k<<<1024,256>>>(emb_W, EPNZ_, 0, H_, E_, NT_E, embEH, embEL);

    // 4: G1: enc_gx [1024, 4000] = inp @ wih^T + biases
    mma_gemm<<<dim3(32, 8), 256, SMEM_B>>>(inpH, inpL, wihH, wihL,
        p_gx, enc_bih, enc_bhh, T_*B_, G4H_, NT_E, G4H_);

    // remaining packs
    pack_rows_k<<<1024,256>>>(emb_W, EPNZ_, E_, H_, NZ_, NT_NZ, embNH, embNL);
    pack_tr_k<<<dim3(NT_E, 32), dim3(32,8)>>>(out_W, oWTH, oWTL);
    pack_rows_k<<<239*128,256>>>(out_W, H_, 0, E_, H_, NT_H, oWH, oWL);
    pack_rows_k<<<512,256>>>(noise1, NZ_, 0, S_*B_, NZ_, NT_NZ, nzH, nzL);

    // G2: M [1000,1000] = emb_W[:, :E] @ out_W
    mma_gemm<<<dim3(8, 8), 256, SMEM_B>>>(embEH, embEL, oWTH, oWTL,
        p_M, 0, 0, H_, H_, NT_E, H_);
    // G3: n1emb [512, 1000] = noise1 @ emb_W[:, E:]^T
    mma_gemm<<<dim3(8, 4), 256, SMEM_B>>>(nzH, nzL, embNH, embNL,
        p_n1, 0, 0, S_*B_, H_, NT_NZ, H_);

    vvec_k<<<H_,256>>>(emb_W, out_b, emb_b);
    sgemm_nt<<<dim3(1,4),256>>>(noise2, attn_W, p_n2, attn_b,
        S_*B_, T_, H_, H_, 3*H_, 2*H_, T_);
    skinny_k<<<H_/8,256>>>(init_dec, emb_W);
    zero_k<<<32,256>>>();

    for (int t = 0; t < T_; t++)
        enc_step_k<<<H_/8,256>>>(enc_Whh, t);

    for (int s = 0; s < S_; s++){
        if (s == 0) emb0_k<<<32,256>>>(emb_b);
        else        dk1_k<<<H_/8,256>>>(s);
        dk2_k<<<B_,256>>>(attn_W, s);
        dk3_k<<<H_/8,256>>>(comb_W, comb_b);
        dk4_k<<<H_/8,256>>>(dec_Wih, dec_Whh, dec_bih, dec_bhh, s);
    }

    // G4: summary [512, E] = Hs @ out_W^T + out_b
    pack_rows_k<<<512,256>>>(p_Hs, H_, 0, S_*B_, H_, NT_H, HsH, HsL);
    mma_gemm<<<dim3(239, 4), 256, SMEM_B>>>(HsH, HsL, oWH, oWL,
        out, out_b, 0, S_*B_, E_, NT_H, E_);
}

// round 10
// speedup vs baseline: 1.2190x; 1.0071x over previous
#include <cuda_runtime.h>
#include <cuda_bf16.h>
#include <math.h>
#include <stdint.h>

#define B_ 8
#define T_ 128
#define E_ 30522
#define H_ 1000
#define S_ 64
#define NZ_ 10000
#define EPNZ_ 40522
#define G4H_ (4*H_)
#define KP_ 30528   // E padded (mult 32)
#define NZP_ 10016
#define HP_ 1024
#define NT_E (KP_/32)    // 954
#define NT_NZ (NZP_/32)  // 313
#define NT_H (HP_/32)    // 32

// ---------------- fp32 scratch ----------------
__device__ float g_encGX[(size_t)T_*B_*G4H_];
__device__ float g_M[(size_t)H_*H_];
__device__ float g_n1[(size_t)S_*B_*H_];
__device__ float g_n2[(size_t)S_*B_*T_];
__device__ float g_emb0[B_*H_];
__device__ float g_v2[H_];
__device__ float g_encBTH[(size_t)B_*T_*H_];
__device__ float g_h[2][B_*H_];
__device__ float g_c[B_*H_];
__device__ float g_emb[B_*H_];
__device__ float g_app[B_*H_];
__device__ float g_outv[B_*H_];
__device__ float g_Hs[(size_t)S_*B_*H_];

// ---------------- packed bf16 operands (panel = 128 rows; tile = 128x32 = 4096 bf16, swizzled) ----
__device__ __nv_bfloat16 g_inpH[(size_t)8*NT_E*4096],   g_inpL[(size_t)8*NT_E*4096];
__device__ __nv_bfloat16 g_wihH[(size_t)32*NT_E*4096],  g_wihL[(size_t)32*NT_E*4096];
__device__ __nv_bfloat16 g_embEH[(size_t)8*NT_E*4096],  g_embEL[(size_t)8*NT_E*4096];
__device__ __nv_bfloat16 g_embNH[(size_t)8*NT_NZ*4096], g_embNL[(size_t)8*NT_NZ*4096];
__device__ __nv_bfloat16 g_oWTH[(size_t)8*NT_E*4096],   g_oWTL[(size_t)8*NT_E*4096];
__device__ __nv_bfloat16 g_oWH[(size_t)239*NT_H*4096],  g_oWL[(size_t)239*NT_H*4096];
__device__ __nv_bfloat16 g_nzH[(size_t)4*NT_NZ*4096],   g_nzL[(size_t)4*NT_NZ*4096];
__device__ __nv_bfloat16 g_HsH[(size_t)4*NT_H*4096],    g_HsL[(size_t)4*NT_H*4096];

__device__ __forceinline__ float wsum(float v){
#pragma unroll
    for (int o = 16; o; o >>= 1) v += __shfl_xor_sync(0xffffffffu, v, o);
    return v;
}
__device__ __forceinline__ float sigf(float x){ return 1.f/(1.f+expf(-x)); }

__device__ __forceinline__ uint32_t smem_u32(const void* p){
    uint32_t a;
    asm("{ .reg .u64 t; cvta.to.shared.u64 t, %1; cvt.u32.u64 %0, t; }" : "=r"(a) : "l"(p));
    return a;
}
__device__ __forceinline__ void ldsm4(uint32_t* r, uint32_t a){
    asm volatile("ldmatrix.sync.aligned.m8n8.x4.shared.b16 {%0,%1,%2,%3}, [%4];"
        : "=r"(r[0]),"=r"(r[1]),"=r"(r[2]),"=r"(r[3]) : "r"(a));
}
__device__ __forceinline__ void mma16816(float* c, const uint32_t* a,
                                         uint32_t b0, uint32_t b1){
    asm volatile("mma.sync.aligned.m16n8k16.row.col.f32.bf16.bf16.f32 "
        "{%0,%1,%2,%3}, {%4,%5,%6,%7}, {%8,%9}, {%0,%1,%2,%3};"
        : "+f"(c[0]),"+f"(c[1]),"+f"(c[2]),"+f"(c[3])
        : "r"(a[0]),"r"(a[1]),"r"(a[2]),"r"(a[3]), "r"(b0),"r"(b1));
}
#define MB_INIT(mb, c)  asm volatile("mbarrier.init.shared.b64 [%0], %1;" :: "r"((uint32_t)(mb)), "r"((uint32_t)(c)) : "memory")
#define MB_EXPECT(mb, n) asm volatile("mbarrier.arrive.expect_tx.shared.b64 _, [%0], %1;" :: "r"((uint32_t)(mb)), "r"((uint32_t)(n)) : "memory")
#define MB_WAIT(mb, ph) do { \
    uint32_t _m=(uint32_t)(mb), _p=(uint32_t)(ph), _d; \
    asm volatile("{\n\t.reg .pred p;\n\tmbarrier.try_wait.parity.shared.b64 p, [%1], %2;\n\tselp.b32 %0, 1, 0, p;\n\t}" \
        : "=r"(_d) : "r"(_m), "r"(_p) : "memory"); \
    if (!_d){ \
        asm volatile("{\n\t.reg .pred P1;\n\tWL_%=:\n\tmbarrier.try_wait.parity.shared.b64 P1, [%0], %1;\n\t@P1 bra.uni WD_%=;\n\tbra.uni WL_%=;\n\tWD_%=:\n\t}" \
            :: "r"(_m), "r"(_p) : "memory"); \
    } } while(0)
__device__ __forceinline__ void bulk_cp(uint32_t dst, const void* src, uint32_t sz, uint32_t mb){
    asm volatile("cp.async.bulk.shared::cta.global.mbarrier::complete_tx::bytes [%0], [%1], %2, [%3];"
        :: "r"(dst), "l"(src), "r"(sz), "r"(mb) : "memory");
}

#define STG_B 32768    // 4 arrays x 8192B
#define SMEM_B (2*STG_B)

// ---------------- packed split-bf16 HMMA NT GEMM: C = A@B^T (+bias) ----------------
__global__ __launch_bounds__(256,2)
void mma_gemm(const __nv_bfloat16* __restrict__ Ah, const __nv_bfloat16* __restrict__ Al,
              const __nv_bfloat16* __restrict__ Bh, const __nv_bfloat16* __restrict__ Bl,
              float* __restrict__ C, const float* __restrict__ bias0,
              const float* __restrict__ bias1,
              int M, int N, int NT, int ldc)
{
    extern __shared__ char smem[];
    __shared__ __align__(8) uint64_t mbar[2];
    uint32_t sb = smem_u32(smem);
    uint32_t mba = smem_u32(mbar);
    const int tid = threadIdx.x, lane = tid & 31, wid = tid >> 5;
    const int pa = blockIdx.y, pb = blockIdx.x;
    const int row0 = pa*128, col0 = pb*128;
    const int wm = wid >> 2, wn = wid & 3;

    if (tid == 0){ MB_INIT(mba, 1); MB_INIT(mba+8, 1); }
    __syncthreads();

    float c[4][4][4];
#pragma unroll
    for (int i = 0; i < 4; i++)
#pragma unroll
        for (int j = 0; j < 4; j++)
#pragma unroll
            for (int q = 0; q < 4; q++) c[i][j][q] = 0.f;

    auto load = [&](int kt, int stg){
        if (tid == 0){
            uint32_t mb = mba + stg*8;
            MB_EXPECT(mb, STG_B);
            uint32_t d = sb + stg*STG_B;
            bulk_cp(d,          Ah + ((size_t)pa*NT + kt)*4096, 8192, mb);
            bulk_cp(d + 8192,   Al + ((size_t)pa*NT + kt)*4096, 8192, mb);
            bulk_cp(d + 16384,  Bh + ((size_t)pb*NT + kt)*4096, 8192, mb);
            bulk_cp(d + 24576,  Bl + ((size_t)pb*NT + kt)*4096, 8192, mb);
        }
    };

    int ph[2] = {0, 0};
    load(0, 0);
    for (int kt = 0; kt < NT; kt++){
        int cur = kt & 1;
        if (kt + 1 < NT) load(kt+1, cur ^ 1);
        MB_WAIT(mba + cur*8, ph[cur]); ph[cur] ^= 1;
        __syncthreads();

        uint32_t sbase = sb + cur*STG_B;
#pragma unroll
        for (int ks = 0; ks < 2; ks++){
            uint32_t bh[2][4], bl[2][4];
#pragma unroll
            for (int nj = 0; nj < 2; nj++){
                uint32_t rb = (uint32_t)(wn*32 + nj*16 + (lane & 15));
                uint32_t c4 = (uint32_t)(ks*2 + (lane >> 4)) ^ ((rb >> 1) & 3);
                uint32_t ab = sbase + 16384 + rb*64 + c4*16;
                ldsm4(bh[nj], ab);
                ldsm4(bl[nj], ab + 8192);
            }
#pragma unroll
            for (int mi = 0; mi < 4; mi++){
                uint32_t ra = (uint32_t)(wm*64 + mi*16 + (lane & 15));
                uint32_t c4 = (uint32_t)(ks*2 + (lane >> 4)) ^ ((ra >> 1) & 3);
                uint32_t aa = sbase + ra*64 + c4*16;
                uint32_t a4h[4], a4l[4];
                ldsm4(a4h, aa);
                ldsm4(a4l, aa + 8192);
#pragma unroll
                for (int nf = 0; nf < 4; nf++){
                    int nj = nf >> 1, s = nf & 1;
                    uint32_t b0h = bh[nj][s], b1h = bh[nj][2+s];
                    uint32_t b0l = bl[nj][s], b1l = bl[nj][2+s];
                    mma16816(c[mi][nf], a4h, b0h, b1h);
                    mma16816(c[mi][nf], a4h, b0l, b1l);
                    mma16816(c[mi][nf], a4l, b0h, b1h);
                }
            }
        }
        __syncthreads();
    }

    // epilogue
#pragma unroll
    for (int mi = 0; mi < 4; mi++){
#pragma unroll
        for (int nf = 0; nf < 4; nf++){
            int gr = row0 + wm*64 + mi*16 + (lane >> 2);
            int gc = col0 + wn*32 + nf*8 + (lane & 3)*2;
#pragma unroll
            for (int q = 0; q < 4; q++){
                int rr = gr + (q >> 1)*8;
                int cc = gc + (q & 1);
                if (rr < M && cc < N){
                    float v = c[mi][nf][q];
                    if (bias0) v += bias0[cc];
                    if (bias1) v += bias1[cc];
                    C[(size_t)rr*ldc + cc] = v;
                }
            }
        }
    }
}

// ---------------- pack kernels (fp32 -> swizzled packed bf16 hi/lo) ----------------
// packed offset for panel-local row pr, tile kt, k-in-tile kc:
//   (p*NT + kt)*4096 + pr*32 + (((kc>>3) ^ ((pr>>1)&3))*8) + (kc&7)
__global__ void pack_rows_k(const float* __restrict__ src, long srcLd, int colOff,
                            int Rr, int Kr, int NT,
                            __nv_bfloat16* __restrict__ hi, __nv_bfloat16* __restrict__ lo)
{
    int r = blockIdx.x;
    int p = r >> 7, pr = r & 127;
    size_t pbase = ((size_t)p*NT)*4096 + (size_t)pr*32;
    const float* s = src + (size_t)r*srcLd + colOff;
    int Kp = NT*32;
    bool rok = (r < Rr);
    int sw = (pr >> 1) & 3;
    for (int k = threadIdx.x; k < Kp; k += 256){
        int kt = k >> 5, kc = k & 31;
        size_t off = pbase + (size_t)kt*4096 + (size_t)(((kc>>3) ^ sw)*8 + (kc&7));
        float x = (rok && k < Kr) ? s[k] : 0.f;
        __nv_bfloat16 h = __float2bfloat16(x);
        hi[off] = h;
        lo[off] = __float2bfloat16(x - __bfloat162float(h));
    }
}

__global__ void pack_inp_k(const float* __restrict__ inp,
                           __nv_bfloat16* __restrict__ hi, __nv_bfloat16* __restrict__ lo)
{
    int r = blockIdx.x;              // r = t*B + b
    int t = r / B_, b = r % B_;
    int p = r >> 7, pr = r & 127;
    size_t pbase = ((size_t)p*NT_E)*4096 + (size_t)pr*32;
    const float* s = inp + ((size_t)b*T_ + t)*E_;
    int sw = (pr >> 1) & 3;
    for (int k = threadIdx.x; k < KP_; k += 256){
        int kt = k >> 5, kc = k & 31;
        size_t off = pbase + (size_t)kt*4096 + (size_t)(((kc>>3) ^ sw)*8 + (kc&7));
        float x = (k < E_) ? s[k] : 0.f;
        __nv_bfloat16 h = __float2bfloat16(x);
        hi[off] = h;
        lo[off] = __float2bfloat16(x - __bfloat162float(h));
    }
}

// out_W [E,H] -> packed transpose rows j in [0,1024), k = e in [0,KP_)
__global__ void pack_tr_k(const float* __restrict__ src,
                          __nv_bfloat16* __restrict__ hi, __nv_bfloat16* __restrict__ lo)
{
    __shared__ float t[32][33];
    int e0 = blockIdx.x*32, j0 = blockIdx.y*32;
    for (int i = threadIdx.y; i < 32; i += 8){
        int e = e0+i, j = j0+threadIdx.x;
        t[i][threadIdx.x] = (e < E_ && j < H_) ? src[(size_t)e*H_ + j] : 0.f;
    }
    __syncthreads();
    for (int i = threadIdx.y; i < 32; i += 8){
        int j = j0+i;
        int e = e0+threadIdx.x;
        int p = j >> 7, pr = j & 127;
        int kt = e >> 5, kc = e & 31;
        size_t off = ((size_t)p*NT_E + kt)*4096 + (size_t)pr*32
                   + (size_t)((((kc>>3) ^ ((pr>>1)&3))*8) + (kc&7));
        float x = t[threadIdx.x][i];
        __nv_bfloat16 h = __float2bfloat16(x);
        hi[off] = h;
        lo[off] = __float2bfloat16(x - __bfloat162float(h));
    }
}

// ---------------- small SIMT GEMM for n2attn ----------------
__global__ __launch_bounds__(256,2)
void sgemm_nt(const float* __restrict__ A, const float* __restrict__ Bm,
              float* __restrict__ C,
              const float* __restrict__ bias0,
              int M, int N, int K, int lda, int ldb, int bColOff, int ldc)
{
    __shared__ float As[16][132];
    __shared__ float Bs[16][132];
    const int row0 = blockIdx.y*128, col0 = blockIdx.x*128;
    const int tid = threadIdx.x;
    const int tx = tid & 15, ty = tid >> 4;
    const int lk = tid & 15, lr0 = tid >> 4;
    long aOff[8]; int aOk[8]; long bOff[8]; int bOk[8];
#pragma unroll
    for (int i = 0; i < 8; i++){
        int gr = row0 + lr0 + i*16;
        aOk[i] = (gr < M); aOff[i] = (long)(aOk[i] ? gr : 0)*lda;
        int gc = col0 + lr0 + i*16;
        bOk[i] = (gc < N); bOff[i] = (long)(bOk[i] ? gc : 0)*ldb + bColOff;
    }
    float acc[8][8];
#pragma unroll
    for (int i = 0; i < 8; i++)
#pragma unroll
        for (int j = 0; j < 8; j++) acc[i][j] = 0.f;
    for (int k0 = 0; k0 < K; k0 += 16){
        int gk = k0 + lk; bool kOk = (gk < K);
#pragma unroll
        for (int i = 0; i < 8; i++){
            As[lk][lr0+i*16] = (kOk && aOk[i]) ? A[aOff[i]+gk] : 0.f;
            Bs[lk][lr0+i*16] = (kOk && bOk[i]) ? Bm[bOff[i]+gk] : 0.f;
        }
        __syncthreads();
#pragma unroll
        for (int kk = 0; kk < 16; kk++){
            float4 a0 = *(const float4*)&As[kk][ty*8];
            float4 a1 = *(const float4*)&As[kk][ty*8+4];
            float4 b0 = *(const float4*)&Bs[kk][tx*8];
            float4 b1 = *(const float4*)&Bs[kk][tx*8+4];
            float a[8] = {a0.x,a0.y,a0.z,a0.w,a1.x,a1.y,a1.z,a1.w};
            float b[8] = {b0.x,b0.y,b0.z,b0.w,b1.x,b1.y,b1.z,b1.w};
#pragma unroll
            for (int i = 0; i < 8; i++)
#pragma unroll
                for (int j = 0; j < 8; j++) acc[i][j] += a[i]*b[j];
        }
        __syncthreads();
    }
#pragma unroll
    for (int i = 0; i < 8; i++){
        int gr = row0 + ty*8 + i;
        if (gr >= M) continue;
#pragma unroll
        for (int j = 0; j < 8; j++){
            int gc = col0 + tx*8 + j;
            if (gc >= N) continue;
            float v = acc[i][j];
            if (bias0) v += bias0[gc];
            C[(long)gr*ldc + gc] = v;
        }
    }
}

__global__ void skinny_k(const float* __restrict__ A, const float* __restrict__ Bm)
{
    __shared__ float Ash[8*1024];
    int w = threadIdx.x >> 5, lane = threadIdx.x & 31;
    int j = blockIdx.x*8 + w;
    float acc[8] = {0,0,0,0,0,0,0,0};
    for (int k0 = 0; k0 < E_; k0 += 1024){
        int kc = min(1024, E_ - k0);
        __syncthreads();
        for (int idx = threadIdx.x; idx < 8192; idx += 256){
            int r = idx >> 10, k = idx & 1023;
            Ash[idx] = (k < kc) ? A[(long)r*E_ + k0 + k] : 0.f;
        }
        __syncthreads();
        if (j < H_){
            const float* br = Bm + (long)j*EPNZ_ + k0;
            for (int k = lane; k < kc; k += 32){
                float wv = br[k];
#pragma unroll
                for (int b = 0; b < 8; b++) acc[b] += wv*Ash[b*1024 + k];
            }
        }
    }
    if (j < H_){
#pragma unroll
        for (int b = 0; b < 8; b++) acc[b] = wsum(acc[b]);
        if (lane == 0)
            for (int b = 0; b < 8; b++) g_emb0[b*H_ + j] = acc[b];
    }
}

__global__ void vvec_k(const float* __restrict__ embW, const float* __restrict__ out_b,
                       const float* __restrict__ emb_b)
{
    __shared__ float red[256];
    int j = blockIdx.x;
    float s = 0.f;
    for (int k = threadIdx.x; k < E_; k += 256) s += embW[(long)j*EPNZ_ + k]*out_b[k];
    red[threadIdx.x] = s; __syncthreads();
    for (int o = 128; o; o >>= 1){
        if (threadIdx.x < o) red[threadIdx.x] += red[threadIdx.x+o];
        __syncthreads();
    }
    if (threadIdx.x == 0) g_v2[j] = red[0] + emb_b[j];
}

__global__ void zero_k(){
    int i = blockIdx.x*256 + threadIdx.x;
    if (i < B_*H_){ g_h[0][i] = 0.f; g_c[i] = 0.f; }
}

__global__ void enc_step_k(const float* __restrict__ Whh, int t)
{
    __shared__ float hs[B_*H_];
    const float* hIn = g_h[t & 1];
    float* hOut = g_h[(t & 1) ^ 1];
    const float* gx = g_encGX + (long)t*B_*G4H_;
    int tid = threadIdx.x;
    for (int i = tid; i < B_*H_; i += 256) hs[i] = hIn[i];
    __syncthreads();
    int w = tid >> 5, lane = tid & 31;
    int j = blockIdx.x*8 + w;
    const float *w0 = Whh+(long)j*H_, *w1 = Whh+(long)(H_+j)*H_;
    const float *w2 = Whh+(long)(2*H_+j)*H_, *w3 = Whh+(long)(3*H_+j)*H_;
    float a0[8]={0},a1[8]={0},a2[8]={0},a3[8]={0};
    for (int k = lane; k < H_; k += 32){
        float x0=w0[k],x1=w1[k],x2=w2[k],x3=w3[k];
#pragma unroll
        for (int b = 0; b < 8; b++){
            float hv = hs[b*H_+k];
            a0[b]+=x0*hv; a1[b]+=x1*hv; a2[b]+=x2*hv; a3[b]+=x3*hv;
        }
    }
#pragma unroll
    for (int b = 0; b < 8; b++){
        a0[b]=wsum(a0[b]); a1[b]=wsum(a1[b]); a2[b]=wsum(a2[b]); a3[b]=wsum(a3[b]);
    }
    if (lane == 0){
#pragma unroll
        for (int b = 0; b < 8; b++){
            const float* gr = gx + (long)b*G4H_;
            float ig = sigf (gr[j]       + a0[b]);
            float fg = sigf (gr[H_+j]    + a1[b]);
            float gg = tanhf(gr[2*H_+j]  + a2[b]);
            float og = sigf (gr[3*H_+j]  + a3[b]);
            float c = fg*g_c[b*H_+j] + ig*gg;
            g_c[b*H_+j] = c;
            float h = og*tanhf(c);
            hOut[b*H_+j] = h;
            g_encBTH[((long)b*T_ + t)*H_ + j] = h;
        }
    }
}

__global__ void emb0_k(const float* __restrict__ emb_b)
{
    int i = blockIdx.x*256 + threadIdx.x;
    if (i < B_*H_) g_emb[i] = g_emb0[i] + g_n1[i] + emb_b[i % H_];
}

__global__ void dk1_k(int s)
{
    __shared__ float hs[B_*H_];
    const float* hIn = g_h[s & 1];
    const float* n1 = g_n1 + (long)s*B_*H_;
    int tid = threadIdx.x;
    for (int i = tid; i < B_*H_; i += 256) hs[i] = hIn[i];
    __syncthreads();
    int w = tid >> 5, lane = tid & 31;
    int j = blockIdx.x*8 + w;
    const float* mr = g_M + (long)j*H_;
    float acc[8]={0,0,0,0,0,0,0,0};
    for (int k = lane; k < H_; k += 32){
        float mv = mr[k];
#pragma unroll
        for (int b = 0; b < 8; b++) acc[b] += mv*hs[b*H_+k];
    }
#pragma unroll
    for (int b = 0; b < 8; b++) acc[b] = wsum(acc[b]);
    if (lane == 0){
        float vb = g_v2[j];
        for (int b = 0; b < 8; b++) g_emb[b*H_+j] = acc[b] + n1[b*H_+j] + vb;
    }
}

__global__ void dk2_k(const float* __restrict__ attW, int s)
{
    __shared__ float xs[2*H_];
    __shared__ float lg[T_];
    __shared__ float ps[T_];
    int b = blockIdx.x, tid = threadIdx.x;
    const float* hIn = g_h[s & 1];
    const float* n2 = g_n2 + (long)s*B_*T_;
    for (int i = tid; i < H_; i += 256){ xs[i] = g_emb[b*H_+i]; xs[H_+i] = hIn[b*H_+i]; }
    __syncthreads();
    int w = tid >> 5, lane = tid & 31;
    for (int ti = 0; ti < 16; ti++){
        int t = w*16 + ti;
        const float* wr = attW + (long)t*3*H_;
        float sv = 0.f;
        for (int k = lane; k < 2*H_; k += 32) sv += wr[k]*xs[k];
        sv = wsum(sv);
        if (lane == 0) lg[t] = sv + n2[b*T_+t];
    }
    __syncthreads();
    if (w == 0){
        float m = -1e30f;
        for (int i = lane; i < T_; i += 32) m = fmaxf(m, lg[i]);
#pragma unroll
        for (int o = 16; o; o >>= 1) m = fmaxf(m, __shfl_xor_sync(0xffffffffu, m, o));
        float ss = 0.f;
        for (int i = lane; i < T_; i += 32){ float e = expf(lg[i]-m); ps[i] = e; ss += e; }
        ss = wsum(ss);
        float inv = 1.f/ss;
        for (int i = lane; i < T_; i += 32) ps[i] *= inv;
    }
    __syncthreads();
    for (int j = tid; j < H_; j += 256){
        float sv = 0.f;
        const float* eb = g_encBTH + (long)b*T_*H_ + j;
#pragma unroll 4
        for (int t = 0; t < T_; t++) sv += ps[t]*eb[(long)t*H_];
        g_app[b*H_+j] = sv;
    }
}

__global__ void dk3_k(const float* __restrict__ combW, const float* __restrict__ comb_b)
{
    __shared__ float sh[B_*H_];
    int tid = threadIdx.x;
    int w = tid >> 5, lane = tid & 31;
    int j = blockIdx.x*8 + w;
    const float* wr = combW + (long)j*2*H_;
    float acc[8]={0,0,0,0,0,0,0,0};
    for (int i = tid; i < B_*H_; i += 256) sh[i] = g_emb[i];
    __syncthreads();
    for (int k = lane; k < H_; k += 32){
        float wv = wr[k];
#pragma unroll
        for (int b = 0; b < 8; b++) acc[b] += wv*sh[b*H_+k];
    }
    __syncthreads();
    for (int i = tid; i < B_*H_; i += 256) sh[i] = g_app[i];
    __syncthreads();
    for (int k = lane; k < H_; k += 32){
        float wv = wr[H_+k];
#pragma unroll
        for (int b = 0; b < 8; b++) acc[b] += wv*sh[b*H_+k];
    }
#pragma unroll
    for (int b = 0; b < 8; b++) acc[b] = wsum(acc[b]);
    if (lane == 0){
        float cb = comb_b[j];
        for (int b = 0; b < 8; b++) g_outv[b*H_+j] = fmaxf(0.f, acc[b] + cb);
    }
}

__global__ void dk4_k(const float* __restrict__ Wih, const float* __restrict__ Whh,
                      const float* __restrict__ bih, const float* __restrict__ bhh, int s)
{
    __shared__ float sh[B_*H_];
    int pp = s & 1;
    const float* hIn = g_h[pp];
    float* hOut = g_h[pp ^ 1];
    int tid = threadIdx.x;
    int w = tid >> 5, lane = tid & 31;
    int j = blockIdx.x*8 + w;
    float a0[8]={0},a1[8]={0},a2[8]={0},a3[8]={0};
    for (int i = tid; i < B_*H_; i += 256) sh[i] = g_outv[i];
    __syncthreads();
    {
        const float *w0=Wih+(long)j*H_, *w1=Wih+(long)(H_+j)*H_;
        const float *w2=Wih+(long)(2*H_+j)*H_, *w3=Wih+(long)(3*H_+j)*H_;
        for (int k = lane; k < H_; k += 32){
            float x0=w0[k],x1=w1[k],x2=w2[k],x3=w3[k];
#pragma unroll
            for (int b = 0; b < 8; b++){
                float hv = sh[b*H_+k];
                a0[b]+=x0*hv; a1[b]+=x1*hv; a2[b]+=x2*hv; a3[b]+=x3*hv;
            }
        }
    }
    __syncthreads();
    for (int i = tid; i < B_*H_; i += 256) sh[i] = hIn[i];
    __syncthreads();
    {
        const float *w0=Whh+(long)j*H_, *w1=Whh+(long)(H_+j)*H_;
        const float *w2=Whh+(long)(2*H_+j)*H_, *w3=Whh+(long)(3*H_+j)*H_;
        for (int k = lane; k < H_; k += 32){
            float x0=w0[k],x1=w1[k],x2=w2[k],x3=w3[k];
#pragma unroll
            for (int b = 0; b < 8; b++){
                float hv = sh[b*H_+k];
                a0[b]+=x0*hv; a1[b]+=x1*hv; a2[b]+=x2*hv; a3[b]+=x3*hv;
            }
        }
    }
#pragma unroll
    for (int b = 0; b < 8; b++){
        a0[b]=wsum(a0[b]); a1[b]=wsum(a1[b]); a2[b]=wsum(a2[b]); a3[b]=wsum(a3[b]);
    }
    if (lane == 0){
        float bi0=bih[j]+bhh[j], bi1=bih[H_+j]+bhh[H_+j];
        float bi2=bih[2*H_+j]+bhh[2*H_+j], bi3=bih[3*H_+j]+bhh[3*H_+j];
#pragma unroll
        for (int b = 0; b < 8; b++){
            float ig = sigf (a0[b]+bi0);
            float fg = sigf (a1[b]+bi1);
            float gg = tanhf(a2[b]+bi2);
            float og = sigf (a3[b]+bi3);
            float c = fg*g_c[b*H_+j] + ig*gg;
            g_c[b*H_+j] = c;
            float h = og*tanhf(c);
            hOut[b*H_+j] = h;
            g_Hs[((long)s*B_ + b)*H_ + j] = h;
        }
    }
}

extern "C" void kernel_launch(void* const* d_in, const int* in_sizes, int n_in,
                              void* d_out, int out_size)
{
    int off = (in_sizes[1] == 1) ? 1 : 0;
    const float* input    = (const float*)d_in[0];
    const float* noise1   = (const float*)d_in[1+off];
    const float* noise2   = (const float*)d_in[2+off];
    const float* init_dec = (const float*)d_in[3+off];
    const float* enc_Wih  = (const float*)d_in[4+off];
    const float* enc_Whh  = (const float*)d_in[5+off];
    const float* enc_bih  = (const float*)d_in[6+off];
    const float* enc_bhh  = (const float*)d_in[7+off];
    const float* dec_Wih  = (const float*)d_in[8+off];
    const float* dec_Whh  = (const float*)d_in[9+off];
    const float* dec_bih  = (const float*)d_in[10+off];
    const float* dec_bhh  = (const float*)d_in[11+off];
    const float* emb_W    = (const float*)d_in[12+off];
    const float* emb_b    = (const float*)d_in[13+off];
    const float* attn_W   = (const float*)d_in[14+off];
    const float* attn_b   = (const float*)d_in[15+off];
    const float* comb_W   = (const float*)d_in[16+off];
    const float* comb_b   = (const float*)d_in[17+off];
    const float* out_W    = (const float*)d_in[18+off];
    const float* out_b    = (const float*)d_in[19+off];
    float* out = (float*)d_out;

    float *p_gx, *p_M, *p_n1, *p_n2, *p_Hs;
    cudaGetSymbolAddress((void**)&p_gx, g_encGX);
    cudaGetSymbolAddress((void**)&p_M,  g_M);
    cudaGetSymbolAddress((void**)&p_n1, g_n1);
    cudaGetSymbolAddress((void**)&p_n2, g_n2);
    cudaGetSymbolAddress((void**)&p_Hs, g_Hs);
    __nv_bfloat16 *inpH,*inpL,*wihH,*wihL,*embEH,*embEL,*embNH,*embNL;
    __nv_bfloat16 *oWTH,*oWTL,*oWH,*oWL,*nzH,*nzL,*HsH,*HsL;
    cudaGetSymbolAddress((void**)&inpH, g_inpH);   cudaGetSymbolAddress((void**)&inpL, g_inpL);
    cudaGetSymbolAddress((void**)&wihH, g_wihH);   cudaGetSymbolAddress((void**)&wihL, g_wihL);
    cudaGetSymbolAddress((void**)&embEH, g_embEH); cudaGetSymbolAddress((void**)&embEL, g_embEL);
    cudaGetSymbolAddress((void**)&embNH, g_embNH); cudaGetSymbolAddress((void**)&embNL, g_embNL);
    cudaGetSymbolAddress((void**)&oWTH, g_oWTH);   cudaGetSymbolAddress((void**)&oWTL, g_oWTL);
    cudaGetSymbolAddress((void**)&oWH, g_oWH);     cudaGetSymbolAddress((void**)&oWL, g_oWL);
    cudaGetSymbolAddress((void**)&nzH, g_nzH);     cudaGetSymbolAddress((void**)&nzL, g_nzL);
    cudaGetSymbolAddress((void**)&HsH, g_HsH);     cudaGetSymbolAddress((void**)&HsL, g_HsL);

    cudaFuncSetAttribute(mma_gemm, cudaFuncAttributeMaxDynamicSharedMemorySize, SMEM_B);

    // 1-3: G1 prerequisites (so G1 sits in the ncu-profiled slot)
    pack_inp_k<<<1024,256>>>(input, inpH, inpL);
    pack_rows_k<<<4096,256>>>(enc_Wih, E_, 0, G4H_, E_, NT_E, wihH, wihL);
    pack_rows_k<<<1024,256>>>(emb_W, EPNZ_, 0, H_, E_, NT_E, embEH, embEL);

    // 4: G1: enc_gx [1024, 4000] = inp @ wih^T + biases
    mma_gemm<<<dim3(32, 8), 256, SMEM_B>>>(inpH, inpL, wihH, wihL,
        p_gx, enc_bih, enc_bhh, T_*B_, G4H_, NT_E, G4H_);

    // remaining packs
    pack_rows_k<<<1024,256>>>(emb_W, EPNZ_, E_, H_, NZ_, NT_NZ, embNH, embNL);
    pack_tr_k<<<dim3(NT_E, 32), dim3(32,8)>>>(out_W, oWTH, oWTL);
    pack_rows_k<<<239*128,256>>>(out_W, H_, 0, E_, H_, NT_H, oWH, oWL);
    pack_rows_k<<<512,256>>>(noise1, NZ_, 0, S_*B_, NZ_, NT_NZ, nzH, nzL);

    // G2: M [1000,1000] = emb_W[:, :E] @ out_W
    mma_gemm<<<dim3(8, 8), 256, SMEM_B>>>(embEH, embEL, oWTH, oWTL,
        p_M, 0, 0, H_, H_, NT_E, H_);
    // G3: n1emb [512, 1000] = noise1 @ emb_W[:, E:]^T
    mma_gemm<<<dim3(8, 4), 256, SMEM_B>>>(nzH, nzL, embNH, embNL,
        p_n1, 0, 0, S_*B_, H_, NT_NZ, H_);

    vvec_k<<<H_,256>>>(emb_W, out_b, emb_b);
    sgemm_nt<<<dim3(1,4),256>>>(noise2, attn_W, p_n2, attn_b,
        S_*B_, T_, H_, H_, 3*H_, 2*H_, T_);
    skinny_k<<<H_/8,256>>>(init_dec, emb_W);
    zero_k<<<32,256>>>();

    for (int t = 0; t < T_; t++)
        enc_step_k<<<H_/8,256>>>(enc_Whh, t);

    for (int s = 0; s < S_; s++){
        if (s == 0) emb0_k<<<32,256>>>(emb_b);
        else        dk1_k<<<H_/8,256>>>(s);
        dk2_k<<<B_,256>>>(attn_W, s);
        dk3_k<<<H_/8,256>>>(comb_W, comb_b);
        dk4_k<<<H_/8,256>>>(dec_Wih, dec_Whh, dec_bih, dec_bhh, s);
    }

    // G4: summary [512, E] = Hs @ out_W^T + out_b
    pack_rows_k<<<512,256>>>(p_Hs, H_, 0, S_*B_, H_, NT_H, HsH, HsL);
    mma_gemm<<<dim3(239, 4), 256, SMEM_B>>>(HsH, HsL, oWH, oWL,
        out, out_b, 0, S_*B_, E_, NT_H, E_);
}

// round 12
// speedup vs baseline: 1.2921x; 1.0600x over previous
#include <cuda_runtime.h>
#include <cuda_bf16.h>
#include <math.h>
#include <stdint.h>

#define B_ 8
#define T_ 128
#define E_ 30522
#define H_ 1000
#define S_ 64
#define NZ_ 10000
#define EPNZ_ 40522
#define G4H_ (4*H_)
#define KP_ 30528
#define NZP_ 10016
#define HP_ 1024
#define NT_E (KP_/32)    // 954
#define NT_NZ (NZP_/32)  // 313
#define NT_H (HP_/32)    // 32

// ---------------- fp32 scratch ----------------
__device__ float g_encGX[(size_t)T_*B_*G4H_];
__device__ float g_M[(size_t)H_*H_];
__device__ float g_Mp[(size_t)4*H_*H_];        // G2 K-split partials
__device__ float g_n1[(size_t)S_*B_*H_];
__device__ float g_n1p[(size_t)4*S_*B_*H_];    // G3 K-split partials
__device__ float g_n2[(size_t)S_*B_*T_];
__device__ float g_emb0[B_*H_];
__device__ float g_v2[H_];
__device__ float g_encBTH[(size_t)B_*T_*H_];
__device__ float g_h[2][B_*H_];
__device__ float g_c[B_*H_];
__device__ float g_emb[B_*H_];
__device__ float g_app[B_*H_];
__device__ float g_outv[B_*H_];
__device__ float g_Hs[(size_t)S_*B_*H_];

// ---------------- packed bf16 operands ----------------
__device__ __nv_bfloat16 g_inpH[(size_t)8*NT_E*4096],   g_inpL[(size_t)8*NT_E*4096];
__device__ __nv_bfloat16 g_wihH[(size_t)32*NT_E*4096],  g_wihL[(size_t)32*NT_E*4096];
__device__ __nv_bfloat16 g_embEH[(size_t)8*NT_E*4096],  g_embEL[(size_t)8*NT_E*4096];
__device__ __nv_bfloat16 g_embNH[(size_t)8*NT_NZ*4096], g_embNL[(size_t)8*NT_NZ*4096];
__device__ __nv_bfloat16 g_oWTH[(size_t)8*NT_E*4096],   g_oWTL[(size_t)8*NT_E*4096];
__device__ __nv_bfloat16 g_oWH[(size_t)239*NT_H*4096],  g_oWL[(size_t)239*NT_H*4096];
__device__ __nv_bfloat16 g_nzH[(size_t)4*NT_NZ*4096],   g_nzL[(size_t)4*NT_NZ*4096];
__device__ __nv_bfloat16 g_HsH[(size_t)4*NT_H*4096],    g_HsL[(size_t)4*NT_H*4096];

__device__ __forceinline__ float wsum(float v){
#pragma unroll
    for (int o = 16; o; o >>= 1) v += __shfl_xor_sync(0xffffffffu, v, o);
    return v;
}
__device__ __forceinline__ float sigf(float x){ return 1.f/(1.f+expf(-x)); }

__device__ __forceinline__ uint32_t smem_u32(const void* p){
    uint32_t a;
    asm("{ .reg .u64 t; cvta.to.shared.u64 t, %1; cvt.u32.u64 %0, t; }" : "=r"(a) : "l"(p));
    return a;
}
__device__ __forceinline__ void ldsm4(uint32_t* r, uint32_t a){
    asm volatile("ldmatrix.sync.aligned.m8n8.x4.shared.b16 {%0,%1,%2,%3}, [%4];"
        : "=r"(r[0]),"=r"(r[1]),"=r"(r[2]),"=r"(r[3]) : "r"(a));
}
__device__ __forceinline__ void mma16816(float* c, const uint32_t* a,
                                         uint32_t b0, uint32_t b1){
    asm volatile("mma.sync.aligned.m16n8k16.row.col.f32.bf16.bf16.f32 "
        "{%0,%1,%2,%3}, {%4,%5,%6,%7}, {%8,%9}, {%0,%1,%2,%3};"
        : "+f"(c[0]),"+f"(c[1]),"+f"(c[2]),"+f"(c[3])
        : "r"(a[0]),"r"(a[1]),"r"(a[2]),"r"(a[3]), "r"(b0),"r"(b1));
}
#define MB_INIT(mb, c)  asm volatile("mbarrier.init.shared.b64 [%0], %1;" :: "r"((uint32_t)(mb)), "r"((uint32_t)(c)) : "memory")
#define MB_EXPECT(mb, n) asm volatile("mbarrier.arrive.expect_tx.shared.b64 _, [%0], %1;" :: "r"((uint32_t)(mb)), "r"((uint32_t)(n)) : "memory")
#define MB_WAIT(mb, ph) do { \
    uint32_t _m=(uint32_t)(mb), _p=(uint32_t)(ph), _d; \
    asm volatile("{\n\t.reg .pred p;\n\tmbarrier.try_wait.parity.shared.b64 p, [%1], %2;\n\tselp.b32 %0, 1, 0, p;\n\t}" \
        : "=r"(_d) : "r"(_m), "r"(_p) : "memory"); \
    if (!_d){ \
        asm volatile("{\n\t.reg .pred P1;\n\tWL_%=:\n\tmbarrier.try_wait.parity.shared.b64 P1, [%0], %1;\n\t@P1 bra.uni WD_%=;\n\tbra.uni WL_%=;\n\tWD_%=:\n\t}" \
            :: "r"(_m), "r"(_p) : "memory"); \
    } } while(0)
__device__ __forceinline__ void bulk_cp(uint32_t dst, const void* src, uint32_t sz, uint32_t mb){
    asm volatile("cp.async.bulk.shared::cta.global.mbarrier::complete_tx::bytes [%0], [%1], %2, [%3];"
        :: "r"(dst), "l"(src), "r"(sz), "r"(mb) : "memory");
}

#define STG_B 32768
#define SMEM_B (2*STG_B)

// ---------------- packed split-bf16 HMMA NT GEMM: C = A@B^T (+bias) ----------------
// grid.z = K-split: partial z writes C + z*M*ldc; bias applied only on z==0.
__global__ __launch_bounds__(256,2)
void mma_gemm(const __nv_bfloat16* __restrict__ Ah, const __nv_bfloat16* __restrict__ Al,
              const __nv_bfloat16* __restrict__ Bh, const __nv_bfloat16* __restrict__ Bl,
              float* __restrict__ C, const float* __restrict__ bias0,
              const float* __restrict__ bias1,
              int M, int N, int NT, int ldc)
{
    extern __shared__ char smem[];
    __shared__ __align__(8) uint64_t mbar[2];
    uint32_t sb = smem_u32(smem);
    uint32_t mba = smem_u32(mbar);
    const int tid = threadIdx.x, lane = tid & 31, wid = tid >> 5;
    const int pa = blockIdx.y, pb = blockIdx.x;
    const int row0 = pa*128, col0 = pb*128;
    const int wm = wid >> 2, wn = wid & 3;

    const int zc = gridDim.z, z = blockIdx.z;
    const int chunk = (NT + zc - 1)/zc;
    const int kb = z*chunk;
    const int ke = min(NT, kb + chunk);
    float* Cz = C + (size_t)z*M*ldc;
    const bool addB = (z == 0);

    if (tid == 0){ MB_INIT(mba, 1); MB_INIT(mba+8, 1); }
    __syncthreads();

    float c[4][4][4];
#pragma unroll
    for (int i = 0; i < 4; i++)
#pragma unroll
        for (int j = 0; j < 4; j++)
#pragma unroll
            for (int q = 0; q < 4; q++) c[i][j][q] = 0.f;

    auto load = [&](int kt, int stg){
        if (tid == 0){
            uint32_t mb = mba + stg*8;
            MB_EXPECT(mb, STG_B);
            uint32_t d = sb + stg*STG_B;
            bulk_cp(d,          Ah + ((size_t)pa*NT + kt)*4096, 8192, mb);
            bulk_cp(d + 8192,   Al + ((size_t)pa*NT + kt)*4096, 8192, mb);
            bulk_cp(d + 16384,  Bh + ((size_t)pb*NT + kt)*4096, 8192, mb);
            bulk_cp(d + 24576,  Bl + ((size_t)pb*NT + kt)*4096, 8192, mb);
        }
    };

    int ph[2] = {0, 0};
    load(kb, 0);
    for (int kt = kb; kt < ke; kt++){
        int cur = (kt - kb) & 1;
        if (kt + 1 < ke) load(kt+1, cur ^ 1);
        MB_WAIT(mba + cur*8, ph[cur]); ph[cur] ^= 1;
        __syncthreads();

        uint32_t sbase = sb + cur*STG_B;
#pragma unroll
        for (int ks = 0; ks < 2; ks++){
            uint32_t bh[2][4], bl[2][4];
#pragma unroll
            for (int nj = 0; nj < 2; nj++){
                uint32_t rb = (uint32_t)(wn*32 + nj*16 + (lane & 15));
                uint32_t c4 = (uint32_t)(ks*2 + (lane >> 4)) ^ ((rb >> 1) & 3);
                uint32_t ab = sbase + 16384 + rb*64 + c4*16;
                ldsm4(bh[nj], ab);
                ldsm4(bl[nj], ab + 8192);
            }
#pragma unroll
            for (int mi = 0; mi < 4; mi++){
                uint32_t ra = (uint32_t)(wm*64 + mi*16 + (lane & 15));
                uint32_t c4 = (uint32_t)(ks*2 + (lane >> 4)) ^ ((ra >> 1) & 3);
                uint32_t aa = sbase + ra*64 + c4*16;
                uint32_t a4h[4], a4l[4];
                ldsm4(a4h, aa);
                ldsm4(a4l, aa + 8192);
#pragma unroll
                for (int nf = 0; nf < 4; nf++){
                    int nj = nf >> 1, s = nf & 1;
                    uint32_t b0h = bh[nj][s], b1h = bh[nj][2+s];
                    uint32_t b0l = bl[nj][s], b1l = bl[nj][2+s];
                    mma16816(c[mi][nf], a4h, b0h, b1h);
                    mma16816(c[mi][nf], a4h, b0l, b1l);
                    mma16816(c[mi][nf], a4l, b0h, b1h);
                }
            }
        }
        __syncthreads();
    }

#pragma unroll
    for (int mi = 0; mi < 4; mi++){
#pragma unroll
        for (int nf = 0; nf < 4; nf++){
            int gr = row0 + wm*64 + mi*16 + (lane >> 2);
            int gc = col0 + wn*32 + nf*8 + (lane & 3)*2;
#pragma unroll
            for (int q = 0; q < 4; q++){
                int rr = gr + (q >> 1)*8;
                int cc = gc + (q & 1);
                if (rr < M && cc < N){
                    float v = c[mi][nf][q];
                    if (addB){
                        if (bias0) v += bias0[cc];
                        if (bias1) v += bias1[cc];
                    }
                    Cz[(size_t)rr*ldc + cc] = v;
                }
            }
        }
    }
}

__global__ void reduce_z(const float* __restrict__ in, float* __restrict__ out,
                         int zc, int mn)
{
    int i = blockIdx.x*256 + threadIdx.x;
    if (i >= mn) return;
    float s = 0.f;
    for (int z = 0; z < zc; z++) s += in[(size_t)z*mn + i];
    out[i] = s;
}

// ---------------- pack kernels ----------------
__global__ void pack_rows_k(const float* __restrict__ src, long srcLd, int colOff,
                            int Rr, int Kr, int NT,
                            __nv_bfloat16* __restrict__ hi, __nv_bfloat16* __restrict__ lo)
{
    int r = blockIdx.x;
    int p = r >> 7, pr = r & 127;
    size_t pbase = ((size_t)p*NT)*4096 + (size_t)pr*32;
    const float* s = src + (size_t)r*srcLd + colOff;
    int Kp = NT*32;
    bool rok = (r < Rr);
    int sw = (pr >> 1) & 3;
    for (int k = threadIdx.x; k < Kp; k += 256){
        int kt = k >> 5, kc = k & 31;
        size_t off = pbase + (size_t)kt*4096 + (size_t)(((kc>>3) ^ sw)*8 + (kc&7));
        float x = (rok && k < Kr) ? s[k] : 0.f;
        __nv_bfloat16 h = __float2bfloat16(x);
        hi[off] = h;
        lo[off] = __float2bfloat16(x - __bfloat162float(h));
    }
}

__global__ void pack_inp_k(const float* __restrict__ inp,
                           __nv_bfloat16* __restrict__ hi, __nv_bfloat16* __restrict__ lo)
{
    int r = blockIdx.x;
    int t = r / B_, b = r % B_;
    int p = r >> 7, pr = r & 127;
    size_t pbase = ((size_t)p*NT_E)*4096 + (size_t)pr*32;
    const float* s = inp + ((size_t)b*T_ + t)*E_;
    int sw = (pr >> 1) & 3;
    for (int k = threadIdx.x; k < KP_; k += 256){
        int kt = k >> 5, kc = k & 31;
        size_t off = pbase + (size_t)kt*4096 + (size_t)(((kc>>3) ^ sw)*8 + (kc&7));
        float x = (k < E_) ? s[k] : 0.f;
        __nv_bfloat16 h = __float2bfloat16(x);
        hi[off] = h;
        lo[off] = __float2bfloat16(x - __bfloat162float(h));
    }
}

__global__ void pack_tr_k(const float* __restrict__ src,
                          __nv_bfloat16* __restrict__ hi, __nv_bfloat16* __restrict__ lo)
{
    __shared__ float t[32][33];
    int e0 = blockIdx.x*32, j0 = blockIdx.y*32;
    for (int i = threadIdx.y; i < 32; i += 8){
        int e = e0+i, j = j0+threadIdx.x;
        t[i][threadIdx.x] = (e < E_ && j < H_) ? src[(size_t)e*H_ + j] : 0.f;
    }
    __syncthreads();
    for (int i = threadIdx.y; i < 32; i += 8){
        int j = j0+i;
        int e = e0+threadIdx.x;
        int p = j >> 7, pr = j & 127;
        int kt = e >> 5, kc = e & 31;
        size_t off = ((size_t)p*NT_E + kt)*4096 + (size_t)pr*32
                   + (size_t)((((kc>>3) ^ ((pr>>1)&3))*8) + (kc&7));
        float x = t[threadIdx.x][i];
        __nv_bfloat16 h = __float2bfloat16(x);
        hi[off] = h;
        lo[off] = __float2bfloat16(x - __bfloat162float(h));
    }
}

// ---------------- small SIMT GEMM for n2attn ----------------
__global__ __launch_bounds__(256,2)
void sgemm_nt(const float* __restrict__ A, const float* __restrict__ Bm,
              float* __restrict__ C,
              const float* __restrict__ bias0,
              int M, int N, int K, int lda, int ldb, int bColOff, int ldc)
{
    __shared__ float As[16][132];
    __shared__ float Bs[16][132];
    const int row0 = blockIdx.y*128, col0 = blockIdx.x*128;
    const int tid = threadIdx.x;
    const int tx = tid & 15, ty = tid >> 4;
    const int lk = tid & 15, lr0 = tid >> 4;
    long aOff[8]; int aOk[8]; long bOff[8]; int bOk[8];
#pragma unroll
    for (int i = 0; i < 8; i++){
        int gr = row0 + lr0 + i*16;
        aOk[i] = (gr < M); aOff[i] = (long)(aOk[i] ? gr : 0)*lda;
        int gc = col0 + lr0 + i*16;
        bOk[i] = (gc < N); bOff[i] = (long)(bOk[i] ? gc : 0)*ldb + bColOff;
    }
    float acc[8][8];
#pragma unroll
    for (int i = 0; i < 8; i++)
#pragma unroll
        for (int j = 0; j < 8; j++) acc[i][j] = 0.f;
    for (int k0 = 0; k0 < K; k0 += 16){
        int gk = k0 + lk; bool kOk = (gk < K);
#pragma unroll
        for (int i = 0; i < 8; i++){
            As[lk][lr0+i*16] = (kOk && aOk[i]) ? A[aOff[i]+gk] : 0.f;
            Bs[lk][lr0+i*16] = (kOk && bOk[i]) ? Bm[bOff[i]+gk] : 0.f;
        }
        __syncthreads();
#pragma unroll
        for (int kk = 0; kk < 16; kk++){
            float4 a0 = *(const float4*)&As[kk][ty*8];
            float4 a1 = *(const float4*)&As[kk][ty*8+4];
            float4 b0 = *(const float4*)&Bs[kk][tx*8];
            float4 b1 = *(const float4*)&Bs[kk][tx*8+4];
            float a[8] = {a0.x,a0.y,a0.z,a0.w,a1.x,a1.y,a1.z,a1.w};
            float b[8] = {b0.x,b0.y,b0.z,b0.w,b1.x,b1.y,b1.z,b1.w};
#pragma unroll
            for (int i = 0; i < 8; i++)
#pragma unroll
                for (int j = 0; j < 8; j++) acc[i][j] += a[i]*b[j];
        }
        __syncthreads();
    }
#pragma unroll
    for (int i = 0; i < 8; i++){
        int gr = row0 + ty*8 + i;
        if (gr >= M) continue;
#pragma unroll
        for (int j = 0; j < 8; j++){
            int gc = col0 + tx*8 + j;
            if (gc >= N) continue;
            float v = acc[i][j];
            if (bias0) v += bias0[gc];
            C[(long)gr*ldc + gc] = v;
        }
    }
}

__global__ void skinny_k(const float* __restrict__ A, const float* __restrict__ Bm)
{
    __shared__ float Ash[8*1024];
    int w = threadIdx.x >> 5, lane = threadIdx.x & 31;
    int j = blockIdx.x*8 + w;
    float acc[8] = {0,0,0,0,0,0,0,0};
    for (int k0 = 0; k0 < E_; k0 += 1024){
        int kc = min(1024, E_ - k0);
        __syncthreads();
        for (int idx = threadIdx.x; idx < 8192; idx += 256){
            int r = idx >> 10, k = idx & 1023;
            Ash[idx] = (k < kc) ? A[(long)r*E_ + k0 + k] : 0.f;
        }
        __syncthreads();
        if (j < H_){
            const float* br = Bm + (long)j*EPNZ_ + k0;
            for (int k = lane; k < kc; k += 32){
                float wv = br[k];
#pragma unroll
                for (int b = 0; b < 8; b++) acc[b] += wv*Ash[b*1024 + k];
            }
        }
    }
    if (j < H_){
#pragma unroll
        for (int b = 0; b < 8; b++) acc[b] = wsum(acc[b]);
        if (lane == 0)
            for (int b = 0; b < 8; b++) g_emb0[b*H_ + j] = acc[b];
    }
}

__global__ void vvec_k(const float* __restrict__ embW, const float* __restrict__ out_b,
                       const float* __restrict__ emb_b)
{
    __shared__ float red[256];
    int j = blockIdx.x;
    float s = 0.f;
    for (int k = threadIdx.x; k < E_; k += 256) s += embW[(long)j*EPNZ_ + k]*out_b[k];
    red[threadIdx.x] = s; __syncthreads();
    for (int o = 128; o; o >>= 1){
        if (threadIdx.x < o) red[threadIdx.x] += red[threadIdx.x+o];
        __syncthreads();
    }
    if (threadIdx.x == 0) g_v2[j] = red[0] + emb_b[j];
}

__global__ void zero_k(){
    int i = blockIdx.x*256 + threadIdx.x;
    if (i < B_*H_){ g_h[0][i] = 0.f; g_c[i] = 0.f; }
}

__global__ void enc_step_k(const float* __restrict__ Whh, int t)
{
    __shared__ float hs[B_*H_];
    const float* hIn = g_h[t & 1];
    float* hOut = g_h[(t & 1) ^ 1];
    const float* gx = g_encGX + (long)t*B_*G4H_;
    int tid = threadIdx.x;
    for (int i = tid; i < B_*H_; i += 256) hs[i] = hIn[i];
    __syncthreads();
    int w = tid >> 5, lane = tid & 31;
    int j = blockIdx.x*8 + w;
    const float *w0 = Whh+(long)j*H_, *w1 = Whh+(long)(H_+j)*H_;
    const float *w2 = Whh+(long)(2*H_+j)*H_, *w3 = Whh+(long)(3*H_+j)*H_;
    float a0[8]={0},a1[8]={0},a2[8]={0},a3[8]={0};
    for (int k = lane; k < H_; k += 32){
        float x0=w0[k],x1=w1[k],x2=w2[k],x3=w3[k];
#pragma unroll
        for (int b = 0; b < 8; b++){
            float hv = hs[b*H_+k];
            a0[b]+=x0*hv; a1[b]+=x1*hv; a2[b]+=x2*hv; a3[b]+=x3*hv;
        }
    }
#pragma unroll
    for (int b = 0; b < 8; b++){
        a0[b]=wsum(a0[b]); a1[b]=wsum(a1[b]); a2[b]=wsum(a2[b]); a3[b]=wsum(a3[b]);
    }
    if (lane == 0){
#pragma unroll
        for (int b = 0; b < 8; b++){
            const float* gr = gx + (long)b*G4H_;
            float ig = sigf (gr[j]       + a0[b]);
            float fg = sigf (gr[H_+j]    + a1[b]);
            float gg = tanhf(gr[2*H_+j]  + a2[b]);
            float og = sigf (gr[3*H_+j]  + a3[b]);
            float c = fg*g_c[b*H_+j] + ig*gg;
            g_c[b*H_+j] = c;
            float h = og*tanhf(c);
            hOut[b*H_+j] = h;
            g_encBTH[((long)b*T_ + t)*H_ + j] = h;
        }
    }
}

__global__ void emb0_k(const float* __restrict__ emb_b)
{
    int i = blockIdx.x*256 + threadIdx.x;
    if (i < B_*H_) g_emb[i] = g_emb0[i] + g_n1[i] + emb_b[i % H_];
}

__global__ void dk1_k(int s)
{
    __shared__ float hs[B_*H_];
    const float* hIn = g_h[s & 1];
    const float* n1 = g_n1 + (long)s*B_*H_;
    int tid = threadIdx.x;
    for (int i = tid; i < B_*H_; i += 256) hs[i] = hIn[i];
    __syncthreads();
    int w = tid >> 5, lane = tid & 31;
    int j = blockIdx.x*8 + w;
    const float* mr = g_M + (long)j*H_;
    float acc[8]={0,0,0,0,0,0,0,0};
    for (int k = lane; k < H_; k += 32){
        float mv = mr[k];
#pragma unroll
        for (int b = 0; b < 8; b++) acc[b] += mv*hs[b*H_+k];
    }
#pragma unroll
    for (int b = 0; b < 8; b++) acc[b] = wsum(acc[b]);
    if (lane == 0){
        float vb = g_v2[j];
        for (int b = 0; b < 8; b++) g_emb[b*H_+j] = acc[b] + n1[b*H_+j] + vb;
    }
}

__global__ void dk2_k(const float* __restrict__ attW, int s)
{
    __shared__ float xs[2*H_];
    __shared__ float lg[T_];
    __shared__ float ps[T_];
    int b = blockIdx.x, tid = threadIdx.x;
    const float* hIn = g_h[s & 1];
    const float* n2 = g_n2 + (long)s*B_*T_;
    for (int i = tid; i < H_; i += 256){ xs[i] = g_emb[b*H_+i]; xs[H_+i] = hIn[b*H_+i]; }
    __syncthreads();
    int w = tid >> 5, lane = tid & 31;
    for (int ti = 0; ti < 16; ti++){
        int t = w*16 + ti;
        const float* wr = attW + (long)t*3*H_;
        float sv = 0.f;
        for (int k = lane; k < 2*H_; k += 32) sv += wr[k]*xs[k];
        sv = wsum(sv);
        if (lane == 0) lg[t] = sv + n2[b*T_+t];
    }
    __syncthreads();
    if (w == 0){
        float m = -1e30f;
        for (int i = lane; i < T_; i += 32) m = fmaxf(m, lg[i]);
#pragma unroll
        for (int o = 16; o; o >>= 1) m = fmaxf(m, __shfl_xor_sync(0xffffffffu, m, o));
        float ss = 0.f;
        for (int i = lane; i < T_; i += 32){ float e = expf(lg[i]-m); ps[i] = e; ss += e; }
        ss = wsum(ss);
        float inv = 1.f/ss;
        for (int i = lane; i < T_; i += 32) ps[i] *= inv;
    }
    __syncthreads();
    for (int j = tid; j < H_; j += 256){
        float sv = 0.f;
        const float* eb = g_encBTH + (long)b*T_*H_ + j;
#pragma unroll 4
        for (int t = 0; t < T_; t++) sv += ps[t]*eb[(long)t*H_];
        g_app[b*H_+j] = sv;
    }
}

__global__ void dk3_k(const float* __restrict__ combW, const float* __restrict__ comb_b)
{
    __shared__ float sh[B_*H_];
    int tid = threadIdx.x;
    int w = tid >> 5, lane = tid & 31;
    int j = blockIdx.x*8 + w;
    const float* wr = combW + (long)j*2*H_;
    float acc[8]={0,0,0,0,0,0,0,0};
    for (int i = tid; i < B_*H_; i += 256) sh[i] = g_emb[i];
    __syncthreads();
    for (int k = lane; k < H_; k += 32){
        float wv = wr[k];
#pragma unroll
        for (int b = 0; b < 8; b++) acc[b] += wv*sh[b*H_+k];
    }
    __syncthreads();
    for (int i = tid; i < B_*H_; i += 256) sh[i] = g_app[i];
    __syncthreads();
    for (int k = lane; k < H_; k += 32){
        float wv = wr[H_+k];
#pragma unroll
        for (int b = 0; b < 8; b++) acc[b] += wv*sh[b*H_+k];
    }
#pragma unroll
    for (int b = 0; b < 8; b++) acc[b] = wsum(acc[b]);
    if (lane == 0){
        float cb = comb_b[j];
        for (int b = 0; b < 8; b++) g_outv[b*H_+j] = fmaxf(0.f, acc[b] + cb);
    }
}

__global__ void dk4_k(const float* __restrict__ Wih, const float* __restrict__ Whh,
                      const float* __restrict__ bih, const float* __restrict__ bhh, int s)
{
    __shared__ float sh[B_*H_];
    int pp = s & 1;
    const float* hIn = g_h[pp];
    float* hOut = g_h[pp ^ 1];
    int tid = threadIdx.x;
    int w = tid >> 5, lane = tid & 31;
    int j = blockIdx.x*8 + w;
    float a0[8]={0},a1[8]={0},a2[8]={0},a3[8]={0};
    for (int i = tid; i < B_*H_; i += 256) sh[i] = g_outv[i];
    __syncthreads();
    {
        const float *w0=Wih+(long)j*H_, *w1=Wih+(long)(H_+j)*H_;
        const float *w2=Wih+(long)(2*H_+j)*H_, *w3=Wih+(long)(3*H_+j)*H_;
        for (int k = lane; k < H_; k += 32){
            float x0=w0[k],x1=w1[k],x2=w2[k],x3=w3[k];
#pragma unroll
            for (int b = 0; b < 8; b++){
                float hv = sh[b*H_+k];
                a0[b]+=x0*hv; a1[b]+=x1*hv; a2[b]+=x2*hv; a3[b]+=x3*hv;
            }
        }
    }
    __syncthreads();
    for (int i = tid; i < B_*H_; i += 256) sh[i] = hIn[i];
    __syncthreads();
    {
        const float *w0=Whh+(long)j*H_, *w1=Whh+(long)(H_+j)*H_;
        const float *w2=Whh+(long)(2*H_+j)*H_, *w3=Whh+(long)(3*H_+j)*H_;
        for (int k = lane; k < H_; k += 32){
            float x0=w0[k],x1=w1[k],x2=w2[k],x3=w3[k];
#pragma unroll
            for (int b = 0; b < 8; b++){
                float hv = sh[b*H_+k];
                a0[b]+=x0*hv; a1[b]+=x1*hv; a2[b]+=x2*hv; a3[b]+=x3*hv;
            }
        }
    }
#pragma unroll
    for (int b = 0; b < 8; b++){
        a0[b]=wsum(a0[b]); a1[b]=wsum(a1[b]); a2[b]=wsum(a2[b]); a3[b]=wsum(a3[b]);
    }
    if (lane == 0){
        float bi0=bih[j]+bhh[j], bi1=bih[H_+j]+bhh[H_+j];
        float bi2=bih[2*H_+j]+bhh[2*H_+j], bi3=bih[3*H_+j]+bhh[3*H_+j];
#pragma unroll
        for (int b = 0; b < 8; b++){
            float ig = sigf (a0[b]+bi0);
            float fg = sigf (a1[b]+bi1);
            float gg = tanhf(a2[b]+bi2);
            float og = sigf (a3[b]+bi3);
            float c = fg*g_c[b*H_+j] + ig*gg;
            g_c[b*H_+j] = c;
            float h = og*tanhf(c);
            hOut[b*H_+j] = h;
            g_Hs[((long)s*B_ + b)*H_ + j] = h;
        }
    }
}

extern "C" void kernel_launch(void* const* d_in, const int* in_sizes, int n_in,
                              void* d_out, int out_size)
{
    int off = (in_sizes[1] == 1) ? 1 : 0;
    const float* input    = (const float*)d_in[0];
    const float* noise1   = (const float*)d_in[1+off];
    const float* noise2   = (const float*)d_in[2+off];
    const float* init_dec = (const float*)d_in[3+off];
    const float* enc_Wih  = (const float*)d_in[4+off];
    const float* enc_Whh  = (const float*)d_in[5+off];
    const float* enc_bih  = (const float*)d_in[6+off];
    const float* enc_bhh  = (const float*)d_in[7+off];
    const float* dec_Wih  = (const float*)d_in[8+off];
    const float* dec_Whh  = (const float*)d_in[9+off];
    const float* dec_bih  = (const float*)d_in[10+off];
    const float* dec_bhh  = (const float*)d_in[11+off];
    const float* emb_W    = (const float*)d_in[12+off];
    const float* emb_b    = (const float*)d_in[13+off];
    const float* attn_W   = (const float*)d_in[14+off];
    const float* attn_b   = (const float*)d_in[15+off];
    const float* comb_W   = (const float*)d_in[16+off];
    const float* comb_b   = (const float*)d_in[17+off];
    const float* out_W    = (const float*)d_in[18+off];
    const float* out_b    = (const float*)d_in[19+off];
    float* out = (float*)d_out;

    float *p_gx, *p_M, *p_Mp, *p_n1, *p_n1p, *p_n2, *p_Hs;
    cudaGetSymbolAddress((void**)&p_gx,  g_encGX);
    cudaGetSymbolAddress((void**)&p_M,   g_M);
    cudaGetSymbolAddress((void**)&p_Mp,  g_Mp);
    cudaGetSymbolAddress((void**)&p_n1,  g_n1);
    cudaGetSymbolAddress((void**)&p_n1p, g_n1p);
    cudaGetSymbolAddress((void**)&p_n2,  g_n2);
    cudaGetSymbolAddress((void**)&p_Hs,  g_Hs);
    __nv_bfloat16 *inpH,*inpL,*wihH,*wihL,*embEH,*embEL,*embNH,*embNL;
    __nv_bfloat16 *oWTH,*oWTL,*oWH,*oWL,*nzH,*nzL,*HsH,*HsL;
    cudaGetSymbolAddress((void**)&inpH, g_inpH);   cudaGetSymbolAddress((void**)&inpL, g_inpL);
    cudaGetSymbolAddress((void**)&wihH, g_wihH);   cudaGetSymbolAddress((void**)&wihL, g_wihL);
    cudaGetSymbolAddress((void**)&embEH, g_embEH); cudaGetSymbolAddress((void**)&embEL, g_embEL);
    cudaGetSymbolAddress((void**)&embNH, g_embNH); cudaGetSymbolAddress((void**)&embNL, g_embNL);
    cudaGetSymbolAddress((void**)&oWTH, g_oWTH);   cudaGetSymbolAddress((void**)&oWTL, g_oWTL);
    cudaGetSymbolAddress((void**)&oWH, g_oWH);     cudaGetSymbolAddress((void**)&oWL, g_oWL);
    cudaGetSymbolAddress((void**)&nzH, g_nzH);     cudaGetSymbolAddress((void**)&nzL, g_nzL);
    cudaGetSymbolAddress((void**)&HsH, g_HsH);     cudaGetSymbolAddress((void**)&HsL, g_HsL);

    cudaFuncSetAttribute(mma_gemm, cudaFuncAttributeMaxDynamicSharedMemorySize, SMEM_B);

    pack_inp_k<<<1024,256>>>(input, inpH, inpL);
    pack_rows_k<<<4096,256>>>(enc_Wih, E_, 0, G4H_, E_, NT_E, wihH, wihL);
    pack_rows_k<<<1024,256>>>(emb_W, EPNZ_, 0, H_, E_, NT_E, embEH, embEL);

    // G1: enc_gx [1024, 4000]
    mma_gemm<<<dim3(32, 8, 1), 256, SMEM_B>>>(inpH, inpL, wihH, wihL,
        p_gx, enc_bih, enc_bhh, T_*B_, G4H_, NT_E, G4H_);

    pack_rows_k<<<1024,256>>>(emb_W, EPNZ_, E_, H_, NZ_, NT_NZ, embNH, embNL);
    pack_tr_k<<<dim3(NT_E, 32), dim3(32,8)>>>(out_W, oWTH, oWTL);
    pack_rows_k<<<239*128,256>>>(out_W, H_, 0, E_, H_, NT_H, oWH, oWL);
    pack_rows_k<<<512,256>>>(noise1, NZ_, 0, S_*B_, NZ_, NT_NZ, nzH, nzL);

    // G2: M [1000,1000], K-split x4 -> partials + reduce (256 CTAs)
    mma_gemm<<<dim3(8, 8, 4), 256, SMEM_B>>>(embEH, embEL, oWTH, oWTL,
        p_Mp, 0, 0, H_, H_, NT_E, H_);
    reduce_z<<<(H_*H_+255)/256,256>>>(p_Mp, p_M, 4, H_*H_);

    // G3: n1emb [512, 1000], K-split x4 -> partials + reduce (128 CTAs)
    mma_gemm<<<dim3(8, 4, 4), 256, SMEM_B>>>(nzH, nzL, embNH, embNL,
        p_n1p, 0, 0, S_*B_, H_, NT_NZ, H_);
    reduce_z<<<(S_*B_*H_+255)/256,256>>>(p_n1p, p_n1, 4, S_*B_*H_);

    vvec_k<<<H_,256>>>(emb_W, out_b, emb_b);
    sgemm_nt<<<dim3(1,4),256>>>(noise2, attn_W, p_n2, attn_b,
        S_*B_, T_, H_, H_, 3*H_, 2*H_, T_);
    skinny_k<<<H_/8,256>>>(init_dec, emb_W);
    zero_k<<<32,256>>>();

    for (int t = 0; t < T_; t++)
        enc_step_k<<<H_/8,256>>>(enc_Whh, t);

    for (int s = 0; s < S_; s++){
        if (s == 0) emb0_k<<<32,256>>>(emb_b);
        else        dk1_k<<<H_/8,256>>>(s);
        dk2_k<<<B_,256>>>(attn_W, s);
        dk3_k<<<H_/8,256>>>(comb_W, comb_b);
        dk4_k<<<H_/8,256>>>(dec_Wih, dec_Whh, dec_bih, dec_bhh, s);
    }

    // G4: summary [512, E]
    pack_rows_k<<<512,256>>>(p_Hs, H_, 0, S_*B_, H_, NT_H, HsH, HsL);
    mma_gemm<<<dim3(239, 4, 1), 256, SMEM_B>>>(HsH, HsL, oWH, oWL,
        out, out_b, 0, S_*B_, E_, NT_H, E_);
}

// round 13
// speedup vs baseline: 1.4816x; 1.1466x over previous
#include <cuda_runtime.h>
#include <cuda_fp16.h>
#include <math.h>
#include <stdint.h>

#define B_ 8
#define T_ 128
#define E_ 30522
#define H_ 1000
#define S_ 64
#define NZ_ 10000
#define EPNZ_ 40522
#define G4H_ (4*H_)
#define KP_ 30528
#define NZP_ 10016
#define HP_ 1024
#define NT_E (KP_/32)    // 954
#define NT_NZ (NZP_/32)  // 313
#define NT_H (HP_/32)    // 32

// ---------------- fp32 scratch ----------------
__device__ float g_encGX[(size_t)T_*B_*G4H_];
__device__ float g_M[(size_t)H_*H_];
__device__ float g_Mp[(size_t)4*H_*H_];
__device__ float g_n1[(size_t)S_*B_*H_];
__device__ float g_n1p[(size_t)4*S_*B_*H_];
__device__ float g_n2[(size_t)S_*B_*T_];
__device__ float g_emb0[B_*H_];
__device__ float g_v2[H_];
__device__ float g_encBTH[(size_t)B_*T_*H_];
__device__ float g_h[2][B_*H_];
__device__ float g_c[B_*H_];
__device__ float g_emb[B_*H_];
__device__ float g_app[B_*H_];
__device__ float g_outv[B_*H_];
__device__ float g_Hs[(size_t)S_*B_*H_];

// ---------------- packed fp16 operands (tile = 128x32 halves = 8KB, swizzled) ----
__device__ __half g_inpH[(size_t)8*NT_E*4096];
__device__ __half g_wihH[(size_t)32*NT_E*4096];
__device__ __half g_embEH[(size_t)8*NT_E*4096];
__device__ __half g_embNH[(size_t)8*NT_NZ*4096];
__device__ __half g_oWTH[(size_t)8*NT_E*4096];
__device__ __half g_oWH[(size_t)239*NT_H*4096];
__device__ __half g_nzH[(size_t)4*NT_NZ*4096];
__device__ __half g_HsH[(size_t)4*NT_H*4096];

__device__ __forceinline__ float wsum(float v){
#pragma unroll
    for (int o = 16; o; o >>= 1) v += __shfl_xor_sync(0xffffffffu, v, o);
    return v;
}
__device__ __forceinline__ float sigf(float x){ return 1.f/(1.f+expf(-x)); }

__device__ __forceinline__ uint32_t smem_u32(const void* p){
    uint32_t a;
    asm("{ .reg .u64 t; cvta.to.shared.u64 t, %1; cvt.u32.u64 %0, t; }" : "=r"(a) : "l"(p));
    return a;
}
__device__ __forceinline__ void ldsm4(uint32_t* r, uint32_t a){
    asm volatile("ldmatrix.sync.aligned.m8n8.x4.shared.b16 {%0,%1,%2,%3}, [%4];"
        : "=r"(r[0]),"=r"(r[1]),"=r"(r[2]),"=r"(r[3]) : "r"(a));
}
__device__ __forceinline__ void mma16816h(float* c, const uint32_t* a,
                                          uint32_t b0, uint32_t b1){
    asm volatile("mma.sync.aligned.m16n8k16.row.col.f32.f16.f16.f32 "
        "{%0,%1,%2,%3}, {%4,%5,%6,%7}, {%8,%9}, {%0,%1,%2,%3};"
        : "+f"(c[0]),"+f"(c[1]),"+f"(c[2]),"+f"(c[3])
        : "r"(a[0]),"r"(a[1]),"r"(a[2]),"r"(a[3]), "r"(b0),"r"(b1));
}
#define MB_INIT(mb, c)  asm volatile("mbarrier.init.shared.b64 [%0], %1;" :: "r"((uint32_t)(mb)), "r"((uint32_t)(c)) : "memory")
#define MB_EXPECT(mb, n) asm volatile("mbarrier.arrive.expect_tx.shared.b64 _, [%0], %1;" :: "r"((uint32_t)(mb)), "r"((uint32_t)(n)) : "memory")
#define MB_WAIT(mb, ph) do { \
    uint32_t _m=(uint32_t)(mb), _p=(uint32_t)(ph), _d; \
    asm volatile("{\n\t.reg .pred p;\n\tmbarrier.try_wait.parity.shared.b64 p, [%1], %2;\n\tselp.b32 %0, 1, 0, p;\n\t}" \
        : "=r"(_d) : "r"(_m), "r"(_p) : "memory"); \
    if (!_d){ \
        asm volatile("{\n\t.reg .pred P1;\n\tWL_%=:\n\tmbarrier.try_wait.parity.shared.b64 P1, [%0], %1;\n\t@P1 bra.uni WD_%=;\n\tbra.uni WL_%=;\n\tWD_%=:\n\t}" \
            :: "r"(_m), "r"(_p) : "memory"); \
    } } while(0)
__device__ __forceinline__ void bulk_cp(uint32_t dst, const void* src, uint32_t sz, uint32_t mb){
    asm volatile("cp.async.bulk.shared::cta.global.mbarrier::complete_tx::bytes [%0], [%1], %2, [%3];"
        :: "r"(dst), "l"(src), "r"(sz), "r"(mb) : "memory");
}

#define STG_B 16384    // 2 arrays x 8192B
#define SMEM_B (2*STG_B)

// ---------------- packed fp16 HMMA NT GEMM: C = A@B^T (+bias) ----------------
// grid.z = K-split: partial z writes C + z*M*ldc; bias applied only on z==0.
__global__ __launch_bounds__(256,2)
void mma_gemm(const __half* __restrict__ Ah, const __half* __restrict__ Bh,
              float* __restrict__ C, const float* __restrict__ bias0,
              const float* __restrict__ bias1,
              int M, int N, int NT, int ldc)
{
    extern __shared__ char smem[];
    __shared__ __align__(8) uint64_t mbar[2];
    uint32_t sb = smem_u32(smem);
    uint32_t mba = smem_u32(mbar);
    const int tid = threadIdx.x, lane = tid & 31, wid = tid >> 5;
    const int pa = blockIdx.y, pb = blockIdx.x;
    const int row0 = pa*128, col0 = pb*128;
    const int wm = wid >> 2, wn = wid & 3;

    const int zc = gridDim.z, z = blockIdx.z;
    const int chunk = (NT + zc - 1)/zc;
    const int kb = z*chunk;
    const int ke = min(NT, kb + chunk);
    float* Cz = C + (size_t)z*M*ldc;
    const bool addB = (z == 0);

    if (tid == 0){ MB_INIT(mba, 1); MB_INIT(mba+8, 1); }
    __syncthreads();

    float c[4][4][4];
#pragma unroll
    for (int i = 0; i < 4; i++)
#pragma unroll
        for (int j = 0; j < 4; j++)
#pragma unroll
            for (int q = 0; q < 4; q++) c[i][j][q] = 0.f;

    auto load = [&](int kt, int stg){
        if (tid == 0){
            uint32_t mb = mba + stg*8;
            MB_EXPECT(mb, STG_B);
            uint32_t d = sb + stg*STG_B;
            bulk_cp(d,         Ah + ((size_t)pa*NT + kt)*4096, 8192, mb);
            bulk_cp(d + 8192,  Bh + ((size_t)pb*NT + kt)*4096, 8192, mb);
        }
    };

    int ph[2] = {0, 0};
    load(kb, 0);
    for (int kt = kb; kt < ke; kt++){
        int cur = (kt - kb) & 1;
        if (kt + 1 < ke) load(kt+1, cur ^ 1);
        MB_WAIT(mba + cur*8, ph[cur]); ph[cur] ^= 1;
        __syncthreads();

        uint32_t sbase = sb + cur*STG_B;
#pragma unroll
        for (int ks = 0; ks < 2; ks++){
            uint32_t bh[2][4];
#pragma unroll
            for (int nj = 0; nj < 2; nj++){
                uint32_t rb = (uint32_t)(wn*32 + nj*16 + (lane & 15));
                uint32_t c4 = (uint32_t)(ks*2 + (lane >> 4)) ^ ((rb >> 1) & 3);
                uint32_t ab = sbase + 8192 + rb*64 + c4*16;
                ldsm4(bh[nj], ab);
            }
#pragma unroll
            for (int mi = 0; mi < 4; mi++){
                uint32_t ra = (uint32_t)(wm*64 + mi*16 + (lane & 15));
                uint32_t c4 = (uint32_t)(ks*2 + (lane >> 4)) ^ ((ra >> 1) & 3);
                uint32_t aa = sbase + ra*64 + c4*16;
                uint32_t a4[4];
                ldsm4(a4, aa);
#pragma unroll
                for (int nf = 0; nf < 4; nf++){
                    int nj = nf >> 1, s = nf & 1;
                    mma16816h(c[mi][nf], a4, bh[nj][s], bh[nj][2+s]);
                }
            }
        }
        __syncthreads();
    }

#pragma unroll
    for (int mi = 0; mi < 4; mi++){
#pragma unroll
        for (int nf = 0; nf < 4; nf++){
            int gr = row0 + wm*64 + mi*16 + (lane >> 2);
            int gc = col0 + wn*32 + nf*8 + (lane & 3)*2;
#pragma unroll
            for (int q = 0; q < 4; q++){
                int rr = gr + (q >> 1)*8;
                int cc = gc + (q & 1);
                if (rr < M && cc < N){
                    float v = c[mi][nf][q];
                    if (addB){
                        if (bias0) v += bias0[cc];
                        if (bias1) v += bias1[cc];
                    }
                    Cz[(size_t)rr*ldc + cc] = v;
                }
            }
        }
    }
}

__global__ void reduce_z(const float* __restrict__ in, float* __restrict__ out,
                         int zc, int mn)
{
    int i = blockIdx.x*256 + threadIdx.x;
    if (i >= mn) return;
    float s = 0.f;
    for (int z = 0; z < zc; z++) s += in[(size_t)z*mn + i];
    out[i] = s;
}

// ---------------- pack kernels (fp32 -> swizzled packed fp16) ----------------
__global__ void pack_rows_k(const float* __restrict__ src, long srcLd, int colOff,
                            int Rr, int Kr, int NT, __half* __restrict__ hi)
{
    int r = blockIdx.x;
    int p = r >> 7, pr = r & 127;
    size_t pbase = ((size_t)p*NT)*4096 + (size_t)pr*32;
    const float* s = src + (size_t)r*srcLd + colOff;
    int Kp = NT*32;
    bool rok = (r < Rr);
    int sw = (pr >> 1) & 3;
    for (int k = threadIdx.x; k < Kp; k += 256){
        int kt = k >> 5, kc = k & 31;
        size_t off = pbase + (size_t)kt*4096 + (size_t)(((kc>>3) ^ sw)*8 + (kc&7));
        float x = (rok && k < Kr) ? s[k] : 0.f;
        hi[off] = __float2half(x);
    }
}

__global__ void pack_inp_k(const float* __restrict__ inp, __half* __restrict__ hi)
{
    int r = blockIdx.x;
    int t = r / B_, b = r % B_;
    int p = r >> 7, pr = r & 127;
    size_t pbase = ((size_t)p*NT_E)*4096 + (size_t)pr*32;
    const float* s = inp + ((size_t)b*T_ + t)*E_;
    int sw = (pr >> 1) & 3;
    for (int k = threadIdx.x; k < KP_; k += 256){
        int kt = k >> 5, kc = k & 31;
        size_t off = pbase + (size_t)kt*4096 + (size_t)(((kc>>3) ^ sw)*8 + (kc&7));
        float x = (k < E_) ? s[k] : 0.f;
        hi[off] = __float2half(x);
    }
}

__global__ void pack_tr_k(const float* __restrict__ src, __half* __restrict__ hi)
{
    __shared__ float t[32][33];
    int e0 = blockIdx.x*32, j0 = blockIdx.y*32;
    for (int i = threadIdx.y; i < 32; i += 8){
        int e = e0+i, j = j0+threadIdx.x;
        t[i][threadIdx.x] = (e < E_ && j < H_) ? src[(size_t)e*H_ + j] : 0.f;
    }
    __syncthreads();
    for (int i = threadIdx.y; i < 32; i += 8){
        int j = j0+i;
        int e = e0+threadIdx.x;
        int p = j >> 7, pr = j & 127;
        int kt = e >> 5, kc = e & 31;
        size_t off = ((size_t)p*NT_E + kt)*4096 + (size_t)pr*32
                   + (size_t)((((kc>>3) ^ ((pr>>1)&3))*8) + (kc&7));
        hi[off] = __float2half(t[threadIdx.x][i]);
    }
}

// ---------------- small SIMT GEMM for n2attn ----------------
__global__ __launch_bounds__(256,2)
void sgemm_nt(const float* __restrict__ A, const float* __restrict__ Bm,
              float* __restrict__ C,
              const float* __restrict__ bias0,
              int M, int N, int K, int lda, int ldb, int bColOff, int ldc)
{
    __shared__ float As[16][132];
    __shared__ float Bs[16][132];
    const int row0 = blockIdx.y*128, col0 = blockIdx.x*128;
    const int tid = threadIdx.x;
    const int tx = tid & 15, ty = tid >> 4;
    const int lk = tid & 15, lr0 = tid >> 4;
    long aOff[8]; int aOk[8]; long bOff[8]; int bOk[8];
#pragma unroll
    for (int i = 0; i < 8; i++){
        int gr = row0 + lr0 + i*16;
        aOk[i] = (gr < M); aOff[i] = (long)(aOk[i] ? gr : 0)*lda;
        int gc = col0 + lr0 + i*16;
        bOk[i] = (gc < N); bOff[i] = (long)(bOk[i] ? gc : 0)*ldb + bColOff;
    }
    float acc[8][8];
#pragma unroll
    for (int i = 0; i < 8; i++)
#pragma unroll
        for (int j = 0; j < 8; j++) acc[i][j] = 0.f;
    for (int k0 = 0; k0 < K; k0 += 16){
        int gk = k0 + lk; bool kOk = (gk < K);
#pragma unroll
        for (int i = 0; i < 8; i++){
            As[lk][lr0+i*16] = (kOk && aOk[i]) ? A[aOff[i]+gk] : 0.f;
            Bs[lk][lr0+i*16] = (kOk && bOk[i]) ? Bm[bOff[i]+gk] : 0.f;
        }
        __syncthreads();
#pragma unroll
        for (int kk = 0; kk < 16; kk++){
            float4 a0 = *(const float4*)&As[kk][ty*8];
            float4 a1 = *(const float4*)&As[kk][ty*8+4];
            float4 b0 = *(const float4*)&Bs[kk][tx*8];
            float4 b1 = *(const float4*)&Bs[kk][tx*8+4];
            float a[8] = {a0.x,a0.y,a0.z,a0.w,a1.x,a1.y,a1.z,a1.w};
            float b[8] = {b0.x,b0.y,b0.z,b0.w,b1.x,b1.y,b1.z,b1.w};
#pragma unroll
            for (int i = 0; i < 8; i++)
#pragma unroll
                for (int j = 0; j < 8; j++) acc[i][j] += a[i]*b[j];
        }
        __syncthreads();
    }
#pragma unroll
    for (int i = 0; i < 8; i++){
        int gr = row0 + ty*8 + i;
        if (gr >= M) continue;
#pragma unroll
        for (int j = 0; j < 8; j++){
            int gc = col0 + tx*8 + j;
            if (gc >= N) continue;
            float v = acc[i][j];
            if (bias0) v += bias0[gc];
            C[(long)gr*ldc + gc] = v;
        }
    }
}

__global__ void skinny_k(const float* __restrict__ A, const float* __restrict__ Bm)
{
    __shared__ float Ash[8*1024];
    int w = threadIdx.x >> 5, lane = threadIdx.x & 31;
    int j = blockIdx.x*8 + w;
    float acc[8] = {0,0,0,0,0,0,0,0};
    for (int k0 = 0; k0 < E_; k0 += 1024){
        int kc = min(1024, E_ - k0);
        __syncthreads();
        for (int idx = threadIdx.x; idx < 8192; idx += 256){
            int r = idx >> 10, k = idx & 1023;
            Ash[idx] = (k < kc) ? A[(long)r*E_ + k0 + k] : 0.f;
        }
        __syncthreads();
        if (j < H_){
            const float* br = Bm + (long)j*EPNZ_ + k0;
            for (int k = lane; k < kc; k += 32){
                float wv = br[k];
#pragma unroll
                for (int b = 0; b < 8; b++) acc[b] += wv*Ash[b*1024 + k];
            }
        }
    }
    if (j < H_){
#pragma unroll
        for (int b = 0; b < 8; b++) acc[b] = wsum(acc[b]);
        if (lane == 0)
            for (int b = 0; b < 8; b++) g_emb0[b*H_ + j] = acc[b];
    }
}

__global__ void vvec_k(const float* __restrict__ embW, const float* __restrict__ out_b,
                       const float* __restrict__ emb_b)
{
    __shared__ float red[256];
    int j = blockIdx.x;
    float s = 0.f;
    for (int k = threadIdx.x; k < E_; k += 256) s += embW[(long)j*EPNZ_ + k]*out_b[k];
    red[threadIdx.x] = s; __syncthreads();
    for (int o = 128; o; o >>= 1){
        if (threadIdx.x < o) red[threadIdx.x] += red[threadIdx.x+o];
        __syncthreads();
    }
    if (threadIdx.x == 0) g_v2[j] = red[0] + emb_b[j];
}

__global__ void zero_k(){
    int i = blockIdx.x*256 + threadIdx.x;
    if (i < B_*H_){ g_h[0][i] = 0.f; g_c[i] = 0.f; }
}

__global__ void enc_step_k(const float* __restrict__ Whh, int t)
{
    __shared__ float hs[B_*H_];
    const float* hIn = g_h[t & 1];
    float* hOut = g_h[(t & 1) ^ 1];
    const float* gx = g_encGX + (long)t*B_*G4H_;
    int tid = threadIdx.x;
    for (int i = tid; i < B_*H_; i += 256) hs[i] = hIn[i];
    __syncthreads();
    int w = tid >> 5, lane = tid & 31;
    int j = blockIdx.x*8 + w;
    const float *w0 = Whh+(long)j*H_, *w1 = Whh+(long)(H_+j)*H_;
    const float *w2 = Whh+(long)(2*H_+j)*H_, *w3 = Whh+(long)(3*H_+j)*H_;
    float a0[8]={0},a1[8]={0},a2[8]={0},a3[8]={0};
    for (int k = lane; k < H_; k += 32){
        float x0=w0[k],x1=w1[k],x2=w2[k],x3=w3[k];
#pragma unroll
        for (int b = 0; b < 8; b++){
            float hv = hs[b*H_+k];
            a0[b]+=x0*hv; a1[b]+=x1*hv; a2[b]+=x2*hv; a3[b]+=x3*hv;
        }
    }
#pragma unroll
    for (int b = 0; b < 8; b++){
        a0[b]=wsum(a0[b]); a1[b]=wsum(a1[b]); a2[b]=wsum(a2[b]); a3[b]=wsum(a3[b]);
    }
    if (lane == 0){
#pragma unroll
        for (int b = 0; b < 8; b++){
            const float* gr = gx + (long)b*G4H_;
            float ig = sigf (gr[j]       + a0[b]);
            float fg = sigf (gr[H_+j]    + a1[b]);
            float gg = tanhf(gr[2*H_+j]  + a2[b]);
            float og = sigf (gr[3*H_+j]  + a3[b]);
            float c = fg*g_c[b*H_+j] + ig*gg;
            g_c[b*H_+j] = c;
            float h = og*tanhf(c);
            hOut[b*H_+j] = h;
            g_encBTH[((long)b*T_ + t)*H_ + j] = h;
        }
    }
}

__global__ void emb0_k(const float* __restrict__ emb_b)
{
    int i = blockIdx.x*256 + threadIdx.x;
    if (i < B_*H_) g_emb[i] = g_emb0[i] + g_n1[i] + emb_b[i % H_];
}

__global__ void dk1_k(int s)
{
    __shared__ float hs[B_*H_];
    const float* hIn = g_h[s & 1];
    const float* n1 = g_n1 + (long)s*B_*H_;
    int tid = threadIdx.x;
    for (int i = tid; i < B_*H_; i += 256) hs[i] = hIn[i];
    __syncthreads();
    int w = tid >> 5, lane = tid & 31;
    int j = blockIdx.x*8 + w;
    const float* mr = g_M + (long)j*H_;
    float acc[8]={0,0,0,0,0,0,0,0};
    for (int k = lane; k < H_; k += 32){
        float mv = mr[k];
#pragma unroll
        for (int b = 0; b < 8; b++) acc[b] += mv*hs[b*H_+k];
    }
#pragma unroll
    for (int b = 0; b < 8; b++) acc[b] = wsum(acc[b]);
    if (lane == 0){
        float vb = g_v2[j];
        for (int b = 0; b < 8; b++) g_emb[b*H_+j] = acc[b] + n1[b*H_+j] + vb;
    }
}

__global__ void dk2_k(const float* __restrict__ attW, int s)
{
    __shared__ float xs[2*H_];
    __shared__ float lg[T_];
    __shared__ float ps[T_];
    int b = blockIdx.x, tid = threadIdx.x;
    const float* hIn = g_h[s & 1];
    const float* n2 = g_n2 + (long)s*B_*T_;
    for (int i = tid; i < H_; i += 256){ xs[i] = g_emb[b*H_+i]; xs[H_+i] = hIn[b*H_+i]; }
    __syncthreads();
    int w = tid >> 5, lane = tid & 31;
    for (int ti = 0; ti < 16; ti++){
        int t = w*16 + ti;
        const float* wr = attW + (long)t*3*H_;
        float sv = 0.f;
        for (int k = lane; k < 2*H_; k += 32) sv += wr[k]*xs[k];
        sv = wsum(sv);
        if (lane == 0) lg[t] = sv + n2[b*T_+t];
    }
    __syncthreads();
    if (w == 0){
        float m = -1e30f;
        for (int i = lane; i < T_; i += 32) m = fmaxf(m, lg[i]);
#pragma unroll
        for (int o = 16; o; o >>= 1) m = fmaxf(m, __shfl_xor_sync(0xffffffffu, m, o));
        float ss = 0.f;
        for (int i = lane; i < T_; i += 32){ float e = expf(lg[i]-m); ps[i] = e; ss += e; }
        ss = wsum(ss);
        float inv = 1.f/ss;
        for (int i = lane; i < T_; i += 32) ps[i] *= inv;
    }
    __syncthreads();
    for (int j = tid; j < H_; j += 256){
        float sv = 0.f;
        const float* eb = g_encBTH + (long)b*T_*H_ + j;
#pragma unroll 4
        for (int t = 0; t < T_; t++) sv += ps[t]*eb[(long)t*H_];
        g_app[b*H_+j] = sv;
    }
}

__global__ void dk3_k(const float* __restrict__ combW, const float* __restrict__ comb_b)
{
    __shared__ float sh[B_*H_];
    int tid = threadIdx.x;
    int w = tid >> 5, lane = tid & 31;
    int j = blockIdx.x*8 + w;
    const float* wr = combW + (long)j*2*H_;
    float acc[8]={0,0,0,0,0,0,0,0};
    for (int i = tid; i < B_*H_; i += 256) sh[i] = g_emb[i];
    __syncthreads();
    for (int k = lane; k < H_; k += 32){
        float wv = wr[k];
#pragma unroll
        for (int b = 0; b < 8; b++) acc[b] += wv*sh[b*H_+k];
    }
    __syncthreads();
    for (int i = tid; i < B_*H_; i += 256) sh[i] = g_app[i];
    __syncthreads();
    for (int k = lane; k < H_; k += 32){
        float wv = wr[H_+k];
#pragma unroll
        for (int b = 0; b < 8; b++) acc[b] += wv*sh[b*H_+k];
    }
#pragma unroll
    for (int b = 0; b < 8; b++) acc[b] = wsum(acc[b]);
    if (lane == 0){
        float cb = comb_b[j];
        for (int b = 0; b < 8; b++) g_outv[b*H_+j] = fmaxf(0.f, acc[b] + cb);
    }
}

__global__ void dk4_k(const float* __restrict__ Wih, const float* __restrict__ Whh,
                      const float* __restrict__ bih, const float* __restrict__ bhh, int s)
{
    __shared__ float sh[B_*H_];
    int pp = s & 1;
    const float* hIn = g_h[pp];
    float* hOut = g_h[pp ^ 1];
    int tid = threadIdx.x;
    int w = tid >> 5, lane = tid & 31;
    int j = blockIdx.x*8 + w;
    float a0[8]={0},a1[8]={0},a2[8]={0},a3[8]={0};
    for (int i = tid; i < B_*H_; i += 256) sh[i] = g_outv[i];
    __syncthreads();
    {
        const float *w0=Wih+(long)j*H_, *w1=Wih+(long)(H_+j)*H_;
        const float *w2=Wih+(long)(2*H_+j)*H_, *w3=Wih+(long)(3*H_+j)*H_;
        for (int k = lane; k < H_; k += 32){
            float x0=w0[k],x1=w1[k],x2=w2[k],x3=w3[k];
#pragma unroll
            for (int b = 0; b < 8; b++){
                float hv = sh[b*H_+k];
                a0[b]+=x0*hv; a1[b]+=x1*hv; a2[b]+=x2*hv; a3[b]+=x3*hv;
            }
        }
    }
    __syncthreads();
    for (int i = tid; i < B_*H_; i += 256) sh[i] = hIn[i];
    __syncthreads();
    {
        const float *w0=Whh+(long)j*H_, *w1=Whh+(long)(H_+j)*H_;
        const float *w2=Whh+(long)(2*H_+j)*H_, *w3=Whh+(long)(3*H_+j)*H_;
        for (int k = lane; k < H_; k += 32){
            float x0=w0[k],x1=w1[k],x2=w2[k],x3=w3[k];
#pragma unroll
            for (int b = 0; b < 8; b++){
                float hv = sh[b*H_+k];
                a0[b]+=x0*hv; a1[b]+=x1*hv; a2[b]+=x2*hv; a3[b]+=x3*hv;
            }
        }
    }
#pragma unroll
    for (int b = 0; b < 8; b++){
        a0[b]=wsum(a0[b]); a1[b]=wsum(a1[b]); a2[b]=wsum(a2[b]); a3[b]=wsum(a3[b]);
    }
    if (lane == 0){
        float bi0=bih[j]+bhh[j], bi1=bih[H_+j]+bhh[H_+j];
        float bi2=bih[2*H_+j]+bhh[2*H_+j], bi3=bih[3*H_+j]+bhh[3*H_+j];
#pragma unroll
        for (int b = 0; b < 8; b++){
            float ig = sigf (a0[b]+bi0);
            float fg = sigf (a1[b]+bi1);
            float gg = tanhf(a2[b]+bi2);
            float og = sigf (a3[b]+bi3);
            float c = fg*g_c[b*H_+j] + ig*gg;
            g_c[b*H_+j] = c;
            float h = og*tanhf(c);
            hOut[b*H_+j] = h;
            g_Hs[((long)s*B_ + b)*H_ + j] = h;
        }
    }
}

extern "C" void kernel_launch(void* const* d_in, const int* in_sizes, int n_in,
                              void* d_out, int out_size)
{
    int off = (in_sizes[1] == 1) ? 1 : 0;
    const float* input    = (const float*)d_in[0];
    const float* noise1   = (const float*)d_in[1+off];
    const float* noise2   = (const float*)d_in[2+off];
    const float* init_dec = (const float*)d_in[3+off];
    const float* enc_Wih  = (const float*)d_in[4+off];
    const float* enc_Whh  = (const float*)d_in[5+off];
    const float* enc_bih  = (const float*)d_in[6+off];
    const float* enc_bhh  = (const float*)d_in[7+off];
    const float* dec_Wih  = (const float*)d_in[8+off];
    const float* dec_Whh  = (const float*)d_in[9+off];
    const float* dec_bih  = (const float*)d_in[10+off];
    const float* dec_bhh  = (const float*)d_in[11+off];
    const float* emb_W    = (const float*)d_in[12+off];
    const float* emb_b    = (const float*)d_in[13+off];
    const float* attn_W   = (const float*)d_in[14+off];
    const float* attn_b   = (const float*)d_in[15+off];
    const float* comb_W   = (const float*)d_in[16+off];
    const float* comb_b   = (const float*)d_in[17+off];
    const float* out_W    = (const float*)d_in[18+off];
    const float* out_b    = (const float*)d_in[19+off];
    float* out = (float*)d_out;

    float *p_gx, *p_M, *p_Mp, *p_n1, *p_n1p, *p_n2, *p_Hs;
    cudaGetSymbolAddress((void**)&p_gx,  g_encGX);
    cudaGetSymbolAddress((void**)&p_M,   g_M);
    cudaGetSymbolAddress((void**)&p_Mp,  g_Mp);
    cudaGetSymbolAddress((void**)&p_n1,  g_n1);
    cudaGetSymbolAddress((void**)&p_n1p, g_n1p);
    cudaGetSymbolAddress((void**)&p_n2,  g_n2);
    cudaGetSymbolAddress((void**)&p_Hs,  g_Hs);
    __half *inpH,*wihH,*embEH,*embNH,*oWTH,*oWH,*nzH,*HsH;
    cudaGetSymbolAddress((void**)&inpH, g_inpH);
    cudaGetSymbolAddress((void**)&wihH, g_wihH);
    cudaGetSymbolAddress((void**)&embEH, g_embEH);
    cudaGetSymbolAddress((void**)&embNH, g_embNH);
    cudaGetSymbolAddress((void**)&oWTH, g_oWTH);
    cudaGetSymbolAddress((void**)&oWH, g_oWH);
    cudaGetSymbolAddress((void**)&nzH, g_nzH);
    cudaGetSymbolAddress((void**)&HsH, g_HsH);

    cudaFuncSetAttribute(mma_gemm, cudaFuncAttributeMaxDynamicSharedMemorySize, SMEM_B);

    pack_inp_k<<<1024,256>>>(input, inpH);
    pack_rows_k<<<4096,256>>>(enc_Wih, E_, 0, G4H_, E_, NT_E, wihH);
    pack_rows_k<<<1024,256>>>(emb_W, EPNZ_, 0, H_, E_, NT_E, embEH);

    // G1: enc_gx [1024, 4000]
    mma_gemm<<<dim3(32, 8, 1), 256, SMEM_B>>>(inpH, wihH,
        p_gx, enc_bih, enc_bhh, T_*B_, G4H_, NT_E, G4H_);

    pack_rows_k<<<1024,256>>>(emb_W, EPNZ_, E_, H_, NZ_, NT_NZ, embNH);
    pack_tr_k<<<dim3(NT_E, 32), dim3(32,8)>>>(out_W, oWTH);
    pack_rows_k<<<239*128,256>>>(out_W, H_, 0, E_, H_, NT_H, oWH);
    pack_rows_k<<<512,256>>>(noise1, NZ_, 0, S_*B_, NZ_, NT_NZ, nzH);

    // G2: M [1000,1000], K-split x4
    mma_gemm<<<dim3(8, 8, 4), 256, SMEM_B>>>(embEH, oWTH,
        p_Mp, 0, 0, H_, H_, NT_E, H_);
    reduce_z<<<(H_*H_+255)/256,256>>>(p_Mp, p_M, 4, H_*H_);

    // G3: n1emb [512, 1000], K-split x4
    mma_gemm<<<dim3(8, 4, 4), 256, SMEM_B>>>(nzH, embNH,
        p_n1p, 0, 0, S_*B_, H_, NT_NZ, H_);
    reduce_z<<<(S_*B_*H_+255)/256,256>>>(p_n1p, p_n1, 4, S_*B_*H_);

    vvec_k<<<H_,256>>>(emb_W, out_b, emb_b);
    sgemm_nt<<<dim3(1,4),256>>>(noise2, attn_W, p_n2, attn_b,
        S_*B_, T_, H_, H_, 3*H_, 2*H_, T_);
    skinny_k<<<H_/8,256>>>(init_dec, emb_W);
    zero_k<<<32,256>>>();

    for (int t = 0; t < T_; t++)
        enc_step_k<<<H_/8,256>>>(enc_Whh, t);

    for (int s = 0; s < S_; s++){
        if (s == 0) emb0_k<<<32,256>>>(emb_b);
        else        dk1_k<<<H_/8,256>>>(s);
        dk2_k<<<B_,256>>>(attn_W, s);
        dk3_k<<<H_/8,256>>>(comb_W, comb_b);
        dk4_k<<<H_/8,256>>>(dec_Wih, dec_Whh, dec_bih, dec_bhh, s);
    }

    // G4: summary [512, E]
    pack_rows_k<<<512,256>>>(p_Hs, H_, 0, S_*B_, H_, NT_H, HsH);
    mma_gemm<<<dim3(239, 4, 1), 256, SMEM_B>>>(HsH, oWH,
        out, out_b, 0, S_*B_, E_, NT_H, E_);
}

// round 15
// speedup vs baseline: 1.5442x; 1.0423x over previous
#include <cuda_runtime.h>
#include <cuda_fp16.h>
#include <math.h>
#include <stdint.h>

#define B_ 8
#define T_ 128
#define E_ 30522
#define H_ 1000
#define S_ 64
#define NZ_ 10000
#define EPNZ_ 40522
#define G4H_ (4*H_)
#define KP_ 30528
#define NZP_ 10016
#define HP_ 1024
#define NT_E (KP_/32)    // 954
#define NT_NZ (NZP_/32)  // 313
#define NT_H (HP_/32)    // 32
#define NB_ 125

// ---------------- fp32 scratch ----------------
__device__ float g_encGX[(size_t)T_*B_*G4H_];
__device__ float g_M[(size_t)H_*H_];
__device__ float g_Mp[(size_t)4*H_*H_];
__device__ float g_n1[(size_t)S_*B_*H_];
__device__ float g_n1p[(size_t)4*S_*B_*H_];
__device__ float g_n2[(size_t)S_*B_*T_];
__device__ float g_emb0[B_*H_];
__device__ float g_v2[H_];
__device__ float g_encBTH[(size_t)B_*T_*H_];
__device__ float g_h[2][B_*H_];
__device__ float g_c[B_*H_];
__device__ float g_emb[B_*H_];
__device__ float g_app[B_*H_];
__device__ float g_outv[B_*H_];
__device__ float g_Hs[(size_t)S_*B_*H_];
__device__ unsigned g_bars[192];   // per-step barrier counters (encoder uses 128)

// ---------------- packed fp16 operands ----------------
__device__ __half g_inpH[(size_t)8*NT_E*4096];
__device__ __half g_wihH[(size_t)32*NT_E*4096];
__device__ __half g_embEH[(size_t)8*NT_E*4096];
__device__ __half g_embNH[(size_t)8*NT_NZ*4096];
__device__ __half g_oWTH[(size_t)8*NT_E*4096];
__device__ __half g_oWH[(size_t)239*NT_H*4096];
__device__ __half g_nzH[(size_t)4*NT_NZ*4096];
__device__ __half g_HsH[(size_t)4*NT_H*4096];

__device__ __forceinline__ float wsum(float v){
#pragma unroll
    for (int o = 16; o; o >>= 1) v += __shfl_xor_sync(0xffffffffu, v, o);
    return v;
}
__device__ __forceinline__ float sigf(float x){ return 1.f/(1.f+expf(-x)); }

// cross-block visibility helpers
__device__ __forceinline__ float ldv(const float* p){
    float v; asm volatile("ld.global.cv.f32 %0, [%1];" : "=f"(v) : "l"(p)); return v;
}
__device__ __forceinline__ void stg(float* p, float v){
    asm volatile("st.global.cg.f32 [%0], %1;" :: "l"(p), "f"(v) : "memory");
}

// per-index grid barrier: dedicated counter per barrier, release/acquire semantics.
// All NB_ blocks co-resident (125 <= 148 SMs, 1 block/SM).
__device__ __forceinline__ void gbar(int idx){
    __syncthreads();
    __threadfence();
    if (threadIdx.x == 0){
        unsigned pv;
        asm volatile("atom.release.gpu.global.add.u32 %0, [%1], %2;"
            : "=r"(pv) : "l"(&g_bars[idx]), "r"(1u) : "memory");
        unsigned v;
        do {
            asm volatile("ld.acquire.gpu.global.u32 %0, [%1];"
                : "=r"(v) : "l"(&g_bars[idx]) : "memory");
        } while (v < (unsigned)NB_);
    }
    __syncthreads();
}

__global__ void bar_reset(){
    if (threadIdx.x < 192) g_bars[threadIdx.x] = 0u;
}

__device__ __forceinline__ uint32_t smem_u32(const void* p){
    uint32_t a;
    asm("{ .reg .u64 t; cvta.to.shared.u64 t, %1; cvt.u32.u64 %0, t; }" : "=r"(a) : "l"(p));
    return a;
}
__device__ __forceinline__ void ldsm4(uint32_t* r, uint32_t a){
    asm volatile("ldmatrix.sync.aligned.m8n8.x4.shared.b16 {%0,%1,%2,%3}, [%4];"
        : "=r"(r[0]),"=r"(r[1]),"=r"(r[2]),"=r"(r[3]) : "r"(a));
}
__device__ __forceinline__ void mma16816h(float* c, const uint32_t* a,
                                          uint32_t b0, uint32_t b1){
    asm volatile("mma.sync.aligned.m16n8k16.row.col.f32.f16.f16.f32 "
        "{%0,%1,%2,%3}, {%4,%5,%6,%7}, {%8,%9}, {%0,%1,%2,%3};"
        : "+f"(c[0]),"+f"(c[1]),"+f"(c[2]),"+f"(c[3])
        : "r"(a[0]),"r"(a[1]),"r"(a[2]),"r"(a[3]), "r"(b0),"r"(b1));
}
#define MB_INIT(mb, c)  asm volatile("mbarrier.init.shared.b64 [%0], %1;" :: "r"((uint32_t)(mb)), "r"((uint32_t)(c)) : "memory")
#define MB_EXPECT(mb, n) asm volatile("mbarrier.arrive.expect_tx.shared.b64 _, [%0], %1;" :: "r"((uint32_t)(mb)), "r"((uint32_t)(n)) : "memory")
#define MB_WAIT(mb, ph) do { \
    uint32_t _m=(uint32_t)(mb), _p=(uint32_t)(ph), _d; \
    asm volatile("{\n\t.reg .pred p;\n\tmbarrier.try_wait.parity.shared.b64 p, [%1], %2;\n\tselp.b32 %0, 1, 0, p;\n\t}" \
        : "=r"(_d) : "r"(_m), "r"(_p) : "memory"); \
    if (!_d){ \
        asm volatile("{\n\t.reg .pred P1;\n\tWL_%=:\n\tmbarrier.try_wait.parity.shared.b64 P1, [%0], %1;\n\t@P1 bra.uni WD_%=;\n\tbra.uni WL_%=;\n\tWD_%=:\n\t}" \
            :: "r"(_m), "r"(_p) : "memory"); \
    } } while(0)
__device__ __forceinline__ void bulk_cp(uint32_t dst, const void* src, uint32_t sz, uint32_t mb){
    asm volatile("cp.async.bulk.shared::cta.global.mbarrier::complete_tx::bytes [%0], [%1], %2, [%3];"
        :: "r"(dst), "l"(src), "r"(sz), "r"(mb) : "memory");
}

#define STG_B 16384
#define SMEM_B (2*STG_B)

// ---------------- packed fp16 HMMA NT GEMM ----------------
__global__ __launch_bounds__(256,2)
void mma_gemm(const __half* __restrict__ Ah, const __half* __restrict__ Bh,
              float* __restrict__ C, const float* __restrict__ bias0,
              const float* __restrict__ bias1,
              int M, int N, int NT, int ldc)
{
    extern __shared__ char smem[];
    __shared__ __align__(8) uint64_t mbar[2];
    uint32_t sb = smem_u32(smem);
    uint32_t mba = smem_u32(mbar);
    const int tid = threadIdx.x, lane = tid & 31, wid = tid >> 5;
    const int pa = blockIdx.y, pb = blockIdx.x;
    const int row0 = pa*128, col0 = pb*128;
    const int wm = wid >> 2, wn = wid & 3;

    const int zc = gridDim.z, z = blockIdx.z;
    const int chunk = (NT + zc - 1)/zc;
    const int kb = z*chunk;
    const int ke = min(NT, kb + chunk);
    float* Cz = C + (size_t)z*M*ldc;
    const bool addB = (z == 0);

    if (tid == 0){ MB_INIT(mba, 1); MB_INIT(mba+8, 1); }
    __syncthreads();

    float c[4][4][4];
#pragma unroll
    for (int i = 0; i < 4; i++)
#pragma unroll
        for (int j = 0; j < 4; j++)
#pragma unroll
            for (int q = 0; q < 4; q++) c[i][j][q] = 0.f;

    auto load = [&](int kt, int stg){
        if (tid == 0){
            uint32_t mb = mba + stg*8;
            MB_EXPECT(mb, STG_B);
            uint32_t d = sb + stg*STG_B;
            bulk_cp(d,         Ah + ((size_t)pa*NT + kt)*4096, 8192, mb);
            bulk_cp(d + 8192,  Bh + ((size_t)pb*NT + kt)*4096, 8192, mb);
        }
    };

    int ph[2] = {0, 0};
    load(kb, 0);
    for (int kt = kb; kt < ke; kt++){
        int cur = (kt - kb) & 1;
        if (kt + 1 < ke) load(kt+1, cur ^ 1);
        MB_WAIT(mba + cur*8, ph[cur]); ph[cur] ^= 1;
        __syncthreads();

        uint32_t sbase = sb + cur*STG_B;
#pragma unroll
        for (int ks = 0; ks < 2; ks++){
            uint32_t bh[2][4];
#pragma unroll
            for (int nj = 0; nj < 2; nj++){
                uint32_t rb = (uint32_t)(wn*32 + nj*16 + (lane & 15));
                uint32_t c4 = (uint32_t)(ks*2 + (lane >> 4)) ^ ((rb >> 1) & 3);
                uint32_t ab = sbase + 8192 + rb*64 + c4*16;
                ldsm4(bh[nj], ab);
            }
#pragma unroll
            for (int mi = 0; mi < 4; mi++){
                uint32_t ra = (uint32_t)(wm*64 + mi*16 + (lane & 15));
                uint32_t c4 = (uint32_t)(ks*2 + (lane >> 4)) ^ ((ra >> 1) & 3);
                uint32_t aa = sbase + ra*64 + c4*16;
                uint32_t a4[4];
                ldsm4(a4, aa);
#pragma unroll
                for (int nf = 0; nf < 4; nf++){
                    int nj = nf >> 1, s = nf & 1;
                    mma16816h(c[mi][nf], a4, bh[nj][s], bh[nj][2+s]);
                }
            }
        }
        __syncthreads();
    }

#pragma unroll
    for (int mi = 0; mi < 4; mi++){
#pragma unroll
        for (int nf = 0; nf < 4; nf++){
            int gr = row0 + wm*64 + mi*16 + (lane >> 2);
            int gc = col0 + wn*32 + nf*8 + (lane & 3)*2;
#pragma unroll
            for (int q = 0; q < 4; q++){
                int rr = gr + (q >> 1)*8;
                int cc = gc + (q & 1);
                if (rr < M && cc < N){
                    float v = c[mi][nf][q];
                    if (addB){
                        if (bias0) v += bias0[cc];
                        if (bias1) v += bias1[cc];
                    }
                    Cz[(size_t)rr*ldc + cc] = v;
                }
            }
        }
    }
}

__global__ void reduce_z(const float* __restrict__ in, float* __restrict__ out,
                         int zc, int mn)
{
    int i = blockIdx.x*256 + threadIdx.x;
    if (i >= mn) return;
    float s = 0.f;
    for (int z = 0; z < zc; z++) s += in[(size_t)z*mn + i];
    out[i] = s;
}

// ---------------- pack kernels ----------------
__global__ void pack_rows_k(const float* __restrict__ src, long srcLd, int colOff,
                            int Rr, int Kr, int NT, __half* __restrict__ hi)
{
    int r = blockIdx.x;
    int p = r >> 7, pr = r & 127;
    size_t pbase = ((size_t)p*NT)*4096 + (size_t)pr*32;
    const float* s = src + (size_t)r*srcLd + colOff;
    int Kp = NT*32;
    bool rok = (r < Rr);
    int sw = (pr >> 1) & 3;
    for (int k = threadIdx.x; k < Kp; k += 256){
        int kt = k >> 5, kc = k & 31;
        size_t off = pbase + (size_t)kt*4096 + (size_t)(((kc>>3) ^ sw)*8 + (kc&7));
        float x = (rok && k < Kr) ? s[k] : 0.f;
        hi[off] = __float2half(x);
    }
}

__global__ void pack_inp_k(const float* __restrict__ inp, __half* __restrict__ hi)
{
    int r = blockIdx.x;
    int t = r / B_, b = r % B_;
    int p = r >> 7, pr = r & 127;
    size_t pbase = ((size_t)p*NT_E)*4096 + (size_t)pr*32;
    const float* s = inp + ((size_t)b*T_ + t)*E_;
    int sw = (pr >> 1) & 3;
    for (int k = threadIdx.x; k < KP_; k += 256){
        int kt = k >> 5, kc = k & 31;
        size_t off = pbase + (size_t)kt*4096 + (size_t)(((kc>>3) ^ sw)*8 + (kc&7));
        float x = (k < E_) ? s[k] : 0.f;
        hi[off] = __float2half(x);
    }
}

__global__ void pack_tr_k(const float* __restrict__ src, __half* __restrict__ hi)
{
    __shared__ float t[32][33];
    int e0 = blockIdx.x*32, j0 = blockIdx.y*32;
    for (int i = threadIdx.y; i < 32; i += 8){
        int e = e0+i, j = j0+threadIdx.x;
        t[i][threadIdx.x] = (e < E_ && j < H_) ? src[(size_t)e*H_ + j] : 0.f;
    }
    __syncthreads();
    for (int i = threadIdx.y; i < 32; i += 8){
        int j = j0+i;
        int e = e0+threadIdx.x;
        int p = j >> 7, pr = j & 127;
        int kt = e >> 5, kc = e & 31;
        size_t off = ((size_t)p*NT_E + kt)*4096 + (size_t)pr*32
                   + (size_t)((((kc>>3) ^ ((pr>>1)&3))*8) + (kc&7));
        hi[off] = __float2half(t[threadIdx.x][i]);
    }
}

// ---------------- small SIMT GEMM for n2attn ----------------
__global__ __launch_bounds__(256,2)
void sgemm_nt(const float* __restrict__ A, const float* __restrict__ Bm,
              float* __restrict__ C,
              const float* __restrict__ bias0,
              int M, int N, int K, int lda, int ldb, int bColOff, int ldc)
{
    __shared__ float As[16][132];
    __shared__ float Bs[16][132];
    const int row0 = blockIdx.y*128, col0 = blockIdx.x*128;
    const int tid = threadIdx.x;
    const int tx = tid & 15, ty = tid >> 4;
    const int lk = tid & 15, lr0 = tid >> 4;
    long aOff[8]; int aOk[8]; long bOff[8]; int bOk[8];
#pragma unroll
    for (int i = 0; i < 8; i++){
        int gr = row0 + lr0 + i*16;
        aOk[i] = (gr < M); aOff[i] = (long)(aOk[i] ? gr : 0)*lda;
        int gc = col0 + lr0 + i*16;
        bOk[i] = (gc < N); bOff[i] = (long)(bOk[i] ? gc : 0)*ldb + bColOff;
    }
    float acc[8][8];
#pragma unroll
    for (int i = 0; i < 8; i++)
#pragma unroll
        for (int j = 0; j < 8; j++) acc[i][j] = 0.f;
    for (int k0 = 0; k0 < K; k0 += 16){
        int gk = k0 + lk; bool kOk = (gk < K);
#pragma unroll
        for (int i = 0; i < 8; i++){
            As[lk][lr0+i*16] = (kOk && aOk[i]) ? A[aOff[i]+gk] : 0.f;
            Bs[lk][lr0+i*16] = (kOk && bOk[i]) ? Bm[bOff[i]+gk] : 0.f;
        }
        __syncthreads();
#pragma unroll
        for (int kk = 0; kk < 16; kk++){
            float4 a0 = *(const float4*)&As[kk][ty*8];
            float4 a1 = *(const float4*)&As[kk][ty*8+4];
            float4 b0 = *(const float4*)&Bs[kk][tx*8];
            float4 b1 = *(const float4*)&Bs[kk][tx*8+4];
            float a[8] = {a0.x,a0.y,a0.z,a0.w,a1.x,a1.y,a1.z,a1.w};
            float b[8] = {b0.x,b0.y,b0.z,b0.w,b1.x,b1.y,b1.z,b1.w};
#pragma unroll
            for (int i = 0; i < 8; i++)
#pragma unroll
                for (int j = 0; j < 8; j++) acc[i][j] += a[i]*b[j];
        }
        __syncthreads();
    }
#pragma unroll
    for (int i = 0; i < 8; i++){
        int gr = row0 + ty*8 + i;
        if (gr >= M) continue;
#pragma unroll
        for (int j = 0; j < 8; j++){
            int gc = col0 + tx*8 + j;
            if (gc >= N) continue;
            float v = acc[i][j];
            if (bias0) v += bias0[gc];
            C[(long)gr*ldc + gc] = v;
        }
    }
}

__global__ void skinny_k(const float* __restrict__ A, const float* __restrict__ Bm)
{
    __shared__ float Ash[8*1024];
    int w = threadIdx.x >> 5, lane = threadIdx.x & 31;
    int j = blockIdx.x*8 + w;
    float acc[8] = {0,0,0,0,0,0,0,0};
    for (int k0 = 0; k0 < E_; k0 += 1024){
        int kc = min(1024, E_ - k0);
        __syncthreads();
        for (int idx = threadIdx.x; idx < 8192; idx += 256){
            int r = idx >> 10, k = idx & 1023;
            Ash[idx] = (k < kc) ? A[(long)r*E_ + k0 + k] : 0.f;
        }
        __syncthreads();
        if (j < H_){
            const float* br = Bm + (long)j*EPNZ_ + k0;
            for (int k = lane; k < kc; k += 32){
                float wv = br[k];
#pragma unroll
                for (int b = 0; b < 8; b++) acc[b] += wv*Ash[b*1024 + k];
            }
        }
    }
    if (j < H_){
#pragma unroll
        for (int b = 0; b < 8; b++) acc[b] = wsum(acc[b]);
        if (lane == 0)
            for (int b = 0; b < 8; b++) g_emb0[b*H_ + j] = acc[b];
    }
}

__global__ void vvec_k(const float* __restrict__ embW, const float* __restrict__ out_b,
                       const float* __restrict__ emb_b)
{
    __shared__ float red[256];
    int j = blockIdx.x;
    float s = 0.f;
    for (int k = threadIdx.x; k < E_; k += 256) s += embW[(long)j*EPNZ_ + k]*out_b[k];
    red[threadIdx.x] = s; __syncthreads();
    for (int o = 128; o; o >>= 1){
        if (threadIdx.x < o) red[threadIdx.x] += red[threadIdx.x+o];
        __syncthreads();
    }
    if (threadIdx.x == 0) g_v2[j] = red[0] + emb_b[j];
}

__global__ void zero_k(){
    int i = blockIdx.x*256 + threadIdx.x;
    if (i < B_*H_){ g_h[0][i] = 0.f; g_c[i] = 0.f; }
}

// ---------------- persistent encoder: 128 LSTM steps, 1 kernel ----------------
__global__ __launch_bounds__(256)
void enc_fused(const float* __restrict__ Whh)
{
    __shared__ float hs[B_*H_];
    const int tid = threadIdx.x, w = tid >> 5, lane = tid & 31;
    const int j = blockIdx.x*8 + w;
    const float *w0 = Whh+(size_t)j*H_, *w1 = Whh+(size_t)(H_+j)*H_;
    const float *w2 = Whh+(size_t)(2*H_+j)*H_, *w3 = Whh+(size_t)(3*H_+j)*H_;

    for (int t = 0; t < T_; t++){
        const float* hIn = g_h[t & 1];
        float* hOut = g_h[(t & 1) ^ 1];
        const float* gx = g_encGX + (size_t)t*B_*G4H_;
        for (int i = tid; i < B_*H_; i += 256) hs[i] = ldv(hIn + i);
        __syncthreads();

        float a0[8]={0},a1[8]={0},a2[8]={0},a3[8]={0};
        for (int k = lane; k < H_; k += 32){
            float x0=w0[k],x1=w1[k],x2=w2[k],x3=w3[k];
#pragma unroll
            for (int b = 0; b < 8; b++){
                float hv = hs[b*H_+k];
                a0[b]+=x0*hv; a1[b]+=x1*hv; a2[b]+=x2*hv; a3[b]+=x3*hv;
            }
        }
#pragma unroll
        for (int b = 0; b < 8; b++){
            a0[b]=wsum(a0[b]); a1[b]=wsum(a1[b]); a2[b]=wsum(a2[b]); a3[b]=wsum(a3[b]);
        }
        if (lane == 0){
#pragma unroll
            for (int b = 0; b < 8; b++){
                const float* gr = gx + (size_t)b*G4H_;
                float ig = sigf (gr[j]       + a0[b]);
                float fg = sigf (gr[H_+j]    + a1[b]);
                float gg = tanhf(gr[2*H_+j]  + a2[b]);
                float og = sigf (gr[3*H_+j]  + a3[b]);
                float c = fg*g_c[b*H_+j] + ig*gg;
                g_c[b*H_+j] = c;
                float h = og*tanhf(c);
                stg(&hOut[b*H_+j], h);
                g_encBTH[((size_t)b*T_ + t)*H_ + j] = h;
            }
        }
        gbar(t);
    }
}

// ---------------- per-launch decoder kernels (unchanged, passing) ----------------
__global__ void emb0_k(const float* __restrict__ emb_b)
{
    int i = blockIdx.x*256 + threadIdx.x;
    if (i < B_*H_) g_emb[i] = g_emb0[i] + g_n1[i] + emb_b[i % H_];
}

__global__ void dk1_k(int s)
{
    __shared__ float hs[B_*H_];
    const float* hIn = g_h[s & 1];
    const float* n1 = g_n1 + (long)s*B_*H_;
    int tid = threadIdx.x;
    for (int i = tid; i < B_*H_; i += 256) hs[i] = hIn[i];
    __syncthreads();
    int w = tid >> 5, lane = tid & 31;
    int j = blockIdx.x*8 + w;
    const float* mr = g_M + (long)j*H_;
    float acc[8]={0,0,0,0,0,0,0,0};
    for (int k = lane; k < H_; k += 32){
        float mv = mr[k];
#pragma unroll
        for (int b = 0; b < 8; b++) acc[b] += mv*hs[b*H_+k];
    }
#pragma unroll
    for (int b = 0; b < 8; b++) acc[b] = wsum(acc[b]);
    if (lane == 0){
        float vb = g_v2[j];
        for (int b = 0; b < 8; b++) g_emb[b*H_+j] = acc[b] + n1[b*H_+j] + vb;
    }
}

__global__ void dk2_k(const float* __restrict__ attW, int s)
{
    __shared__ float xs[2*H_];
    __shared__ float lg[T_];
    __shared__ float ps[T_];
    int b = blockIdx.x, tid = threadIdx.x;
    const float* hIn = g_h[s & 1];
    const float* n2 = g_n2 + (long)s*B_*T_;
    for (int i = tid; i < H_; i += 256){ xs[i] = g_emb[b*H_+i]; xs[H_+i] = hIn[b*H_+i]; }
    __syncthreads();
    int w = tid >> 5, lane = tid & 31;
    for (int ti = 0; ti < 16; ti++){
        int t = w*16 + ti;
        const float* wr = attW + (long)t*3*H_;
        float sv = 0.f;
        for (int k = lane; k < 2*H_; k += 32) sv += wr[k]*xs[k];
        sv = wsum(sv);
        if (lane == 0) lg[t] = sv + n2[b*T_+t];
    }
    __syncthreads();
    if (w == 0){
        float m = -1e30f;
        for (int i = lane; i < T_; i += 32) m = fmaxf(m, lg[i]);
#pragma unroll
        for (int o = 16; o; o >>= 1) m = fmaxf(m, __shfl_xor_sync(0xffffffffu, m, o));
        float ss = 0.f;
        for (int i = lane; i < T_; i += 32){ float e = expf(lg[i]-m); ps[i] = e; ss += e; }
        ss = wsum(ss);
        float inv = 1.f/ss;
        for (int i = lane; i < T_; i += 32) ps[i] *= inv;
    }
    __syncthreads();
    for (int j = tid; j < H_; j += 256){
        float sv = 0.f;
        const float* eb = g_encBTH + (long)b*T_*H_ + j;
#pragma unroll 4
        for (int t = 0; t < T_; t++) sv += ps[t]*eb[(long)t*H_];
        g_app[b*H_+j] = sv;
    }
}

__global__ void dk3_k(const float* __restrict__ combW, const float* __restrict__ comb_b)
{
    __shared__ float sh[B_*H_];
    int tid = threadIdx.x;
    int w = tid >> 5, lane = tid & 31;
    int j = blockIdx.x*8 + w;
    const float* wr = combW + (long)j*2*H_;
    float acc[8]={0,0,0,0,0,0,0,0};
    for (int i = tid; i < B_*H_; i += 256) sh[i] = g_emb[i];
    __syncthreads();
    for (int k = lane; k < H_; k += 32){
        float wv = wr[k];
#pragma unroll
        for (int b = 0; b < 8; b++) acc[b] += wv*sh[b*H_+k];
    }
    __syncthreads();
    for (int i = tid; i < B_*H_; i += 256) sh[i] = g_app[i];
    __syncthreads();
    for (int k = lane; k < H_; k += 32){
        float wv = wr[H_+k];
#pragma unroll
        for (int b = 0; b < 8; b++) acc[b] += wv*sh[b*H_+k];
    }
#pragma unroll
    for (int b = 0; b < 8; b++) acc[b] = wsum(acc[b]);
    if (lane == 0){
        float cb = comb_b[j];
        for (int b = 0; b < 8; b++) g_outv[b*H_+j] = fmaxf(0.f, acc[b] + cb);
    }
}

__global__ void dk4_k(const float* __restrict__ Wih, const float* __restrict__ Whh,
                      const float* __restrict__ bih, const float* __restrict__ bhh, int s)
{
    __shared__ float sh[B_*H_];
    int pp = s & 1;
    const float* hIn = g_h[pp];
    float* hOut = g_h[pp ^ 1];
    int tid = threadIdx.x;
    int w = tid >> 5, lane = tid & 31;
    int j = blockIdx.x*8 + w;
    float a0[8]={0},a1[8]={0},a2[8]={0},a3[8]={0};
    for (int i = tid; i < B_*H_; i += 256) sh[i] = g_outv[i];
    __syncthreads();
    {
        const float *w0=Wih+(long)j*H_, *w1=Wih+(long)(H_+j)*H_;
        const float *w2=Wih+(long)(2*H_+j)*H_, *w3=Wih+(long)(3*H_+j)*H_;
        for (int k = lane; k < H_; k += 32){
            float x0=w0[k],x1=w1[k],x2=w2[k],x3=w3[k];
#pragma unroll
            for (int b = 0; b < 8; b++){
                float hv = sh[b*H_+k];
                a0[b]+=x0*hv; a1[b]+=x1*hv; a2[b]+=x2*hv; a3[b]+=x3*hv;
            }
        }
    }
    __syncthreads();
    for (int i = tid; i < B_*H_; i += 256) sh[i] = hIn[i];
    __syncthreads();
    {
        const float *w0=Whh+(long)j*H_, *w1=Whh+(long)(H_+j)*H_;
        const float *w2=Whh+(long)(2*H_+j)*H_, *w3=Whh+(long)(3*H_+j)*H_;
        for (int k = lane; k < H_; k += 32){
            float x0=w0[k],x1=w1[k],x2=w2[k],x3=w3[k];
#pragma unroll
            for (int b = 0; b < 8; b++){
                float hv = sh[b*H_+k];
                a0[b]+=x0*hv; a1[b]+=x1*hv; a2[b]+=x2*hv; a3[b]+=x3*hv;
            }
        }
    }
#pragma unroll
    for (int b = 0; b < 8; b++){
        a0[b]=wsum(a0[b]); a1[b]=wsum(a1[b]); a2[b]=wsum(a2[b]); a3[b]=wsum(a3[b]);
    }
    if (lane == 0){
        float bi0=bih[j]+bhh[j], bi1=bih[H_+j]+bhh[H_+j];
        float bi2=bih[2*H_+j]+bhh[2*H_+j], bi3=bih[3*H_+j]+bhh[3*H_+j];
#pragma unroll
        for (int b = 0; b < 8; b++){
            float ig = sigf (a0[b]+bi0);
            float fg = sigf (a1[b]+bi1);
            float gg = tanhf(a2[b]+bi2);
            float og = sigf (a3[b]+bi3);
            float c = fg*g_c[b*H_+j] + ig*gg;
            g_c[b*H_+j] = c;
            float h = og*tanhf(c);
            hOut[b*H_+j] = h;
            g_Hs[((long)s*B_ + b)*H_ + j] = h;
        }
    }
}

extern "C" void kernel_launch(void* const* d_in, const int* in_sizes, int n_in,
                              void* d_out, int out_size)
{
    int off = (in_sizes[1] == 1) ? 1 : 0;
    const float* input    = (const float*)d_in[0];
    const float* noise1   = (const float*)d_in[1+off];
    const float* noise2   = (const float*)d_in[2+off];
    const float* init_dec = (const float*)d_in[3+off];
    const float* enc_Wih  = (const float*)d_in[4+off];
    const float* enc_Whh  = (const float*)d_in[5+off];
    const float* enc_bih  = (const float*)d_in[6+off];
    const float* enc_bhh  = (const float*)d_in[7+off];
    const float* dec_Wih  = (const float*)d_in[8+off];
    const float* dec_Whh  = (const float*)d_in[9+off];
    const float* dec_bih  = (const float*)d_in[10+off];
    const float* dec_bhh  = (const float*)d_in[11+off];
    const float* emb_W    = (const float*)d_in[12+off];
    const float* emb_b    = (const float*)d_in[13+off];
    const float* attn_W   = (const float*)d_in[14+off];
    const float* attn_b   = (const float*)d_in[15+off];
    const float* comb_W   = (const float*)d_in[16+off];
    const float* comb_b   = (const float*)d_in[17+off];
    const float* out_W    = (const float*)d_in[18+off];
    const float* out_b    = (const float*)d_in[19+off];
    float* out = (float*)d_out;

    float *p_gx, *p_M, *p_Mp, *p_n1, *p_n1p, *p_n2, *p_Hs;
    cudaGetSymbolAddress((void**)&p_gx,  g_encGX);
    cudaGetSymbolAddress((void**)&p_M,   g_M);
    cudaGetSymbolAddress((void**)&p_Mp,  g_Mp);
    cudaGetSymbolAddress((void**)&p_n1,  g_n1);
    cudaGetSymbolAddress((void**)&p_n1p, g_n1p);
    cudaGetSymbolAddress((void**)&p_n2,  g_n2);
    cudaGetSymbolAddress((void**)&p_Hs,  g_Hs);
    __half *inpH,*wihH,*embEH,*embNH,*oWTH,*oWH,*nzH,*HsH;
    cudaGetSymbolAddress((void**)&inpH, g_inpH);
    cudaGetSymbolAddress((void**)&wihH, g_wihH);
    cudaGetSymbolAddress((void**)&embEH, g_embEH);
    cudaGetSymbolAddress((void**)&embNH, g_embNH);
    cudaGetSymbolAddress((void**)&oWTH, g_oWTH);
    cudaGetSymbolAddress((void**)&oWH, g_oWH);
    cudaGetSymbolAddress((void**)&nzH, g_nzH);
    cudaGetSymbolAddress((void**)&HsH, g_HsH);

    cudaFuncSetAttribute(mma_gemm, cudaFuncAttributeMaxDynamicSharedMemorySize, SMEM_B);

    pack_inp_k<<<1024,256>>>(input, inpH);
    pack_rows_k<<<4096,256>>>(enc_Wih, E_, 0, G4H_, E_, NT_E, wihH);
    pack_rows_k<<<1024,256>>>(emb_W, EPNZ_, 0, H_, E_, NT_E, embEH);

    // G1: enc_gx [1024, 4000]
    mma_gemm<<<dim3(32, 8, 1), 256, SMEM_B>>>(inpH, wihH,
        p_gx, enc_bih, enc_bhh, T_*B_, G4H_, NT_E, G4H_);

    pack_rows_k<<<1024,256>>>(emb_W, EPNZ_, E_, H_, NZ_, NT_NZ, embNH);
    pack_tr_k<<<dim3(NT_E, 32), dim3(32,8)>>>(out_W, oWTH);
    pack_rows_k<<<239*128,256>>>(out_W, H_, 0, E_, H_, NT_H, oWH);
    pack_rows_k<<<512,256>>>(noise1, NZ_, 0, S_*B_, NZ_, NT_NZ, nzH);

    // G2: M [1000,1000], K-split x4
    mma_gemm<<<dim3(8, 8, 4), 256, SMEM_B>>>(embEH, oWTH,
        p_Mp, 0, 0, H_, H_, NT_E, H_);
    reduce_z<<<(H_*H_+255)/256,256>>>(p_Mp, p_M, 4, H_*H_);

    // G3: n1emb [512, 1000], K-split x4
    mma_gemm<<<dim3(8, 4, 4), 256, SMEM_B>>>(nzH, embNH,
        p_n1p, 0, 0, S_*B_, H_, NT_NZ, H_);
    reduce_z<<<(S_*B_*H_+255)/256,256>>>(p_n1p, p_n1, 4, S_*B_*H_);

    vvec_k<<<H_,256>>>(emb_W, out_b, emb_b);
    sgemm_nt<<<dim3(1,4),256>>>(noise2, attn_W, p_n2, attn_b,
        S_*B_, T_, H_, H_, 3*H_, 2*H_, T_);
    skinny_k<<<H_/8,256>>>(init_dec, emb_W);
    zero_k<<<32,256>>>();

    // persistent encoder: 128 launches -> 2 (reset + fused)
    bar_reset<<<1,256>>>();
    enc_fused<<<NB_,256>>>(enc_Whh);

    for (int s = 0; s < S_; s++){
        if (s == 0) emb0_k<<<32,256>>>(emb_b);
        else        dk1_k<<<H_/8,256>>>(s);
        dk2_k<<<B_,256>>>(attn_W, s);
        dk3_k<<<H_/8,256>>>(comb_W, comb_b);
        dk4_k<<<H_/8,256>>>(dec_Wih, dec_Whh, dec_bih, dec_bhh, s);
    }

    // G4: summary [512, E]
    pack_rows_k<<<512,256>>>(p_Hs, H_, 0, S_*B_, H_, NT_H, HsH);
    mma_gemm<<<dim3(239, 4, 1), 256, SMEM_B>>>(HsH, oWH,
        out, out_b, 0, S_*B_, E_, NT_H, E_);
}